// round 1
// baseline (speedup 1.0000x reference)
#include <cuda_runtime.h>
#include <math.h>

// Problem constants
static constexpr int BB = 16;     // batch
static constexpr int SS = 512;    // seq len
static constexpr int HH = 768;    // hidden
static constexpr int NHH = 12;    // heads
static constexpr int HDD = 64;    // head dim
static constexpr int MROWS = BB * SS;  // 8192

// Scratch for Q, K, V: 3 * 8192 * 768 floats = ~75 MB (static device alloc, allowed)
__device__ float g_qkv[3][(size_t)MROWS * HH];

// ---------------------------------------------------------------------------
// Kernel 1: QKV projection.  out[m][n] = sum_k X[m][k] * W[n][k] + b[n]
// (i.e. X @ W^T + b).  Classic 128x128x16 SGEMM, 8x8 per thread, 256 threads.
// grid = (HH/128, MROWS/128, 3), z selects Wq/Wk/Wv.
// ---------------------------------------------------------------------------
__global__ __launch_bounds__(256) void qkv_gemm(
    const float* __restrict__ X,
    const float* __restrict__ Wq, const float* __restrict__ bq,
    const float* __restrict__ Wk, const float* __restrict__ bk,
    const float* __restrict__ Wv, const float* __restrict__ bv)
{
    constexpr int BM = 128, BN = 128, BK = 16, TM = 8, TN = 8;
    __shared__ float As[BK][BM + 4];
    __shared__ float Bs[BK][BN + 4];

    const int which = blockIdx.z;
    const float* W    = (which == 0) ? Wq : (which == 1) ? Wk : Wv;
    const float* bias = (which == 0) ? bq : (which == 1) ? bk : bv;
    float* out = g_qkv[which];

    const int tid  = threadIdx.x;
    const int m0   = blockIdx.y * BM;
    const int n0   = blockIdx.x * BN;
    const int trow = tid >> 4;   // 0..15 over M
    const int tcol = tid & 15;   // 0..15 over N

    float acc[TM][TN] = {};

    for (int k0 = 0; k0 < HH; k0 += BK) {
        #pragma unroll
        for (int e = 0; e < 8; e++) {
            int flat = tid + e * 256;     // 2048 elements
            int i = flat >> 4;            // 0..127
            int j = flat & 15;            // 0..15
            As[j][i] = X[(size_t)(m0 + i) * HH + k0 + j];
        }
        #pragma unroll
        for (int e = 0; e < 8; e++) {
            int flat = tid + e * 256;
            int i = flat >> 4;
            int j = flat & 15;
            Bs[j][i] = W[(size_t)(n0 + i) * HH + k0 + j];
        }
        __syncthreads();

        #pragma unroll
        for (int kk = 0; kk < BK; kk++) {
            float a[TM], bv_[TN];
            #pragma unroll
            for (int i = 0; i < TM; i++) a[i] = As[kk][trow * TM + i];
            #pragma unroll
            for (int j = 0; j < TN; j++) bv_[j] = Bs[kk][tcol * TN + j];
            #pragma unroll
            for (int i = 0; i < TM; i++)
                #pragma unroll
                for (int j = 0; j < TN; j++)
                    acc[i][j] += a[i] * bv_[j];
        }
        __syncthreads();
    }

    #pragma unroll
    for (int i = 0; i < TM; i++) {
        int m = m0 + trow * TM + i;
        #pragma unroll
        for (int j = 0; j < TN; j++) {
            int n = n0 + tcol * TN + j;
            out[(size_t)m * HH + n] = acc[i][j] + bias[n];
        }
    }
}

// ---------------------------------------------------------------------------
// Kernel 2: fused attention per (b, h, 64-row q-tile).
//   scores = (Q Kt) * scale + mask_add   (kept in smem, 64 x 512)
//   probs  = softmax(scores)             (written to global, kept in smem)
//   ctx    = probs @ V
// 256 threads, dynamic smem ~166 KB -> 1 CTA/SM.
// ---------------------------------------------------------------------------
static constexpr int SPAD = 513;  // scores row stride (conflict-friendly)
static constexpr int KPAD = 65;   // q/k/v tile row stride

__global__ __launch_bounds__(256) void attn_kernel(
    const float* __restrict__ mask,
    float* __restrict__ ctx,
    float* __restrict__ probs)
{
    extern __shared__ float smem[];
    float* sc  = smem;                    // 64 * SPAD
    float* qs  = sc + 64 * SPAD;          // 64 * KPAD
    float* ks  = qs + 64 * KPAD;          // 64 * KPAD (reused for V)
    float* msk = ks + 64 * KPAD;          // SS

    const int qt = blockIdx.x;   // 0..7
    const int h  = blockIdx.y;   // 0..11
    const int b  = blockIdx.z;   // 0..15
    const int tid  = threadIdx.x;
    const int trow = tid >> 4;   // 0..15
    const int tcol = tid & 15;   // 0..15
    const int q0 = qt * 64;
    const float scale = 0.125f;  // 1/sqrt(64)

    const float* Q = g_qkv[0];
    const float* K = g_qkv[1];
    const float* V = g_qkv[2];

    // mask additive term
    for (int j = tid; j < SS; j += 256)
        msk[j] = (1.0f - mask[(size_t)b * SS + j]) * -10000.0f;

    // load Q tile [64 x 64]
    #pragma unroll
    for (int e = 0; e < 16; e++) {
        int flat = tid + e * 256;   // 4096
        int r = flat >> 6, d = flat & 63;
        qs[r * KPAD + d] = Q[((size_t)b * SS + q0 + r) * HH + h * HDD + d];
    }
    __syncthreads();

    // ---- phase 1: scores ----
    for (int kt = 0; kt < 8; kt++) {
        #pragma unroll
        for (int e = 0; e < 16; e++) {
            int flat = tid + e * 256;
            int r = flat >> 6, d = flat & 63;
            ks[r * KPAD + d] = K[((size_t)b * SS + kt * 64 + r) * HH + h * HDD + d];
        }
        __syncthreads();

        float acc[4][4] = {};
        #pragma unroll
        for (int d = 0; d < 64; d++) {
            float a[4], bb[4];
            #pragma unroll
            for (int i = 0; i < 4; i++) a[i] = qs[(trow * 4 + i) * KPAD + d];
            #pragma unroll
            for (int j = 0; j < 4; j++) bb[j] = ks[(tcol * 4 + j) * KPAD + d];
            #pragma unroll
            for (int i = 0; i < 4; i++)
                #pragma unroll
                for (int j = 0; j < 4; j++)
                    acc[i][j] += a[i] * bb[j];
        }
        #pragma unroll
        for (int i = 0; i < 4; i++)
            #pragma unroll
            for (int j = 0; j < 4; j++) {
                int col = kt * 64 + tcol * 4 + j;
                sc[(trow * 4 + i) * SPAD + col] = acc[i][j] * scale + msk[col];
            }
        __syncthreads();
    }

    // ---- phase 2: softmax (warp per row group), write probs ----
    {
        const int warp = tid >> 5, lane = tid & 31;
        for (int rr = 0; rr < 8; rr++) {
            int r = warp * 8 + rr;
            float* row = sc + r * SPAD;
            float m = -1e30f;
            #pragma unroll
            for (int i = 0; i < 16; i++) m = fmaxf(m, row[lane + i * 32]);
            #pragma unroll
            for (int o = 16; o > 0; o >>= 1) m = fmaxf(m, __shfl_xor_sync(0xffffffffu, m, o));
            float vals[16];
            float sum = 0.0f;
            #pragma unroll
            for (int i = 0; i < 16; i++) {
                float e = expf(row[lane + i * 32] - m);
                vals[i] = e;
                sum += e;
            }
            #pragma unroll
            for (int o = 16; o > 0; o >>= 1) sum += __shfl_xor_sync(0xffffffffu, sum, o);
            float inv = 1.0f / sum;
            size_t pbase = (((size_t)b * NHH + h) * SS + q0 + r) * SS;
            #pragma unroll
            for (int i = 0; i < 16; i++) {
                float p = vals[i] * inv;
                row[lane + i * 32] = p;
                probs[pbase + lane + i * 32] = p;
            }
        }
    }
    __syncthreads();

    // ---- phase 3: ctx = P @ V ----
    float acc[4][4] = {};
    for (int kt = 0; kt < 8; kt++) {
        #pragma unroll
        for (int e = 0; e < 16; e++) {
            int flat = tid + e * 256;
            int r = flat >> 6, d = flat & 63;
            ks[r * KPAD + d] = V[((size_t)b * SS + kt * 64 + r) * HH + h * HDD + d];
        }
        __syncthreads();

        #pragma unroll
        for (int kk = 0; kk < 64; kk++) {
            float a[4], bb[4];
            #pragma unroll
            for (int i = 0; i < 4; i++) a[i] = sc[(trow * 4 + i) * SPAD + kt * 64 + kk];
            #pragma unroll
            for (int j = 0; j < 4; j++) bb[j] = ks[kk * KPAD + tcol * 4 + j];
            #pragma unroll
            for (int i = 0; i < 4; i++)
                #pragma unroll
                for (int j = 0; j < 4; j++)
                    acc[i][j] += a[i] * bb[j];
        }
        __syncthreads();
    }

    #pragma unroll
    for (int i = 0; i < 4; i++) {
        int q = q0 + trow * 4 + i;
        #pragma unroll
        for (int j = 0; j < 4; j++) {
            int d = tcol * 4 + j;
            ctx[((size_t)b * SS + q) * HH + h * HDD + d] = acc[i][j];
        }
    }
}

// ---------------------------------------------------------------------------
// kernel_launch
// Inputs (metadata order): hidden_state, attention_mask, Wq, bq, Wk, bk, Wv, bv
// Output: ctx [16,512,768] then probs [16,12,512,512] (tuple flattened).
// ---------------------------------------------------------------------------
extern "C" void kernel_launch(void* const* d_in, const int* in_sizes, int n_in,
                              void* d_out, int out_size)
{
    const float* hidden = (const float*)d_in[0];
    const float* mask   = (const float*)d_in[1];
    const float* Wq = (const float*)d_in[2];
    const float* bq = (const float*)d_in[3];
    const float* Wk = (const float*)d_in[4];
    const float* bk = (const float*)d_in[5];
    const float* Wv = (const float*)d_in[6];
    const float* bv = (const float*)d_in[7];

    float* out   = (float*)d_out;
    float* ctx   = out;
    float* probs = out + (size_t)BB * SS * HH;

    // QKV projections
    dim3 g1(HH / 128, MROWS / 128, 3);
    qkv_gemm<<<g1, 256>>>(hidden, Wq, bq, Wk, bk, Wv, bv);

    // Fused attention
    const int smem_bytes = (64 * SPAD + 2 * 64 * KPAD + SS) * (int)sizeof(float);
    cudaFuncSetAttribute(attn_kernel, cudaFuncAttributeMaxDynamicSharedMemorySize, smem_bytes);
    dim3 g2(SS / 64, NHH, BB);
    attn_kernel<<<g2, 256, smem_bytes>>>(mask, ctx, probs);
}

// round 3
// speedup vs baseline: 1.0662x; 1.0662x over previous
#include <cuda_runtime.h>
#include <cuda_bf16.h>
#include <cstdint>
#include <math.h>

// Problem constants
static constexpr int BB = 16;     // batch
static constexpr int SS = 512;    // seq len
static constexpr int HH = 768;    // hidden
static constexpr int NHH = 12;    // heads
static constexpr int HDD = 64;    // head dim
static constexpr int MROWS = BB * SS;  // 8192

// Scratch (static device allocations are allowed)
__device__ float g_qkv[3][(size_t)MROWS * HH];                 // fp32 Q,K,V
__device__ __nv_bfloat16 g_xhi[(size_t)MROWS * HH];            // hidden split
__device__ __nv_bfloat16 g_xlo[(size_t)MROWS * HH];
__device__ __nv_bfloat16 g_whi[3][(size_t)HH * HH];            // weight split
__device__ __nv_bfloat16 g_wlo[3][(size_t)HH * HH];

// ---------------------------------------------------------------------------
// helpers
// ---------------------------------------------------------------------------
__device__ __forceinline__ uint32_t smem_to_u32(const void* p) {
    uint32_t a;
    asm("{ .reg .u64 t; cvta.to.shared.u64 t, %1; cvt.u32.u64 %0, t; }" : "=r"(a) : "l"(p));
    return a;
}
#define CP_ASYNC16(dst_u32, src_ptr) \
    asm volatile("cp.async.cg.shared.global [%0], [%1], 16;" :: "r"(dst_u32), "l"(src_ptr) : "memory")
#define CP_COMMIT() asm volatile("cp.async.commit_group;" ::: "memory")
#define CP_WAIT(n)  asm volatile("cp.async.wait_group %0;" :: "n"(n) : "memory")

__device__ __forceinline__ void mma_bf16(float d[4],
                                         uint32_t a0, uint32_t a1, uint32_t a2, uint32_t a3,
                                         uint32_t b0, uint32_t b1) {
    asm volatile(
        "mma.sync.aligned.m16n8k16.row.col.f32.bf16.bf16.f32 "
        "{%0,%1,%2,%3}, {%4,%5,%6,%7}, {%8,%9}, {%0,%1,%2,%3};"
        : "+f"(d[0]), "+f"(d[1]), "+f"(d[2]), "+f"(d[3])
        : "r"(a0), "r"(a1), "r"(a2), "r"(a3), "r"(b0), "r"(b1));
}

// ---------------------------------------------------------------------------
// Kernel 0: split fp32 -> bf16 hi/lo.  z=0: hidden, z=1..3: Wq/Wk/Wv
// ---------------------------------------------------------------------------
__global__ __launch_bounds__(256) void split_kernel(
    const float* __restrict__ X,
    const float* __restrict__ Wq, const float* __restrict__ Wk, const float* __restrict__ Wv)
{
    const int z = blockIdx.z;
    const float* src = (z == 0) ? X : (z == 1) ? Wq : (z == 2) ? Wk : Wv;
    __nv_bfloat16* hi = (z == 0) ? g_xhi : g_whi[z - 1];
    __nv_bfloat16* lo = (z == 0) ? g_xlo : g_wlo[z - 1];
    size_t n = (z == 0) ? (size_t)MROWS * HH : (size_t)HH * HH;

    for (size_t i = (size_t)blockIdx.x * blockDim.x + threadIdx.x; i < n;
         i += (size_t)gridDim.x * blockDim.x) {
        float x = src[i];
        __nv_bfloat16 h = __float2bfloat16_rn(x);
        hi[i] = h;
        lo[i] = __float2bfloat16_rn(x - __bfloat162float(h));
    }
}

// ---------------------------------------------------------------------------
// Kernel 1: QKV projection via mma.sync bf16x3 (HMMA path, legal on sm_103).
// out[m][n] = sum_k X[m][k]*W[n][k] + b[n]   (X @ W^T + b)
// Block tile 128x128, K tile 32, 8 warps in 2(m) x 4(n); warp tile 64x32.
// Double-buffered cp.async smem. grid=(6, 64, 3), block=256.
// ---------------------------------------------------------------------------
static constexpr int BK = 32;
static constexpr int KSTRIDE = 40;                 // bf16 elems per smem row (80B, 16B aligned)
static constexpr int TILE_BYTES_G = 128 * KSTRIDE * 2;  // 10240 B per tile
static constexpr int STAGE_BYTES = 4 * TILE_BYTES_G;    // Ahi,Alo,Bhi,Blo
static constexpr int GEMM_SMEM_TOTAL = 2 * STAGE_BYTES; // 81920 B
static constexpr int NKT = HH / BK;                // 24

__device__ __forceinline__ void load_stage_async(
    char* smem, int s,
    const __nv_bfloat16* __restrict__ Ahi, const __nv_bfloat16* __restrict__ Alo,
    const __nv_bfloat16* __restrict__ Bhi, const __nv_bfloat16* __restrict__ Blo,
    int k0, int tid)
{
    char* base = smem + s * STAGE_BYTES;
    #pragma unroll
    for (int e = 0; e < 8; e++) {
        const int tile = e >> 1;                    // 0:Ahi 1:Alo 2:Bhi 3:Blo
        int idx = ((e & 1) << 8) + tid;             // 0..511
        int r = idx >> 2;                           // 0..127
        int q = idx & 3;                            // 16B quad
        const __nv_bfloat16* src =
            (tile == 0 ? Ahi : tile == 1 ? Alo : tile == 2 ? Bhi : Blo)
            + (size_t)r * HH + k0 + q * 8;
        uint32_t dst = smem_to_u32(base + tile * TILE_BYTES_G + (r * KSTRIDE + q * 8) * 2);
        CP_ASYNC16(dst, src);
    }
}

__global__ __launch_bounds__(256, 1) void qkv_gemm_mma(
    const float* __restrict__ bq, const float* __restrict__ bk, const float* __restrict__ bv)
{
    extern __shared__ char smem[];
    const int tid = threadIdx.x;
    const int wid = tid >> 5;
    const int lane = tid & 31;
    const int g = lane >> 2;        // group 0..7
    const int tig = lane & 3;       // thread-in-group 0..3

    const int which = blockIdx.z;
    const int n0 = blockIdx.x * 128;
    const int m0 = blockIdx.y * 128;
    const float* bias = (which == 0) ? bq : (which == 1) ? bk : bv;
    float* out = g_qkv[which];

    const __nv_bfloat16* Ahi = g_xhi + (size_t)m0 * HH;
    const __nv_bfloat16* Alo = g_xlo + (size_t)m0 * HH;
    const __nv_bfloat16* Bhi = g_whi[which] + (size_t)n0 * HH;
    const __nv_bfloat16* Blo = g_wlo[which] + (size_t)n0 * HH;

    const int m_w = (wid & 1) * 64;   // warp m offset (2 warps over 128)
    const int n_w = (wid >> 1) * 32;  // warp n offset (4 warps over 128)

    float acc[4][4][4];
    #pragma unroll
    for (int i = 0; i < 4; i++)
        #pragma unroll
        for (int j = 0; j < 4; j++)
            #pragma unroll
            for (int r = 0; r < 4; r++) acc[i][j][r] = 0.0f;

    // prologue
    load_stage_async(smem, 0, Ahi, Alo, Bhi, Blo, 0, tid);
    CP_COMMIT();

    for (int kt = 0; kt < NKT; kt++) {
        const int s = kt & 1;
        if (kt + 1 < NKT) {
            load_stage_async(smem, s ^ 1, Ahi, Alo, Bhi, Blo, (kt + 1) * BK, tid);
            CP_COMMIT();
            CP_WAIT(1);
        } else {
            CP_WAIT(0);
        }
        __syncthreads();

        const uint32_t* sAhi = (const uint32_t*)(smem + s * STAGE_BYTES);
        const uint32_t* sAlo = (const uint32_t*)(smem + s * STAGE_BYTES + TILE_BYTES_G);
        const uint32_t* sBhi = (const uint32_t*)(smem + s * STAGE_BYTES + 2 * TILE_BYTES_G);
        const uint32_t* sBlo = (const uint32_t*)(smem + s * STAGE_BYTES + 3 * TILE_BYTES_G);

        #pragma unroll
        for (int kk = 0; kk < BK; kk += 16) {
            const int kh = (kk >> 1) + tig;   // u32 index of k-pair (kk + tig*2)/2

            // A fragments (hi & lo), 4 m-frags of 16 rows each
            uint32_t ahi[4][4], alo[4][4];
            #pragma unroll
            for (int mi = 0; mi < 4; mi++) {
                int r0 = (m_w + mi * 16 + g) * (KSTRIDE / 2);
                int r1 = r0 + 8 * (KSTRIDE / 2);
                ahi[mi][0] = sAhi[r0 + kh];
                ahi[mi][1] = sAhi[r1 + kh];
                ahi[mi][2] = sAhi[r0 + kh + 4];
                ahi[mi][3] = sAhi[r1 + kh + 4];
                alo[mi][0] = sAlo[r0 + kh];
                alo[mi][1] = sAlo[r1 + kh];
                alo[mi][2] = sAlo[r0 + kh + 4];
                alo[mi][3] = sAlo[r1 + kh + 4];
            }
            // B fragments (hi & lo), 4 n-frags of 8 cols each
            uint32_t bhi[4][2], blo[4][2];
            #pragma unroll
            for (int ni = 0; ni < 4; ni++) {
                int r = (n_w + ni * 8 + g) * (KSTRIDE / 2);
                bhi[ni][0] = sBhi[r + kh];
                bhi[ni][1] = sBhi[r + kh + 4];
                blo[ni][0] = sBlo[r + kh];
                blo[ni][1] = sBlo[r + kh + 4];
            }
            // bf16x3 compensated MMAs
            #pragma unroll
            for (int mi = 0; mi < 4; mi++)
                #pragma unroll
                for (int ni = 0; ni < 4; ni++) {
                    mma_bf16(acc[mi][ni], ahi[mi][0], ahi[mi][1], ahi[mi][2], ahi[mi][3],
                             bhi[ni][0], bhi[ni][1]);
                    mma_bf16(acc[mi][ni], ahi[mi][0], ahi[mi][1], ahi[mi][2], ahi[mi][3],
                             blo[ni][0], blo[ni][1]);
                    mma_bf16(acc[mi][ni], alo[mi][0], alo[mi][1], alo[mi][2], alo[mi][3],
                             bhi[ni][0], bhi[ni][1]);
                }
        }
        __syncthreads();
    }

    // epilogue: regs -> gmem with bias (float2 stores)
    #pragma unroll
    for (int mi = 0; mi < 4; mi++) {
        int row = m0 + m_w + mi * 16 + g;
        #pragma unroll
        for (int ni = 0; ni < 4; ni++) {
            int n = n0 + n_w + ni * 8 + tig * 2;
            float b0f = bias[n], b1f = bias[n + 1];
            float2 v0 = make_float2(acc[mi][ni][0] + b0f, acc[mi][ni][1] + b1f);
            float2 v1 = make_float2(acc[mi][ni][2] + b0f, acc[mi][ni][3] + b1f);
            *reinterpret_cast<float2*>(out + (size_t)row * HH + n) = v0;
            *reinterpret_cast<float2*>(out + (size_t)(row + 8) * HH + n) = v1;
        }
    }
}

// ---------------------------------------------------------------------------
// Kernel 2: fused attention (unchanged from round 1 — fp32 SIMT)
// ---------------------------------------------------------------------------
static constexpr int SPAD = 513;
static constexpr int KPAD = 65;

__global__ __launch_bounds__(256) void attn_kernel(
    const float* __restrict__ mask,
    float* __restrict__ ctx,
    float* __restrict__ probs)
{
    extern __shared__ float smemf[];
    float* sc  = smemf;
    float* qs  = sc + 64 * SPAD;
    float* ks  = qs + 64 * KPAD;
    float* msk = ks + 64 * KPAD;

    const int qt = blockIdx.x;
    const int h  = blockIdx.y;
    const int b  = blockIdx.z;
    const int tid  = threadIdx.x;
    const int trow = tid >> 4;
    const int tcol = tid & 15;
    const int q0 = qt * 64;
    const float scale = 0.125f;

    const float* Q = g_qkv[0];
    const float* K = g_qkv[1];
    const float* V = g_qkv[2];

    for (int j = tid; j < SS; j += 256)
        msk[j] = (1.0f - mask[(size_t)b * SS + j]) * -10000.0f;

    #pragma unroll
    for (int e = 0; e < 16; e++) {
        int flat = tid + e * 256;
        int r = flat >> 6, d = flat & 63;
        qs[r * KPAD + d] = Q[((size_t)b * SS + q0 + r) * HH + h * HDD + d];
    }
    __syncthreads();

    for (int kt = 0; kt < 8; kt++) {
        #pragma unroll
        for (int e = 0; e < 16; e++) {
            int flat = tid + e * 256;
            int r = flat >> 6, d = flat & 63;
            ks[r * KPAD + d] = K[((size_t)b * SS + kt * 64 + r) * HH + h * HDD + d];
        }
        __syncthreads();

        float acc[4][4] = {};
        #pragma unroll
        for (int d = 0; d < 64; d++) {
            float a[4], bb[4];
            #pragma unroll
            for (int i = 0; i < 4; i++) a[i] = qs[(trow * 4 + i) * KPAD + d];
            #pragma unroll
            for (int j = 0; j < 4; j++) bb[j] = ks[(tcol * 4 + j) * KPAD + d];
            #pragma unroll
            for (int i = 0; i < 4; i++)
                #pragma unroll
                for (int j = 0; j < 4; j++)
                    acc[i][j] += a[i] * bb[j];
        }
        #pragma unroll
        for (int i = 0; i < 4; i++)
            #pragma unroll
            for (int j = 0; j < 4; j++) {
                int col = kt * 64 + tcol * 4 + j;
                sc[(trow * 4 + i) * SPAD + col] = acc[i][j] * scale + msk[col];
            }
        __syncthreads();
    }

    {
        const int warp = tid >> 5, lane = tid & 31;
        for (int rr = 0; rr < 8; rr++) {
            int r = warp * 8 + rr;
            float* row = sc + r * SPAD;
            float m = -1e30f;
            #pragma unroll
            for (int i = 0; i < 16; i++) m = fmaxf(m, row[lane + i * 32]);
            #pragma unroll
            for (int o = 16; o > 0; o >>= 1) m = fmaxf(m, __shfl_xor_sync(0xffffffffu, m, o));
            float vals[16];
            float sum = 0.0f;
            #pragma unroll
            for (int i = 0; i < 16; i++) {
                float e = expf(row[lane + i * 32] - m);
                vals[i] = e;
                sum += e;
            }
            #pragma unroll
            for (int o = 16; o > 0; o >>= 1) sum += __shfl_xor_sync(0xffffffffu, sum, o);
            float inv = 1.0f / sum;
            size_t pbase = (((size_t)b * NHH + h) * SS + q0 + r) * SS;
            #pragma unroll
            for (int i = 0; i < 16; i++) {
                float p = vals[i] * inv;
                row[lane + i * 32] = p;
                probs[pbase + lane + i * 32] = p;
            }
        }
    }
    __syncthreads();

    float acc[4][4] = {};
    for (int kt = 0; kt < 8; kt++) {
        #pragma unroll
        for (int e = 0; e < 16; e++) {
            int flat = tid + e * 256;
            int r = flat >> 6, d = flat & 63;
            ks[r * KPAD + d] = V[((size_t)b * SS + kt * 64 + r) * HH + h * HDD + d];
        }
        __syncthreads();

        #pragma unroll
        for (int kk = 0; kk < 64; kk++) {
            float a[4], bb[4];
            #pragma unroll
            for (int i = 0; i < 4; i++) a[i] = sc[(trow * 4 + i) * SPAD + kt * 64 + kk];
            #pragma unroll
            for (int j = 0; j < 4; j++) bb[j] = ks[kk * KPAD + tcol * 4 + j];
            #pragma unroll
            for (int i = 0; i < 4; i++)
                #pragma unroll
                for (int j = 0; j < 4; j++)
                    acc[i][j] += a[i] * bb[j];
        }
        __syncthreads();
    }

    #pragma unroll
    for (int i = 0; i < 4; i++) {
        int q = q0 + trow * 4 + i;
        #pragma unroll
        for (int j = 0; j < 4; j++) {
            int d = tcol * 4 + j;
            ctx[((size_t)b * SS + q) * HH + h * HDD + d] = acc[i][j];
        }
    }
}

// ---------------------------------------------------------------------------
// kernel_launch
// Inputs: hidden_state, attention_mask, Wq, bq, Wk, bk, Wv, bv
// Output: ctx [16,512,768] then probs [16,12,512,512]
// ---------------------------------------------------------------------------
extern "C" void kernel_launch(void* const* d_in, const int* in_sizes, int n_in,
                              void* d_out, int out_size)
{
    const float* hidden = (const float*)d_in[0];
    const float* mask   = (const float*)d_in[1];
    const float* Wq = (const float*)d_in[2];
    const float* bq = (const float*)d_in[3];
    const float* Wk = (const float*)d_in[4];
    const float* bk = (const float*)d_in[5];
    const float* Wv = (const float*)d_in[6];
    const float* bv = (const float*)d_in[7];

    float* out   = (float*)d_out;
    float* ctx   = out;
    float* probs = out + (size_t)BB * SS * HH;

    // 0) split fp32 -> bf16 hi/lo
    dim3 gs(512, 1, 4);
    split_kernel<<<gs, 256>>>(hidden, Wq, Wk, Wv);

    // 1) QKV projections (mma.sync bf16x3)
    cudaFuncSetAttribute(qkv_gemm_mma, cudaFuncAttributeMaxDynamicSharedMemorySize, GEMM_SMEM_TOTAL);
    dim3 g1(HH / 128, MROWS / 128, 3);
    qkv_gemm_mma<<<g1, 256, GEMM_SMEM_TOTAL>>>(bq, bk, bv);

    // 2) fused attention
    const int smem_bytes = (64 * SPAD + 2 * 64 * KPAD + SS) * (int)sizeof(float);
    cudaFuncSetAttribute(attn_kernel, cudaFuncAttributeMaxDynamicSharedMemorySize, smem_bytes);
    dim3 g2(SS / 64, NHH, BB);
    attn_kernel<<<g2, 256, smem_bytes>>>(mask, ctx, probs);
}

// round 4
// speedup vs baseline: 3.0756x; 2.8845x over previous
#include <cuda_runtime.h>
#include <cuda_fp16.h>
#include <cstdint>
#include <math.h>

// Problem constants
static constexpr int BB = 16;     // batch
static constexpr int SS = 512;    // seq len
static constexpr int HH = 768;    // hidden
static constexpr int NHH = 12;    // heads
static constexpr int HDD = 64;    // head dim
static constexpr int MROWS = BB * SS;  // 8192

// Scratch (static device allocations allowed)
__device__ __half g_qkvh[3][(size_t)MROWS * HH];   // fp16 Q,K,V
__device__ __half g_xh[(size_t)MROWS * HH];        // fp16 hidden
__device__ __half g_wh[3][(size_t)HH * HH];        // fp16 weights

// ---------------------------------------------------------------------------
// helpers
// ---------------------------------------------------------------------------
__device__ __forceinline__ uint32_t smem_to_u32(const void* p) {
    uint32_t a;
    asm("{ .reg .u64 t; cvta.to.shared.u64 t, %1; cvt.u32.u64 %0, t; }" : "=r"(a) : "l"(p));
    return a;
}
#define CP_ASYNC16(dst_u32, src_ptr) \
    asm volatile("cp.async.cg.shared.global [%0], [%1], 16;" :: "r"(dst_u32), "l"(src_ptr) : "memory")
#define CP_COMMIT() asm volatile("cp.async.commit_group;" ::: "memory")
#define CP_WAIT(n)  asm volatile("cp.async.wait_group %0;" :: "n"(n) : "memory")

__device__ __forceinline__ void mma_fp16(float d[4],
                                         uint32_t a0, uint32_t a1, uint32_t a2, uint32_t a3,
                                         uint32_t b0, uint32_t b1) {
    asm volatile(
        "mma.sync.aligned.m16n8k16.row.col.f32.f16.f16.f32 "
        "{%0,%1,%2,%3}, {%4,%5,%6,%7}, {%8,%9}, {%0,%1,%2,%3};"
        : "+f"(d[0]), "+f"(d[1]), "+f"(d[2]), "+f"(d[3])
        : "r"(a0), "r"(a1), "r"(a2), "r"(a3), "r"(b0), "r"(b1));
}

// FMA-only exp (no MUFU): e^x = 2^(x*log2e), degree-6 Taylor on [-0.5,0.5]
__device__ __forceinline__ float fexp(float x) {
    float y = x * 1.4426950408889634f;
    y = fmaxf(y, -120.0f);
    float r = rintf(y);
    float f = y - r;
    float p = 1.5403530393381609e-4f;
    p = fmaf(p, f, 1.3333558146428443e-3f);
    p = fmaf(p, f, 9.6181291076284770e-3f);
    p = fmaf(p, f, 5.5504108664821580e-2f);
    p = fmaf(p, f, 2.4022650695910070e-1f);
    p = fmaf(p, f, 6.9314718055994531e-1f);
    p = fmaf(p, f, 1.0f);
    int i = (int)r;
    float s = __int_as_float((i + 127) << 23);
    return p * s;
}

// ---------------------------------------------------------------------------
// Kernel 0: fp32 -> fp16 conversion.  z=0: hidden, z=1..3: Wq/Wk/Wv
// ---------------------------------------------------------------------------
__global__ __launch_bounds__(256) void split_kernel(
    const float* __restrict__ X,
    const float* __restrict__ Wq, const float* __restrict__ Wk, const float* __restrict__ Wv)
{
    const int z = blockIdx.z;
    const float* src = (z == 0) ? X : (z == 1) ? Wq : (z == 2) ? Wk : Wv;
    __half* dst = (z == 0) ? g_xh : g_wh[z - 1];
    size_t n = (z == 0) ? (size_t)MROWS * HH : (size_t)HH * HH;

    for (size_t i = (size_t)blockIdx.x * blockDim.x + threadIdx.x; i < n;
         i += (size_t)gridDim.x * blockDim.x) {
        dst[i] = __float2half_rn(src[i]);
    }
}

// ---------------------------------------------------------------------------
// Kernel 1: QKV projection, fp16 mma.sync single precision.
// out[m][n] = fp16( sum_k X[m][k]*W[n][k] + b[n] )
// Block tile 128x128, K tile 32, 8 warps 2(m)x4(n); warp tile 64x32.
// ---------------------------------------------------------------------------
static constexpr int BK = 32;
static constexpr int KSTRIDE = 40;                       // fp16 per smem row (80B)
static constexpr int TILE_BYTES_G = 128 * KSTRIDE * 2;   // 10240
static constexpr int STAGE_BYTES = 2 * TILE_BYTES_G;     // A,B
static constexpr int GEMM_SMEM_TOTAL = 2 * STAGE_BYTES;  // 40960
static constexpr int NKT = HH / BK;                      // 24

__device__ __forceinline__ void load_stage_async(
    char* smem, int s,
    const __half* __restrict__ A, const __half* __restrict__ B,
    int k0, int tid)
{
    char* base = smem + s * STAGE_BYTES;
    #pragma unroll
    for (int e = 0; e < 4; e++) {
        const int tile = e >> 1;                 // 0:A 1:B
        int idx = ((e & 1) << 8) + tid;          // 0..511
        int r = idx >> 2;                        // 0..127
        int q = idx & 3;                         // 16B quad within 64B row
        const __half* src = (tile == 0 ? A : B) + (size_t)r * HH + k0 + q * 8;
        uint32_t dst = smem_to_u32(base + tile * TILE_BYTES_G + (r * KSTRIDE + q * 8) * 2);
        CP_ASYNC16(dst, src);
    }
}

__global__ __launch_bounds__(256, 1) void qkv_gemm_mma(
    const float* __restrict__ bq, const float* __restrict__ bk, const float* __restrict__ bv)
{
    extern __shared__ char smem[];
    const int tid = threadIdx.x;
    const int wid = tid >> 5;
    const int lane = tid & 31;
    const int g = lane >> 2;
    const int tig = lane & 3;

    const int which = blockIdx.z;
    const int n0 = blockIdx.x * 128;
    const int m0 = blockIdx.y * 128;
    const float* bias = (which == 0) ? bq : (which == 1) ? bk : bv;
    __half* out = g_qkvh[which];

    const __half* A = g_xh + (size_t)m0 * HH;
    const __half* B = g_wh[which] + (size_t)n0 * HH;

    const int m_w = (wid & 1) * 64;
    const int n_w = (wid >> 1) * 32;

    float acc[4][4][4];
    #pragma unroll
    for (int i = 0; i < 4; i++)
        #pragma unroll
        for (int j = 0; j < 4; j++)
            #pragma unroll
            for (int r = 0; r < 4; r++) acc[i][j][r] = 0.0f;

    load_stage_async(smem, 0, A, B, 0, tid);
    CP_COMMIT();

    for (int kt = 0; kt < NKT; kt++) {
        const int s = kt & 1;
        if (kt + 1 < NKT) {
            load_stage_async(smem, s ^ 1, A, B, (kt + 1) * BK, tid);
            CP_COMMIT();
            CP_WAIT(1);
        } else {
            CP_WAIT(0);
        }
        __syncthreads();

        const uint32_t* sA = (const uint32_t*)(smem + s * STAGE_BYTES);
        const uint32_t* sB = (const uint32_t*)(smem + s * STAGE_BYTES + TILE_BYTES_G);

        #pragma unroll
        for (int kk = 0; kk < BK; kk += 16) {
            const int kh = (kk >> 1) + tig;
            uint32_t af[4][4];
            #pragma unroll
            for (int mi = 0; mi < 4; mi++) {
                int r0 = (m_w + mi * 16 + g) * (KSTRIDE / 2);
                int r1 = r0 + 8 * (KSTRIDE / 2);
                af[mi][0] = sA[r0 + kh];
                af[mi][1] = sA[r1 + kh];
                af[mi][2] = sA[r0 + kh + 4];
                af[mi][3] = sA[r1 + kh + 4];
            }
            uint32_t bf[4][2];
            #pragma unroll
            for (int ni = 0; ni < 4; ni++) {
                int r = (n_w + ni * 8 + g) * (KSTRIDE / 2);
                bf[ni][0] = sB[r + kh];
                bf[ni][1] = sB[r + kh + 4];
            }
            #pragma unroll
            for (int mi = 0; mi < 4; mi++)
                #pragma unroll
                for (int ni = 0; ni < 4; ni++)
                    mma_fp16(acc[mi][ni], af[mi][0], af[mi][1], af[mi][2], af[mi][3],
                             bf[ni][0], bf[ni][1]);
        }
        __syncthreads();
    }

    // epilogue: fp32 acc + bias -> fp16 (half2 stores)
    #pragma unroll
    for (int mi = 0; mi < 4; mi++) {
        int row = m0 + m_w + mi * 16 + g;
        #pragma unroll
        for (int ni = 0; ni < 4; ni++) {
            int n = n0 + n_w + ni * 8 + tig * 2;
            float b0f = bias[n], b1f = bias[n + 1];
            __half2 v0 = __floats2half2_rn(acc[mi][ni][0] + b0f, acc[mi][ni][1] + b1f);
            __half2 v1 = __floats2half2_rn(acc[mi][ni][2] + b0f, acc[mi][ni][3] + b1f);
            *reinterpret_cast<__half2*>(out + (size_t)row * HH + n) = v0;
            *reinterpret_cast<__half2*>(out + (size_t)(row + 8) * HH + n) = v1;
        }
    }
}

// ---------------------------------------------------------------------------
// Kernel 2: fused attention with fp16 HMMA.
// CTA = (64 q rows, head h, batch b). 256 threads = 8 warps (2m x 4n).
// Phase 1: scores(64x512) = Q K^T * scale + mask  (fp32 in smem)
// Phase 2: softmax rows (fp32, FMA exp), write probs fp32, store P fp16
// Phase 3: ctx = P @ V via HMMA (V transposed in smem)
// ---------------------------------------------------------------------------
static constexpr int SCST = 520;   // fp32 score row stride
static constexpr int PST  = 520;   // fp16 P row stride (260 u32: 260%32=4 -> conflict-free)
static constexpr int TST  = 72;    // fp16 tile row stride (36 u32: 36%32=4 -> conflict-free)

static constexpr int SM_SC  = 0;                       // 64*520*4   = 133120
static constexpr int SM_P   = SM_SC + 64 * SCST * 4;   // 64*520*2   =  66560
static constexpr int SM_Q   = SM_P + 64 * PST * 2;     // 64*72*2    =   9216
static constexpr int SM_KV  = SM_Q + 64 * TST * 2;     // 64*72*2    =   9216
static constexpr int SM_MSK = SM_KV + 64 * TST * 2;    // 512*4      =   2048
static constexpr int ATTN_SMEM_TOTAL = SM_MSK + SS * 4;  // 220160

__global__ __launch_bounds__(256, 1) void attn_kernel(
    const float* __restrict__ mask,
    float* __restrict__ ctx,
    float* __restrict__ probs)
{
    extern __shared__ char smem[];
    float*    sc  = (float*)(smem + SM_SC);
    __half*   ps  = (__half*)(smem + SM_P);
    __half*   qs  = (__half*)(smem + SM_Q);
    __half*   kv  = (__half*)(smem + SM_KV);
    float*    msk = (float*)(smem + SM_MSK);

    const int qt = blockIdx.x;   // 0..7
    const int h  = blockIdx.y;   // 0..11
    const int b  = blockIdx.z;   // 0..15
    const int tid  = threadIdx.x;
    const int wid  = tid >> 5;
    const int lane = tid & 31;
    const int g    = lane >> 2;
    const int tig  = lane & 3;
    const int wm   = (wid & 1) * 32;   // warp m offset within 64
    const int wn   = (wid >> 1) * 16;  // warp n offset within 64
    const int q0 = qt * 64;
    const float scale = 0.125f;

    const __half* Q = g_qkvh[0];
    const __half* K = g_qkvh[1];
    const __half* V = g_qkvh[2];

    // mask additive term
    for (int j = tid; j < SS; j += 256)
        msk[j] = (1.0f - mask[(size_t)b * SS + j]) * -10000.0f;

    // load Q tile [64 x 64] fp16 (uint4 = 8 halves)
    #pragma unroll
    for (int e = 0; e < 2; e++) {
        int slot = tid + e * 256;            // 0..511
        int r = slot >> 3, q = slot & 7;
        uint4 v = *reinterpret_cast<const uint4*>(
            Q + ((size_t)(b * SS + q0 + r)) * HH + h * HDD + q * 8);
        *reinterpret_cast<uint4*>(qs + r * TST + q * 8) = v;
    }
    __syncthreads();

    const uint32_t* qs32 = (const uint32_t*)qs;
    const uint32_t* kv32 = (const uint32_t*)kv;
    const uint32_t* ps32 = (const uint32_t*)ps;

    // ---- phase 1: scores ----
    for (int kt = 0; kt < 8; kt++) {
        #pragma unroll
        for (int e = 0; e < 2; e++) {
            int slot = tid + e * 256;
            int r = slot >> 3, q = slot & 7;
            uint4 v = *reinterpret_cast<const uint4*>(
                K + ((size_t)(b * SS + kt * 64 + r)) * HH + h * HDD + q * 8);
            *reinterpret_cast<uint4*>(kv + r * TST + q * 8) = v;
        }
        __syncthreads();

        float acc[2][2][4];
        #pragma unroll
        for (int mi = 0; mi < 2; mi++)
            #pragma unroll
            for (int ni = 0; ni < 2; ni++)
                #pragma unroll
                for (int r = 0; r < 4; r++) acc[mi][ni][r] = 0.0f;

        #pragma unroll
        for (int kk = 0; kk < 64; kk += 16) {
            const int kh = (kk >> 1) + tig;
            uint32_t af[2][4];
            #pragma unroll
            for (int mi = 0; mi < 2; mi++) {
                int r0 = (wm + mi * 16 + g) * (TST / 2);
                int r1 = r0 + 8 * (TST / 2);
                af[mi][0] = qs32[r0 + kh];
                af[mi][1] = qs32[r1 + kh];
                af[mi][2] = qs32[r0 + kh + 4];
                af[mi][3] = qs32[r1 + kh + 4];
            }
            uint32_t bf[2][2];
            #pragma unroll
            for (int ni = 0; ni < 2; ni++) {
                int r = (wn + ni * 8 + g) * (TST / 2);
                bf[ni][0] = kv32[r + kh];
                bf[ni][1] = kv32[r + kh + 4];
            }
            #pragma unroll
            for (int mi = 0; mi < 2; mi++)
                #pragma unroll
                for (int ni = 0; ni < 2; ni++)
                    mma_fp16(acc[mi][ni], af[mi][0], af[mi][1], af[mi][2], af[mi][3],
                             bf[ni][0], bf[ni][1]);
        }

        // store scores: thread (g,tig) owns rows (m+g, m+g+8), cols n+tig*2..+1
        #pragma unroll
        for (int mi = 0; mi < 2; mi++) {
            int row = wm + mi * 16 + g;
            #pragma unroll
            for (int ni = 0; ni < 2; ni++) {
                int col = kt * 64 + wn + ni * 8 + tig * 2;
                sc[row * SCST + col]       = acc[mi][ni][0] * scale + msk[col];
                sc[row * SCST + col + 1]   = acc[mi][ni][1] * scale + msk[col + 1];
                sc[(row + 8) * SCST + col]     = acc[mi][ni][2] * scale + msk[col];
                sc[(row + 8) * SCST + col + 1] = acc[mi][ni][3] * scale + msk[col + 1];
            }
        }
        __syncthreads();
    }

    // ---- phase 2: softmax (warp per 8 rows), write probs + fp16 P ----
    {
        for (int rr = 0; rr < 8; rr++) {
            int r = wid * 8 + rr;
            float* row = sc + r * SCST;
            float m = -1e30f;
            #pragma unroll
            for (int i = 0; i < 16; i++) m = fmaxf(m, row[lane + i * 32]);
            #pragma unroll
            for (int o = 16; o > 0; o >>= 1) m = fmaxf(m, __shfl_xor_sync(0xffffffffu, m, o));
            float vals[16];
            float sum = 0.0f;
            #pragma unroll
            for (int i = 0; i < 16; i++) {
                float e = fexp(row[lane + i * 32] - m);
                vals[i] = e;
                sum += e;
            }
            #pragma unroll
            for (int o = 16; o > 0; o >>= 1) sum += __shfl_xor_sync(0xffffffffu, sum, o);
            float inv = 1.0f / sum;
            size_t pbase = (((size_t)b * NHH + h) * SS + q0 + r) * SS;
            #pragma unroll
            for (int i = 0; i < 16; i++) {
                float p = vals[i] * inv;
                probs[pbase + lane + i * 32] = p;
                ps[r * PST + lane + i * 32] = __float2half_rn(p);
            }
        }
    }
    __syncthreads();

    // ---- phase 3: ctx = P @ V ----
    float cacc[2][2][4];
    #pragma unroll
    for (int mi = 0; mi < 2; mi++)
        #pragma unroll
        for (int ni = 0; ni < 2; ni++)
            #pragma unroll
            for (int r = 0; r < 4; r++) cacc[mi][ni][r] = 0.0f;

    for (int kt = 0; kt < 8; kt++) {
        // load V tile [64kv x 64d] transposed into kv smem: kv[d][kvrow]
        #pragma unroll
        for (int e = 0; e < 2; e++) {
            int slot = tid + e * 256;
            int r = slot >> 3, q = slot & 7;      // r = kv row, q = d quad
            uint4 v = *reinterpret_cast<const uint4*>(
                V + ((size_t)(b * SS + kt * 64 + r)) * HH + h * HDD + q * 8);
            __half hv[8];
            *reinterpret_cast<uint4*>(hv) = v;
            #pragma unroll
            for (int j = 0; j < 8; j++)
                kv[(q * 8 + j) * TST + r] = hv[j];
        }
        __syncthreads();

        #pragma unroll
        for (int kk = 0; kk < 64; kk += 16) {
            const int khp = ((kt * 64 + kk) >> 1) + tig;   // u32 idx in P row
            const int khv = (kk >> 1) + tig;               // u32 idx in VT row
            uint32_t af[2][4];
            #pragma unroll
            for (int mi = 0; mi < 2; mi++) {
                int r0 = (wm + mi * 16 + g) * (PST / 2);
                int r1 = r0 + 8 * (PST / 2);
                af[mi][0] = ps32[r0 + khp];
                af[mi][1] = ps32[r1 + khp];
                af[mi][2] = ps32[r0 + khp + 4];
                af[mi][3] = ps32[r1 + khp + 4];
            }
            uint32_t bf[2][2];
            #pragma unroll
            for (int ni = 0; ni < 2; ni++) {
                int r = (wn + ni * 8 + g) * (TST / 2);
                bf[ni][0] = kv32[r + khv];
                bf[ni][1] = kv32[r + khv + 4];
            }
            #pragma unroll
            for (int mi = 0; mi < 2; mi++)
                #pragma unroll
                for (int ni = 0; ni < 2; ni++)
                    mma_fp16(cacc[mi][ni], af[mi][0], af[mi][1], af[mi][2], af[mi][3],
                             bf[ni][0], bf[ni][1]);
        }
        __syncthreads();
    }

    // epilogue: ctx fp32
    #pragma unroll
    for (int mi = 0; mi < 2; mi++) {
        int row = wm + mi * 16 + g;
        #pragma unroll
        for (int ni = 0; ni < 2; ni++) {
            int d = wn + ni * 8 + tig * 2;
            size_t base0 = ((size_t)(b * SS + q0 + row)) * HH + h * HDD + d;
            size_t base1 = ((size_t)(b * SS + q0 + row + 8)) * HH + h * HDD + d;
            *reinterpret_cast<float2*>(ctx + base0) = make_float2(cacc[mi][ni][0], cacc[mi][ni][1]);
            *reinterpret_cast<float2*>(ctx + base1) = make_float2(cacc[mi][ni][2], cacc[mi][ni][3]);
        }
    }
}

// ---------------------------------------------------------------------------
// kernel_launch
// Inputs: hidden_state, attention_mask, Wq, bq, Wk, bk, Wv, bv
// Output: ctx [16,512,768] then probs [16,12,512,512]
// ---------------------------------------------------------------------------
extern "C" void kernel_launch(void* const* d_in, const int* in_sizes, int n_in,
                              void* d_out, int out_size)
{
    const float* hidden = (const float*)d_in[0];
    const float* mask   = (const float*)d_in[1];
    const float* Wq = (const float*)d_in[2];
    const float* bq = (const float*)d_in[3];
    const float* Wk = (const float*)d_in[4];
    const float* bk = (const float*)d_in[5];
    const float* Wv = (const float*)d_in[6];
    const float* bv = (const float*)d_in[7];

    float* out   = (float*)d_out;
    float* ctx   = out;
    float* probs = out + (size_t)BB * SS * HH;

    // 0) fp32 -> fp16
    dim3 gs(512, 1, 4);
    split_kernel<<<gs, 256>>>(hidden, Wq, Wk, Wv);

    // 1) QKV projections (fp16 mma.sync)
    cudaFuncSetAttribute(qkv_gemm_mma, cudaFuncAttributeMaxDynamicSharedMemorySize, GEMM_SMEM_TOTAL);
    dim3 g1(HH / 128, MROWS / 128, 3);
    qkv_gemm_mma<<<g1, 256, GEMM_SMEM_TOTAL>>>(bq, bk, bv);

    // 2) fused attention (fp16 HMMA + fp32 softmax)
    cudaFuncSetAttribute(attn_kernel, cudaFuncAttributeMaxDynamicSharedMemorySize, ATTN_SMEM_TOTAL);
    dim3 g2(SS / 64, NHH, BB);
    attn_kernel<<<g2, 256, ATTN_SMEM_TOTAL>>>(mask, ctx, probs);
}

// round 5
// speedup vs baseline: 4.3900x; 1.4274x over previous
#include <cuda_runtime.h>
#include <cuda_fp16.h>
#include <cstdint>
#include <math.h>

// Problem constants
static constexpr int BB = 16;     // batch
static constexpr int SS = 512;    // seq len
static constexpr int HH = 768;    // hidden
static constexpr int NHH = 12;    // heads
static constexpr int HDD = 64;    // head dim
static constexpr int MROWS = BB * SS;  // 8192

// Scratch (static device allocations allowed)
__device__ __half g_qkvh[3][(size_t)MROWS * HH];   // fp16 Q,K,V
__device__ __half g_xh[(size_t)MROWS * HH];        // fp16 hidden
__device__ __half g_wh[3][(size_t)HH * HH];        // fp16 weights

// ---------------------------------------------------------------------------
// helpers
// ---------------------------------------------------------------------------
__device__ __forceinline__ uint32_t smem_to_u32(const void* p) {
    uint32_t a;
    asm("{ .reg .u64 t; cvta.to.shared.u64 t, %1; cvt.u32.u64 %0, t; }" : "=r"(a) : "l"(p));
    return a;
}
#define CP_ASYNC16(dst_u32, src_ptr) \
    asm volatile("cp.async.cg.shared.global [%0], [%1], 16;" :: "r"(dst_u32), "l"(src_ptr) : "memory")
#define CP_COMMIT() asm volatile("cp.async.commit_group;" ::: "memory")
#define CP_WAIT(n)  asm volatile("cp.async.wait_group %0;" :: "n"(n) : "memory")

#define LDSM_X4(r0, r1, r2, r3, a) \
    asm volatile("ldmatrix.sync.aligned.m8n8.x4.shared.b16 {%0,%1,%2,%3}, [%4];" \
                 : "=r"(r0), "=r"(r1), "=r"(r2), "=r"(r3) : "r"(a))
#define LDSM_X4T(r0, r1, r2, r3, a) \
    asm volatile("ldmatrix.sync.aligned.m8n8.x4.trans.shared.b16 {%0,%1,%2,%3}, [%4];" \
                 : "=r"(r0), "=r"(r1), "=r"(r2), "=r"(r3) : "r"(a))

__device__ __forceinline__ void mma_fp16(float d[4],
                                         uint32_t a0, uint32_t a1, uint32_t a2, uint32_t a3,
                                         uint32_t b0, uint32_t b1) {
    asm volatile(
        "mma.sync.aligned.m16n8k16.row.col.f32.f16.f16.f32 "
        "{%0,%1,%2,%3}, {%4,%5,%6,%7}, {%8,%9}, {%0,%1,%2,%3};"
        : "+f"(d[0]), "+f"(d[1]), "+f"(d[2]), "+f"(d[3])
        : "r"(a0), "r"(a1), "r"(a2), "r"(a3), "r"(b0), "r"(b1));
}

// FMA-only exp (no MUFU): e^x = 2^(x*log2e)
__device__ __forceinline__ float fexp(float x) {
    float y = x * 1.4426950408889634f;
    y = fmaxf(y, -120.0f);
    float r = rintf(y);
    float f = y - r;
    float p = 1.5403530393381609e-4f;
    p = fmaf(p, f, 1.3333558146428443e-3f);
    p = fmaf(p, f, 9.6181291076284770e-3f);
    p = fmaf(p, f, 5.5504108664821580e-2f);
    p = fmaf(p, f, 2.4022650695910070e-1f);
    p = fmaf(p, f, 6.9314718055994531e-1f);
    p = fmaf(p, f, 1.0f);
    int i = (int)r;
    float s = __int_as_float((i + 127) << 23);
    return p * s;
}

// ---------------------------------------------------------------------------
// Kernel 0: fp32 -> fp16 conversion (vectorized).  z=0: hidden, z=1..3: W
// ---------------------------------------------------------------------------
__global__ __launch_bounds__(256) void split_kernel(
    const float* __restrict__ X,
    const float* __restrict__ Wq, const float* __restrict__ Wk, const float* __restrict__ Wv)
{
    const int z = blockIdx.z;
    const float* src = (z == 0) ? X : (z == 1) ? Wq : (z == 2) ? Wk : Wv;
    __half* dst = (z == 0) ? g_xh : g_wh[z - 1];
    size_t n4 = ((z == 0) ? (size_t)MROWS * HH : (size_t)HH * HH) >> 2;

    const float4* src4 = (const float4*)src;
    for (size_t i = (size_t)blockIdx.x * blockDim.x + threadIdx.x; i < n4;
         i += (size_t)gridDim.x * blockDim.x) {
        float4 v = src4[i];
        __half2 h0 = __floats2half2_rn(v.x, v.y);
        __half2 h1 = __floats2half2_rn(v.z, v.w);
        uint2 st;
        st.x = reinterpret_cast<uint32_t&>(h0);
        st.y = reinterpret_cast<uint32_t&>(h1);
        *reinterpret_cast<uint2*>(dst + 4 * i) = st;
    }
}

// ---------------------------------------------------------------------------
// Kernel 1: QKV projection, fp16 mma.sync + ldmatrix, 3-stage cp.async.
// out[m][n] = fp16( sum_k X[m][k]*W[n][k] + b[n] )
// Block tile 128x128, K tile 32, 8 warps 2(m)x4(n); warp tile 64x32.
// ---------------------------------------------------------------------------
static constexpr int BK = 32;
static constexpr int KSTRIDE = 40;                       // fp16 per smem row (80B)
static constexpr int TILE_BYTES_G = 128 * KSTRIDE * 2;   // 10240
static constexpr int STAGE_BYTES = 2 * TILE_BYTES_G;     // A,B = 20480
static constexpr int GEMM_SMEM_TOTAL = 3 * STAGE_BYTES;  // 61440
static constexpr int NKT = HH / BK;                      // 24

__device__ __forceinline__ void load_stage_async(
    char* smem, int s,
    const __half* __restrict__ A, const __half* __restrict__ B,
    int k0, int tid)
{
    char* base = smem + s * STAGE_BYTES;
    #pragma unroll
    for (int e = 0; e < 4; e++) {
        const int tile = e >> 1;                 // 0:A 1:B
        int idx = ((e & 1) << 8) + tid;          // 0..511
        int r = idx >> 2;                        // 0..127
        int q = idx & 3;                         // 16B quad
        const __half* src = (tile == 0 ? A : B) + (size_t)r * HH + k0 + q * 8;
        uint32_t dst = smem_to_u32(base + tile * TILE_BYTES_G + (r * KSTRIDE + q * 8) * 2);
        CP_ASYNC16(dst, src);
    }
}

__global__ __launch_bounds__(256, 2) void qkv_gemm_mma(
    const float* __restrict__ bq, const float* __restrict__ bk, const float* __restrict__ bv)
{
    extern __shared__ char smem[];
    const uint32_t smem_base = smem_to_u32(smem);
    const int tid = threadIdx.x;
    const int wid = tid >> 5;
    const int lane = tid & 31;
    const int g = lane >> 2;
    const int tig = lane & 3;

    const int which = blockIdx.z;
    const int n0 = blockIdx.x * 128;
    const int m0 = blockIdx.y * 128;
    const float* bias = (which == 0) ? bq : (which == 1) ? bk : bv;
    __half* out = g_qkvh[which];

    const __half* A = g_xh + (size_t)m0 * HH;
    const __half* B = g_wh[which] + (size_t)n0 * HH;

    const int m_w = (wid & 1) * 64;
    const int n_w = (wid >> 1) * 32;

    // ldmatrix per-lane byte offsets within a stage
    const uint32_t aoff = ((m_w + (lane & 15)) * KSTRIDE + (lane >> 4) * 8) * 2;
    const uint32_t boff = ((n_w + ((lane >> 4) & 1) * 8 + (lane & 7)) * KSTRIDE
                           + ((lane >> 3) & 1) * 8) * 2;

    float acc[4][4][4];
    #pragma unroll
    for (int i = 0; i < 4; i++)
        #pragma unroll
        for (int j = 0; j < 4; j++)
            #pragma unroll
            for (int r = 0; r < 4; r++) acc[i][j][r] = 0.0f;

    load_stage_async(smem, 0, A, B, 0, tid);
    CP_COMMIT();
    load_stage_async(smem, 1, A, B, BK, tid);
    CP_COMMIT();

    for (int kt = 0; kt < NKT; kt++) {
        const int s = kt % 3;
        if (kt + 2 < NKT) {
            load_stage_async(smem, (kt + 2) % 3, A, B, (kt + 2) * BK, tid);
            CP_COMMIT();
        }
        if (kt < NKT - 2)      { CP_WAIT(2); }
        else if (kt == NKT - 2){ CP_WAIT(1); }
        else                   { CP_WAIT(0); }
        __syncthreads();

        const uint32_t sA = smem_base + s * STAGE_BYTES;
        const uint32_t sB = sA + TILE_BYTES_G;

        #pragma unroll
        for (int kc = 0; kc < 2; kc++) {
            uint32_t a[4][4];
            #pragma unroll
            for (int mi = 0; mi < 4; mi++)
                LDSM_X4(a[mi][0], a[mi][1], a[mi][2], a[mi][3],
                        sA + aoff + mi * 16 * KSTRIDE * 2 + kc * 32);
            uint32_t b[2][4];
            #pragma unroll
            for (int n2 = 0; n2 < 2; n2++)
                LDSM_X4(b[n2][0], b[n2][1], b[n2][2], b[n2][3],
                        sB + boff + n2 * 16 * KSTRIDE * 2 + kc * 32);
            #pragma unroll
            for (int mi = 0; mi < 4; mi++)
                #pragma unroll
                for (int ni = 0; ni < 4; ni++)
                    mma_fp16(acc[mi][ni], a[mi][0], a[mi][1], a[mi][2], a[mi][3],
                             b[ni >> 1][(ni & 1) * 2], b[ni >> 1][(ni & 1) * 2 + 1]);
        }
        __syncthreads();
    }

    // epilogue: fp32 acc + bias -> fp16 (half2 stores)
    #pragma unroll
    for (int mi = 0; mi < 4; mi++) {
        int row = m0 + m_w + mi * 16 + g;
        #pragma unroll
        for (int ni = 0; ni < 4; ni++) {
            int n = n0 + n_w + ni * 8 + tig * 2;
            float b0f = bias[n], b1f = bias[n + 1];
            __half2 v0 = __floats2half2_rn(acc[mi][ni][0] + b0f, acc[mi][ni][1] + b1f);
            __half2 v1 = __floats2half2_rn(acc[mi][ni][2] + b0f, acc[mi][ni][3] + b1f);
            *reinterpret_cast<__half2*>(out + (size_t)row * HH + n) = v0;
            *reinterpret_cast<__half2*>(out + (size_t)(row + 8) * HH + n) = v1;
        }
    }
}

// ---------------------------------------------------------------------------
// Kernel 2: fused attention, fp16 HMMA + ldmatrix, cp.async K/V.
// CTA = (64 q rows, head h, batch b). 256 threads = 8 warps (2m x 4n).
// ---------------------------------------------------------------------------
static constexpr int SCST = 520;   // fp32 score row stride
static constexpr int PST  = 520;   // fp16 P row stride (260 u32 ≡ 4 mod 32)
static constexpr int TST  = 72;    // fp16 tile row stride (36 u32 ≡ 4 mod 32)

static constexpr int SM_SC  = 0;                        // 64*520*4 = 133120
static constexpr int SM_P   = SM_SC + 64 * SCST * 4;    // 64*520*2 =  66560
static constexpr int SM_Q   = SM_P + 64 * PST * 2;      // 64*72*2  =   9216
static constexpr int SM_KV  = SM_Q + 64 * TST * 2;      // 2 stages =  18432
static constexpr int SM_MSK = SM_KV + 2 * 64 * TST * 2; // 512*4    =   2048
static constexpr int ATTN_SMEM_TOTAL = SM_MSK + SS * 4; // 229376

__global__ __launch_bounds__(256, 1) void attn_kernel(
    const float* __restrict__ mask,
    float* __restrict__ ctx,
    float* __restrict__ probs)
{
    extern __shared__ char smem[];
    const uint32_t smem_base = smem_to_u32(smem);
    float*  sc  = (float*)(smem + SM_SC);
    __half* ps  = (__half*)(smem + SM_P);
    float*  msk = (float*)(smem + SM_MSK);

    const int qt = blockIdx.x;   // 0..7
    const int h  = blockIdx.y;   // 0..11
    const int b  = blockIdx.z;   // 0..15
    const int tid  = threadIdx.x;
    const int wid  = tid >> 5;
    const int lane = tid & 31;
    const int g    = lane >> 2;
    const int tig  = lane & 3;
    const int wm   = (wid & 1) * 32;   // warp m offset within 64
    const int wn   = (wid >> 1) * 16;  // warp n offset within 64
    const int q0 = qt * 64;
    const float scale = 0.125f;

    const __half* Q = g_qkvh[0];
    const __half* K = g_qkvh[1];
    const __half* V = g_qkvh[2];

    // mask additive term
    for (int j = tid; j < SS; j += 256)
        msk[j] = (1.0f - mask[(size_t)b * SS + j]) * -10000.0f;

    // load Q tile [64 x 64] fp16 into smem (uint4), then frags -> registers
    #pragma unroll
    for (int e = 0; e < 2; e++) {
        int slot = tid + e * 256;
        int r = slot >> 3, q = slot & 7;
        uint4 v = *reinterpret_cast<const uint4*>(
            Q + ((size_t)(b * SS + q0 + r)) * HH + h * HDD + q * 8);
        *reinterpret_cast<uint4*>((__half*)(smem + SM_Q) + r * TST + q * 8) = v;
    }
    // prologue: K tile 0 -> kv buf 0
    {
        const uint32_t kvb = smem_base + SM_KV;
        #pragma unroll
        for (int e = 0; e < 2; e++) {
            int slot = tid + e * 256;
            int r = slot >> 3, q = slot & 7;
            CP_ASYNC16(kvb + r * TST * 2 + q * 16,
                       K + ((size_t)(b * SS + r)) * HH + h * HDD + q * 8);
        }
        CP_COMMIT();
    }
    __syncthreads();

    // Q fragments resident in registers: qf[mi][kc][4]
    uint32_t qf[2][4][4];
    {
        const uint32_t qbase = smem_base + SM_Q
            + ((wm + (lane & 15)) * TST) * 2 + (lane >> 4) * 16;
        #pragma unroll
        for (int mi = 0; mi < 2; mi++)
            #pragma unroll
            for (int kc = 0; kc < 4; kc++)
                LDSM_X4(qf[mi][kc][0], qf[mi][kc][1], qf[mi][kc][2], qf[mi][kc][3],
                        qbase + mi * 16 * TST * 2 + kc * 32);
    }

    // per-lane ldmatrix offsets into a kv buffer
    const uint32_t koff_b = (((lane >> 4) & 1) * 8 + (lane & 7)) * TST * 2
                            + ((lane >> 3) & 1) * 16;          // K (non-trans, rows=kv cols=d? rows=n)
    const uint32_t voff_b = ((lane & 7) + ((lane >> 3) & 1) * 8) * TST * 2
                            + (((lane >> 4) & 1) * 8) * 2;     // V (trans)

    // ---- phase 1: scores = Q K^T ----
    for (int kt = 0; kt < 8; kt++) {
        const int s = kt & 1;
        if (kt + 1 < 8) {
            const uint32_t kvb = smem_base + SM_KV + ((kt + 1) & 1) * 64 * TST * 2;
            #pragma unroll
            for (int e = 0; e < 2; e++) {
                int slot = tid + e * 256;
                int r = slot >> 3, q = slot & 7;
                CP_ASYNC16(kvb + r * TST * 2 + q * 16,
                           K + ((size_t)(b * SS + (kt + 1) * 64 + r)) * HH + h * HDD + q * 8);
            }
            CP_COMMIT();
            CP_WAIT(1);
        } else {
            CP_WAIT(0);
        }
        __syncthreads();

        const uint32_t kvb = smem_base + SM_KV + s * 64 * TST * 2;
        float acc[2][2][4];
        #pragma unroll
        for (int mi = 0; mi < 2; mi++)
            #pragma unroll
            for (int ni = 0; ni < 2; ni++)
                #pragma unroll
                for (int r = 0; r < 4; r++) acc[mi][ni][r] = 0.0f;

        #pragma unroll
        for (int kc = 0; kc < 4; kc++) {
            uint32_t bf[4];
            LDSM_X4(bf[0], bf[1], bf[2], bf[3], kvb + wn * TST * 2 + koff_b + kc * 32);
            #pragma unroll
            for (int mi = 0; mi < 2; mi++) {
                mma_fp16(acc[mi][0], qf[mi][kc][0], qf[mi][kc][1], qf[mi][kc][2], qf[mi][kc][3],
                         bf[0], bf[1]);
                mma_fp16(acc[mi][1], qf[mi][kc][0], qf[mi][kc][1], qf[mi][kc][2], qf[mi][kc][3],
                         bf[2], bf[3]);
            }
        }

        #pragma unroll
        for (int mi = 0; mi < 2; mi++) {
            int row = wm + mi * 16 + g;
            #pragma unroll
            for (int ni = 0; ni < 2; ni++) {
                int col = kt * 64 + wn + ni * 8 + tig * 2;
                sc[row * SCST + col]           = acc[mi][ni][0] * scale + msk[col];
                sc[row * SCST + col + 1]       = acc[mi][ni][1] * scale + msk[col + 1];
                sc[(row + 8) * SCST + col]     = acc[mi][ni][2] * scale + msk[col];
                sc[(row + 8) * SCST + col + 1] = acc[mi][ni][3] * scale + msk[col + 1];
            }
        }
        __syncthreads();
    }

    // ---- phase 2: softmax, write probs fp32 + P fp16 ----
    for (int rr = 0; rr < 8; rr++) {
        int r = wid * 8 + rr;
        float* row = sc + r * SCST;
        float m = -1e30f;
        #pragma unroll
        for (int i = 0; i < 16; i++) m = fmaxf(m, row[lane + i * 32]);
        #pragma unroll
        for (int o = 16; o > 0; o >>= 1) m = fmaxf(m, __shfl_xor_sync(0xffffffffu, m, o));
        float vals[16];
        float sum = 0.0f;
        #pragma unroll
        for (int i = 0; i < 16; i++) {
            float e = fexp(row[lane + i * 32] - m);
            vals[i] = e;
            sum += e;
        }
        #pragma unroll
        for (int o = 16; o > 0; o >>= 1) sum += __shfl_xor_sync(0xffffffffu, sum, o);
        float inv = 1.0f / sum;
        size_t pbase = (((size_t)b * NHH + h) * SS + q0 + r) * SS;
        #pragma unroll
        for (int i = 0; i < 16; i++) {
            float p = vals[i] * inv;
            probs[pbase + lane + i * 32] = p;
            ps[r * PST + lane + i * 32] = __float2half_rn(p);
        }
    }
    // prologue: V tile 0 -> kv buf 0 (after sync so phase-1 reads are done)
    __syncthreads();
    {
        const uint32_t kvb = smem_base + SM_KV;
        #pragma unroll
        for (int e = 0; e < 2; e++) {
            int slot = tid + e * 256;
            int r = slot >> 3, q = slot & 7;
            CP_ASYNC16(kvb + r * TST * 2 + q * 16,
                       V + ((size_t)(b * SS + r)) * HH + h * HDD + q * 8);
        }
        CP_COMMIT();
    }

    // ---- phase 3: ctx = P @ V ----
    float cacc[2][2][4];
    #pragma unroll
    for (int mi = 0; mi < 2; mi++)
        #pragma unroll
        for (int ni = 0; ni < 2; ni++)
            #pragma unroll
            for (int r = 0; r < 4; r++) cacc[mi][ni][r] = 0.0f;

    const uint32_t poff = ((wm + (lane & 15)) * PST) * 2 + (lane >> 4) * 16;

    for (int kt = 0; kt < 8; kt++) {
        const int s = kt & 1;
        if (kt + 1 < 8) {
            const uint32_t kvb = smem_base + SM_KV + ((kt + 1) & 1) * 64 * TST * 2;
            #pragma unroll
            for (int e = 0; e < 2; e++) {
                int slot = tid + e * 256;
                int r = slot >> 3, q = slot & 7;
                CP_ASYNC16(kvb + r * TST * 2 + q * 16,
                           V + ((size_t)(b * SS + (kt + 1) * 64 + r)) * HH + h * HDD + q * 8);
            }
            CP_COMMIT();
            CP_WAIT(1);
        } else {
            CP_WAIT(0);
        }
        __syncthreads();

        const uint32_t kvb = smem_base + SM_KV + s * 64 * TST * 2;

        #pragma unroll
        for (int kc = 0; kc < 4; kc++) {
            // A = P fragments for k-chunk (kt*64 + kc*16)
            uint32_t af[2][4];
            #pragma unroll
            for (int mi = 0; mi < 2; mi++)
                LDSM_X4(af[mi][0], af[mi][1], af[mi][2], af[mi][3],
                        smem_base + SM_P + poff + mi * 16 * PST * 2 + (kt * 64 + kc * 16) * 2);
            // B = V^T fragments via ldmatrix.trans
            uint32_t bf[4];
            LDSM_X4T(bf[0], bf[1], bf[2], bf[3],
                     kvb + kc * 16 * TST * 2 + voff_b + wn * 2);
            #pragma unroll
            for (int mi = 0; mi < 2; mi++) {
                mma_fp16(cacc[mi][0], af[mi][0], af[mi][1], af[mi][2], af[mi][3], bf[0], bf[1]);
                mma_fp16(cacc[mi][1], af[mi][0], af[mi][1], af[mi][2], af[mi][3], bf[2], bf[3]);
            }
        }
        __syncthreads();
    }

    // epilogue: ctx fp32
    #pragma unroll
    for (int mi = 0; mi < 2; mi++) {
        int row = wm + mi * 16 + g;
        #pragma unroll
        for (int ni = 0; ni < 2; ni++) {
            int d = wn + ni * 8 + tig * 2;
            size_t base0 = ((size_t)(b * SS + q0 + row)) * HH + h * HDD + d;
            size_t base1 = ((size_t)(b * SS + q0 + row + 8)) * HH + h * HDD + d;
            *reinterpret_cast<float2*>(ctx + base0) = make_float2(cacc[mi][ni][0], cacc[mi][ni][1]);
            *reinterpret_cast<float2*>(ctx + base1) = make_float2(cacc[mi][ni][2], cacc[mi][ni][3]);
        }
    }
}

// ---------------------------------------------------------------------------
// kernel_launch
// Inputs: hidden_state, attention_mask, Wq, bq, Wk, bk, Wv, bv
// Output: ctx [16,512,768] then probs [16,12,512,512]
// ---------------------------------------------------------------------------
extern "C" void kernel_launch(void* const* d_in, const int* in_sizes, int n_in,
                              void* d_out, int out_size)
{
    const float* hidden = (const float*)d_in[0];
    const float* mask   = (const float*)d_in[1];
    const float* Wq = (const float*)d_in[2];
    const float* bq = (const float*)d_in[3];
    const float* Wk = (const float*)d_in[4];
    const float* bk = (const float*)d_in[5];
    const float* Wv = (const float*)d_in[6];
    const float* bv = (const float*)d_in[7];

    float* out   = (float*)d_out;
    float* ctx   = out;
    float* probs = out + (size_t)BB * SS * HH;

    // 0) fp32 -> fp16
    dim3 gs(256, 1, 4);
    split_kernel<<<gs, 256>>>(hidden, Wq, Wk, Wv);

    // 1) QKV projections (fp16 mma.sync + ldmatrix)
    cudaFuncSetAttribute(qkv_gemm_mma, cudaFuncAttributeMaxDynamicSharedMemorySize, GEMM_SMEM_TOTAL);
    dim3 g1(HH / 128, MROWS / 128, 3);
    qkv_gemm_mma<<<g1, 256, GEMM_SMEM_TOTAL>>>(bq, bk, bv);

    // 2) fused attention (fp16 HMMA + fp32 softmax)
    cudaFuncSetAttribute(attn_kernel, cudaFuncAttributeMaxDynamicSharedMemorySize, ATTN_SMEM_TOTAL);
    dim3 g2(SS / 64, NHH, BB);
    attn_kernel<<<g2, 256, ATTN_SMEM_TOTAL>>>(mask, ctx, probs);
}

// round 6
// speedup vs baseline: 4.7284x; 1.0771x over previous
#include <cuda_runtime.h>
#include <cuda_fp16.h>
#include <cstdint>
#include <math.h>

// Problem constants
static constexpr int BB = 16;     // batch
static constexpr int SS = 512;    // seq len
static constexpr int HH = 768;    // hidden
static constexpr int NHH = 12;    // heads
static constexpr int HDD = 64;    // head dim
static constexpr int MROWS = BB * SS;  // 8192

// Scratch (static device allocations allowed)
__device__ __half g_qkvh[3][(size_t)MROWS * HH];   // fp16 Q,K,V
__device__ __half g_xh[(size_t)MROWS * HH];        // fp16 hidden
__device__ __half g_wh[3][(size_t)HH * HH];        // fp16 weights

// ---------------------------------------------------------------------------
// helpers
// ---------------------------------------------------------------------------
__device__ __forceinline__ uint32_t smem_to_u32(const void* p) {
    uint32_t a;
    asm("{ .reg .u64 t; cvta.to.shared.u64 t, %1; cvt.u32.u64 %0, t; }" : "=r"(a) : "l"(p));
    return a;
}
#define CP_ASYNC16(dst_u32, src_ptr) \
    asm volatile("cp.async.cg.shared.global [%0], [%1], 16;" :: "r"(dst_u32), "l"(src_ptr) : "memory")
#define CP_COMMIT() asm volatile("cp.async.commit_group;" ::: "memory")
#define CP_WAIT(n)  asm volatile("cp.async.wait_group %0;" :: "n"(n) : "memory")

#define LDSM_X4(r0, r1, r2, r3, a) \
    asm volatile("ldmatrix.sync.aligned.m8n8.x4.shared.b16 {%0,%1,%2,%3}, [%4];" \
                 : "=r"(r0), "=r"(r1), "=r"(r2), "=r"(r3) : "r"(a))
#define LDSM_X4T(r0, r1, r2, r3, a) \
    asm volatile("ldmatrix.sync.aligned.m8n8.x4.trans.shared.b16 {%0,%1,%2,%3}, [%4];" \
                 : "=r"(r0), "=r"(r1), "=r"(r2), "=r"(r3) : "r"(a))

__device__ __forceinline__ void mma_fp16(float d[4],
                                         uint32_t a0, uint32_t a1, uint32_t a2, uint32_t a3,
                                         uint32_t b0, uint32_t b1) {
    asm volatile(
        "mma.sync.aligned.m16n8k16.row.col.f32.f16.f16.f32 "
        "{%0,%1,%2,%3}, {%4,%5,%6,%7}, {%8,%9}, {%0,%1,%2,%3};"
        : "+f"(d[0]), "+f"(d[1]), "+f"(d[2]), "+f"(d[3])
        : "r"(a0), "r"(a1), "r"(a2), "r"(a3), "r"(b0), "r"(b1));
}

// FMA-only exp (no MUFU): e^x = 2^(x*log2e)
__device__ __forceinline__ float fexp(float x) {
    float y = x * 1.4426950408889634f;
    y = fmaxf(y, -120.0f);
    float r = rintf(y);
    float f = y - r;
    float p = 1.5403530393381609e-4f;
    p = fmaf(p, f, 1.3333558146428443e-3f);
    p = fmaf(p, f, 9.6181291076284770e-3f);
    p = fmaf(p, f, 5.5504108664821580e-2f);
    p = fmaf(p, f, 2.4022650695910070e-1f);
    p = fmaf(p, f, 6.9314718055994531e-1f);
    p = fmaf(p, f, 1.0f);
    int i = (int)r;
    float s = __int_as_float((i + 127) << 23);
    return p * s;
}

// ---------------------------------------------------------------------------
// Kernel 0: fp32 -> fp16 conversion (vectorized).  z=0: hidden, z=1..3: W
// ---------------------------------------------------------------------------
__global__ __launch_bounds__(256) void split_kernel(
    const float* __restrict__ X,
    const float* __restrict__ Wq, const float* __restrict__ Wk, const float* __restrict__ Wv)
{
    const int z = blockIdx.z;
    const float* src = (z == 0) ? X : (z == 1) ? Wq : (z == 2) ? Wk : Wv;
    __half* dst = (z == 0) ? g_xh : g_wh[z - 1];
    size_t n4 = ((z == 0) ? (size_t)MROWS * HH : (size_t)HH * HH) >> 2;

    const float4* src4 = (const float4*)src;
    for (size_t i = (size_t)blockIdx.x * blockDim.x + threadIdx.x; i < n4;
         i += (size_t)gridDim.x * blockDim.x) {
        float4 v = src4[i];
        __half2 h0 = __floats2half2_rn(v.x, v.y);
        __half2 h1 = __floats2half2_rn(v.z, v.w);
        uint2 st;
        st.x = reinterpret_cast<uint32_t&>(h0);
        st.y = reinterpret_cast<uint32_t&>(h1);
        *reinterpret_cast<uint2*>(dst + 4 * i) = st;
    }
}

// ---------------------------------------------------------------------------
// Kernel 1: QKV projection, fp16 mma.sync + ldmatrix, 3-stage cp.async.
// (unchanged from round 5)
// ---------------------------------------------------------------------------
static constexpr int BK = 32;
static constexpr int KSTRIDE = 40;                       // fp16 per smem row (80B)
static constexpr int TILE_BYTES_G = 128 * KSTRIDE * 2;   // 10240
static constexpr int STAGE_BYTES = 2 * TILE_BYTES_G;     // A,B = 20480
static constexpr int GEMM_SMEM_TOTAL = 3 * STAGE_BYTES;  // 61440
static constexpr int NKT = HH / BK;                      // 24

__device__ __forceinline__ void load_stage_async(
    char* smem, int s,
    const __half* __restrict__ A, const __half* __restrict__ B,
    int k0, int tid)
{
    char* base = smem + s * STAGE_BYTES;
    #pragma unroll
    for (int e = 0; e < 4; e++) {
        const int tile = e >> 1;                 // 0:A 1:B
        int idx = ((e & 1) << 8) + tid;          // 0..511
        int r = idx >> 2;                        // 0..127
        int q = idx & 3;                         // 16B quad
        const __half* src = (tile == 0 ? A : B) + (size_t)r * HH + k0 + q * 8;
        uint32_t dst = smem_to_u32(base + tile * TILE_BYTES_G + (r * KSTRIDE + q * 8) * 2);
        CP_ASYNC16(dst, src);
    }
}

__global__ __launch_bounds__(256, 2) void qkv_gemm_mma(
    const float* __restrict__ bq, const float* __restrict__ bk, const float* __restrict__ bv)
{
    extern __shared__ char smem[];
    const uint32_t smem_base = smem_to_u32(smem);
    const int tid = threadIdx.x;
    const int wid = tid >> 5;
    const int lane = tid & 31;
    const int g = lane >> 2;
    const int tig = lane & 3;

    const int which = blockIdx.z;
    const int n0 = blockIdx.x * 128;
    const int m0 = blockIdx.y * 128;
    const float* bias = (which == 0) ? bq : (which == 1) ? bk : bv;
    __half* out = g_qkvh[which];

    const __half* A = g_xh + (size_t)m0 * HH;
    const __half* B = g_wh[which] + (size_t)n0 * HH;

    const int m_w = (wid & 1) * 64;
    const int n_w = (wid >> 1) * 32;

    const uint32_t aoff = ((m_w + (lane & 15)) * KSTRIDE + (lane >> 4) * 8) * 2;
    const uint32_t boff = ((n_w + ((lane >> 4) & 1) * 8 + (lane & 7)) * KSTRIDE
                           + ((lane >> 3) & 1) * 8) * 2;

    float acc[4][4][4];
    #pragma unroll
    for (int i = 0; i < 4; i++)
        #pragma unroll
        for (int j = 0; j < 4; j++)
            #pragma unroll
            for (int r = 0; r < 4; r++) acc[i][j][r] = 0.0f;

    load_stage_async(smem, 0, A, B, 0, tid);
    CP_COMMIT();
    load_stage_async(smem, 1, A, B, BK, tid);
    CP_COMMIT();

    for (int kt = 0; kt < NKT; kt++) {
        const int s = kt % 3;
        if (kt + 2 < NKT) {
            load_stage_async(smem, (kt + 2) % 3, A, B, (kt + 2) * BK, tid);
            CP_COMMIT();
        }
        if (kt < NKT - 2)      { CP_WAIT(2); }
        else if (kt == NKT - 2){ CP_WAIT(1); }
        else                   { CP_WAIT(0); }
        __syncthreads();

        const uint32_t sA = smem_base + s * STAGE_BYTES;
        const uint32_t sB = sA + TILE_BYTES_G;

        #pragma unroll
        for (int kc = 0; kc < 2; kc++) {
            uint32_t a[4][4];
            #pragma unroll
            for (int mi = 0; mi < 4; mi++)
                LDSM_X4(a[mi][0], a[mi][1], a[mi][2], a[mi][3],
                        sA + aoff + mi * 16 * KSTRIDE * 2 + kc * 32);
            uint32_t b[2][4];
            #pragma unroll
            for (int n2 = 0; n2 < 2; n2++)
                LDSM_X4(b[n2][0], b[n2][1], b[n2][2], b[n2][3],
                        sB + boff + n2 * 16 * KSTRIDE * 2 + kc * 32);
            #pragma unroll
            for (int mi = 0; mi < 4; mi++)
                #pragma unroll
                for (int ni = 0; ni < 4; ni++)
                    mma_fp16(acc[mi][ni], a[mi][0], a[mi][1], a[mi][2], a[mi][3],
                             b[ni >> 1][(ni & 1) * 2], b[ni >> 1][(ni & 1) * 2 + 1]);
        }
        __syncthreads();
    }

    #pragma unroll
    for (int mi = 0; mi < 4; mi++) {
        int row = m0 + m_w + mi * 16 + g;
        #pragma unroll
        for (int ni = 0; ni < 4; ni++) {
            int n = n0 + n_w + ni * 8 + tig * 2;
            float b0f = bias[n], b1f = bias[n + 1];
            __half2 v0 = __floats2half2_rn(acc[mi][ni][0] + b0f, acc[mi][ni][1] + b1f);
            __half2 v1 = __floats2half2_rn(acc[mi][ni][2] + b0f, acc[mi][ni][3] + b1f);
            *reinterpret_cast<__half2*>(out + (size_t)row * HH + n) = v0;
            *reinterpret_cast<__half2*>(out + (size_t)(row + 8) * HH + n) = v1;
        }
    }
}

// ---------------------------------------------------------------------------
// Kernel 2: fused attention, fp16 HMMA + ldmatrix, cp.async K/V.
// NOW 512 threads = 16 warps (4m x 4n warp layout, 16x16 warp tiles).
// ---------------------------------------------------------------------------
static constexpr int SCST = 520;   // fp32 score row stride
static constexpr int PST  = 520;   // fp16 P row stride (260 u32 ≡ 4 mod 32)
static constexpr int TST  = 72;    // fp16 tile row stride (36 u32 ≡ 4 mod 32)

static constexpr int SM_SC  = 0;                        // 64*520*4 = 133120
static constexpr int SM_P   = SM_SC + 64 * SCST * 4;    // 64*520*2 =  66560
static constexpr int SM_Q   = SM_P + 64 * PST * 2;      // 64*72*2  =   9216
static constexpr int SM_KV  = SM_Q + 64 * TST * 2;      // 2 stages =  18432
static constexpr int SM_MSK = SM_KV + 2 * 64 * TST * 2; // 512*4    =   2048
static constexpr int ATTN_SMEM_TOTAL = SM_MSK + SS * 4; // 229376

__global__ __launch_bounds__(512, 1) void attn_kernel(
    const float* __restrict__ mask,
    float* __restrict__ ctx,
    float* __restrict__ probs)
{
    extern __shared__ char smem[];
    const uint32_t smem_base = smem_to_u32(smem);
    float*  sc  = (float*)(smem + SM_SC);
    __half* ps  = (__half*)(smem + SM_P);
    float*  msk = (float*)(smem + SM_MSK);

    const int qt = blockIdx.x;   // 0..7
    const int h  = blockIdx.y;   // 0..11
    const int b  = blockIdx.z;   // 0..15
    const int tid  = threadIdx.x;
    const int wid  = tid >> 5;   // 0..15
    const int lane = tid & 31;
    const int g    = lane >> 2;
    const int tig  = lane & 3;
    const int wm   = (wid & 3) * 16;    // warp m offset within 64
    const int wn   = (wid >> 2) * 16;   // warp n offset within 64
    const int q0 = qt * 64;
    const float scale = 0.125f;

    const __half* Q = g_qkvh[0];
    const __half* K = g_qkvh[1];
    const __half* V = g_qkvh[2];

    // mask additive term (512 threads cover 512)
    msk[tid] = (1.0f - mask[(size_t)b * SS + tid]) * -10000.0f;

    // load Q tile [64 x 64] fp16 into smem (one shot: 512 slots)
    {
        int r = tid >> 3, q = tid & 7;
        uint4 v = *reinterpret_cast<const uint4*>(
            Q + ((size_t)(b * SS + q0 + r)) * HH + h * HDD + q * 8);
        *reinterpret_cast<uint4*>((__half*)(smem + SM_Q) + r * TST + q * 8) = v;
    }
    // prologue: K tile 0 -> kv buf 0
    {
        const uint32_t kvb = smem_base + SM_KV;
        int r = tid >> 3, q = tid & 7;
        CP_ASYNC16(kvb + r * TST * 2 + q * 16,
                   K + ((size_t)(b * SS + r)) * HH + h * HDD + q * 8);
        CP_COMMIT();
    }
    __syncthreads();

    // Q fragments resident in registers: qf[kc][4]  (one 16-row m-frag)
    uint32_t qf[4][4];
    {
        const uint32_t qbase = smem_base + SM_Q
            + ((wm + (lane & 15)) * TST) * 2 + (lane >> 4) * 16;
        #pragma unroll
        for (int kc = 0; kc < 4; kc++)
            LDSM_X4(qf[kc][0], qf[kc][1], qf[kc][2], qf[kc][3], qbase + kc * 32);
    }

    // per-lane ldmatrix offsets into a kv buffer
    const uint32_t koff_b = (((lane >> 4) & 1) * 8 + (lane & 7)) * TST * 2
                            + ((lane >> 3) & 1) * 16;          // K (n16k16)
    const uint32_t voff_b = ((lane & 7) + ((lane >> 3) & 1) * 8) * TST * 2
                            + (((lane >> 4) & 1) * 8) * 2;     // V (trans)

    // ---- phase 1: scores = Q K^T ----
    for (int kt = 0; kt < 8; kt++) {
        const int s = kt & 1;
        if (kt + 1 < 8) {
            const uint32_t kvb = smem_base + SM_KV + ((kt + 1) & 1) * 64 * TST * 2;
            int r = tid >> 3, q = tid & 7;
            CP_ASYNC16(kvb + r * TST * 2 + q * 16,
                       K + ((size_t)(b * SS + (kt + 1) * 64 + r)) * HH + h * HDD + q * 8);
            CP_COMMIT();
            CP_WAIT(1);
        } else {
            CP_WAIT(0);
        }
        __syncthreads();

        const uint32_t kvb = smem_base + SM_KV + s * 64 * TST * 2;
        float acc[2][4];
        #pragma unroll
        for (int ni = 0; ni < 2; ni++)
            #pragma unroll
            for (int r = 0; r < 4; r++) acc[ni][r] = 0.0f;

        #pragma unroll
        for (int kc = 0; kc < 4; kc++) {
            uint32_t bf[4];
            LDSM_X4(bf[0], bf[1], bf[2], bf[3], kvb + wn * TST * 2 + koff_b + kc * 32);
            mma_fp16(acc[0], qf[kc][0], qf[kc][1], qf[kc][2], qf[kc][3], bf[0], bf[1]);
            mma_fp16(acc[1], qf[kc][0], qf[kc][1], qf[kc][2], qf[kc][3], bf[2], bf[3]);
        }

        {
            int row = wm + g;
            #pragma unroll
            for (int ni = 0; ni < 2; ni++) {
                int col = kt * 64 + wn + ni * 8 + tig * 2;
                sc[row * SCST + col]           = acc[ni][0] * scale + msk[col];
                sc[row * SCST + col + 1]       = acc[ni][1] * scale + msk[col + 1];
                sc[(row + 8) * SCST + col]     = acc[ni][2] * scale + msk[col];
                sc[(row + 8) * SCST + col + 1] = acc[ni][3] * scale + msk[col + 1];
            }
        }
        __syncthreads();
    }

    // ---- phase 2: softmax (4 rows per warp), write probs fp32 + P fp16 ----
    for (int rr = 0; rr < 4; rr++) {
        int r = wid * 4 + rr;
        float* row = sc + r * SCST;
        float m = -1e30f;
        #pragma unroll
        for (int i = 0; i < 16; i++) m = fmaxf(m, row[lane + i * 32]);
        #pragma unroll
        for (int o = 16; o > 0; o >>= 1) m = fmaxf(m, __shfl_xor_sync(0xffffffffu, m, o));
        float vals[16];
        float sum = 0.0f;
        #pragma unroll
        for (int i = 0; i < 16; i++) {
            float e = fexp(row[lane + i * 32] - m);
            vals[i] = e;
            sum += e;
        }
        #pragma unroll
        for (int o = 16; o > 0; o >>= 1) sum += __shfl_xor_sync(0xffffffffu, sum, o);
        float inv = 1.0f / sum;
        size_t pbase = (((size_t)b * NHH + h) * SS + q0 + r) * SS;
        #pragma unroll
        for (int i = 0; i < 16; i++) {
            float p = vals[i] * inv;
            probs[pbase + lane + i * 32] = p;
            ps[r * PST + lane + i * 32] = __float2half_rn(p);
        }
    }
    __syncthreads();
    // prologue: V tile 0 -> kv buf 0
    {
        const uint32_t kvb = smem_base + SM_KV;
        int r = tid >> 3, q = tid & 7;
        CP_ASYNC16(kvb + r * TST * 2 + q * 16,
                   V + ((size_t)(b * SS + r)) * HH + h * HDD + q * 8);
        CP_COMMIT();
    }

    // ---- phase 3: ctx = P @ V ----
    float cacc[2][4];
    #pragma unroll
    for (int ni = 0; ni < 2; ni++)
        #pragma unroll
        for (int r = 0; r < 4; r++) cacc[ni][r] = 0.0f;

    const uint32_t poff = ((wm + (lane & 15)) * PST) * 2 + (lane >> 4) * 16;

    for (int kt = 0; kt < 8; kt++) {
        const int s = kt & 1;
        if (kt + 1 < 8) {
            const uint32_t kvb = smem_base + SM_KV + ((kt + 1) & 1) * 64 * TST * 2;
            int r = tid >> 3, q = tid & 7;
            CP_ASYNC16(kvb + r * TST * 2 + q * 16,
                       V + ((size_t)(b * SS + (kt + 1) * 64 + r)) * HH + h * HDD + q * 8);
            CP_COMMIT();
            CP_WAIT(1);
        } else {
            CP_WAIT(0);
        }
        __syncthreads();

        const uint32_t kvb = smem_base + SM_KV + s * 64 * TST * 2;

        #pragma unroll
        for (int kc = 0; kc < 4; kc++) {
            uint32_t af[4];
            LDSM_X4(af[0], af[1], af[2], af[3],
                    smem_base + SM_P + poff + (kt * 64 + kc * 16) * 2);
            uint32_t bf[4];
            LDSM_X4T(bf[0], bf[1], bf[2], bf[3],
                     kvb + kc * 16 * TST * 2 + voff_b + wn * 2);
            mma_fp16(cacc[0], af[0], af[1], af[2], af[3], bf[0], bf[1]);
            mma_fp16(cacc[1], af[0], af[1], af[2], af[3], bf[2], bf[3]);
        }
        __syncthreads();
    }

    // epilogue: ctx fp32
    {
        int row = wm + g;
        #pragma unroll
        for (int ni = 0; ni < 2; ni++) {
            int d = wn + ni * 8 + tig * 2;
            size_t base0 = ((size_t)(b * SS + q0 + row)) * HH + h * HDD + d;
            size_t base1 = ((size_t)(b * SS + q0 + row + 8)) * HH + h * HDD + d;
            *reinterpret_cast<float2*>(ctx + base0) = make_float2(cacc[0 + 0][0], cacc[ni][1]);
            // (corrected below — placeholder removed)
            *reinterpret_cast<float2*>(ctx + base0) = make_float2(cacc[ni][0], cacc[ni][1]);
            *reinterpret_cast<float2*>(ctx + base1) = make_float2(cacc[ni][2], cacc[ni][3]);
        }
    }
}

// ---------------------------------------------------------------------------
// kernel_launch
// ---------------------------------------------------------------------------
extern "C" void kernel_launch(void* const* d_in, const int* in_sizes, int n_in,
                              void* d_out, int out_size)
{
    const float* hidden = (const float*)d_in[0];
    const float* mask   = (const float*)d_in[1];
    const float* Wq = (const float*)d_in[2];
    const float* bq = (const float*)d_in[3];
    const float* Wk = (const float*)d_in[4];
    const float* bk = (const float*)d_in[5];
    const float* Wv = (const float*)d_in[6];
    const float* bv = (const float*)d_in[7];

    float* out   = (float*)d_out;
    float* ctx   = out;
    float* probs = out + (size_t)BB * SS * HH;

    // 0) fp32 -> fp16
    dim3 gs(256, 1, 4);
    split_kernel<<<gs, 256>>>(hidden, Wq, Wk, Wv);

    // 1) QKV projections (fp16 mma.sync + ldmatrix)
    cudaFuncSetAttribute(qkv_gemm_mma, cudaFuncAttributeMaxDynamicSharedMemorySize, GEMM_SMEM_TOTAL);
    dim3 g1(HH / 128, MROWS / 128, 3);
    qkv_gemm_mma<<<g1, 256, GEMM_SMEM_TOTAL>>>(bq, bk, bv);

    // 2) fused attention (fp16 HMMA + fp32 softmax, 512 threads)
    cudaFuncSetAttribute(attn_kernel, cudaFuncAttributeMaxDynamicSharedMemorySize, ATTN_SMEM_TOTAL);
    dim3 g2(SS / 64, NHH, BB);
    attn_kernel<<<g2, 512, ATTN_SMEM_TOTAL>>>(mask, ctx, probs);
}

// round 7
// speedup vs baseline: 5.1463x; 1.0884x over previous
#include <cuda_runtime.h>
#include <cuda_fp16.h>
#include <cstdint>
#include <math.h>

// Problem constants
static constexpr int BB = 16;     // batch
static constexpr int SS = 512;    // seq len
static constexpr int HH = 768;    // hidden
static constexpr int NHH = 12;    // heads
static constexpr int HDD = 64;    // head dim
static constexpr int MROWS = BB * SS;  // 8192

// Scratch (static device allocations allowed)
__device__ __half g_qkvh[3][(size_t)MROWS * HH];   // fp16 Q,K,V
__device__ __half g_xh[(size_t)MROWS * HH];        // fp16 hidden
__device__ __half g_wh[3][(size_t)HH * HH];        // fp16 weights

// ---------------------------------------------------------------------------
// helpers
// ---------------------------------------------------------------------------
__device__ __forceinline__ uint32_t smem_to_u32(const void* p) {
    uint32_t a;
    asm("{ .reg .u64 t; cvta.to.shared.u64 t, %1; cvt.u32.u64 %0, t; }" : "=r"(a) : "l"(p));
    return a;
}
#define CP_ASYNC16(dst_u32, src_ptr) \
    asm volatile("cp.async.cg.shared.global [%0], [%1], 16;" :: "r"(dst_u32), "l"(src_ptr) : "memory")
#define CP_COMMIT() asm volatile("cp.async.commit_group;" ::: "memory")
#define CP_WAIT(n)  asm volatile("cp.async.wait_group %0;" :: "n"(n) : "memory")

#define LDSM_X4(r0, r1, r2, r3, a) \
    asm volatile("ldmatrix.sync.aligned.m8n8.x4.shared.b16 {%0,%1,%2,%3}, [%4];" \
                 : "=r"(r0), "=r"(r1), "=r"(r2), "=r"(r3) : "r"(a))
#define LDSM_X4T(r0, r1, r2, r3, a) \
    asm volatile("ldmatrix.sync.aligned.m8n8.x4.trans.shared.b16 {%0,%1,%2,%3}, [%4];" \
                 : "=r"(r0), "=r"(r1), "=r"(r2), "=r"(r3) : "r"(a))

__device__ __forceinline__ void mma_fp16(float d[4],
                                         uint32_t a0, uint32_t a1, uint32_t a2, uint32_t a3,
                                         uint32_t b0, uint32_t b1) {
    asm volatile(
        "mma.sync.aligned.m16n8k16.row.col.f32.f16.f16.f32 "
        "{%0,%1,%2,%3}, {%4,%5,%6,%7}, {%8,%9}, {%0,%1,%2,%3};"
        : "+f"(d[0]), "+f"(d[1]), "+f"(d[2]), "+f"(d[3])
        : "r"(a0), "r"(a1), "r"(a2), "r"(a3), "r"(b0), "r"(b1));
}

// FMA-only exp (no MUFU): e^x = 2^(x*log2e)
__device__ __forceinline__ float fexp(float x) {
    float y = x * 1.4426950408889634f;
    y = fmaxf(y, -120.0f);
    float r = rintf(y);
    float f = y - r;
    float p = 1.5403530393381609e-4f;
    p = fmaf(p, f, 1.3333558146428443e-3f);
    p = fmaf(p, f, 9.6181291076284770e-3f);
    p = fmaf(p, f, 5.5504108664821580e-2f);
    p = fmaf(p, f, 2.4022650695910070e-1f);
    p = fmaf(p, f, 6.9314718055994531e-1f);
    p = fmaf(p, f, 1.0f);
    int i = (int)r;
    float s = __int_as_float((i + 127) << 23);
    return p * s;
}

// ---------------------------------------------------------------------------
// Kernel 0: fp32 -> fp16 conversion (vectorized).  z=0: hidden, z=1..3: W
// ---------------------------------------------------------------------------
__global__ __launch_bounds__(256) void split_kernel(
    const float* __restrict__ X,
    const float* __restrict__ Wq, const float* __restrict__ Wk, const float* __restrict__ Wv)
{
    const int z = blockIdx.z;
    const float* src = (z == 0) ? X : (z == 1) ? Wq : (z == 2) ? Wk : Wv;
    __half* dst = (z == 0) ? g_xh : g_wh[z - 1];
    size_t n4 = ((z == 0) ? (size_t)MROWS * HH : (size_t)HH * HH) >> 2;

    const float4* src4 = (const float4*)src;
    for (size_t i = (size_t)blockIdx.x * blockDim.x + threadIdx.x; i < n4;
         i += (size_t)gridDim.x * blockDim.x) {
        float4 v = src4[i];
        __half2 h0 = __floats2half2_rn(v.x, v.y);
        __half2 h1 = __floats2half2_rn(v.z, v.w);
        uint2 st;
        st.x = reinterpret_cast<uint32_t&>(h0);
        st.y = reinterpret_cast<uint32_t&>(h1);
        *reinterpret_cast<uint2*>(dst + 4 * i) = st;
    }
}

// ---------------------------------------------------------------------------
// Kernel 1: QKV projection, fp16 mma.sync + ldmatrix, 3-stage cp.async.
// (unchanged)
// ---------------------------------------------------------------------------
static constexpr int BK = 32;
static constexpr int KSTRIDE = 40;
static constexpr int TILE_BYTES_G = 128 * KSTRIDE * 2;
static constexpr int STAGE_BYTES = 2 * TILE_BYTES_G;
static constexpr int GEMM_SMEM_TOTAL = 3 * STAGE_BYTES;
static constexpr int NKT = HH / BK;

__device__ __forceinline__ void load_stage_async(
    char* smem, int s,
    const __half* __restrict__ A, const __half* __restrict__ B,
    int k0, int tid)
{
    char* base = smem + s * STAGE_BYTES;
    #pragma unroll
    for (int e = 0; e < 4; e++) {
        const int tile = e >> 1;
        int idx = ((e & 1) << 8) + tid;
        int r = idx >> 2;
        int q = idx & 3;
        const __half* src = (tile == 0 ? A : B) + (size_t)r * HH + k0 + q * 8;
        uint32_t dst = smem_to_u32(base + tile * TILE_BYTES_G + (r * KSTRIDE + q * 8) * 2);
        CP_ASYNC16(dst, src);
    }
}

__global__ __launch_bounds__(256, 2) void qkv_gemm_mma(
    const float* __restrict__ bq, const float* __restrict__ bk, const float* __restrict__ bv)
{
    extern __shared__ char smem[];
    const uint32_t smem_base = smem_to_u32(smem);
    const int tid = threadIdx.x;
    const int wid = tid >> 5;
    const int lane = tid & 31;
    const int g = lane >> 2;
    const int tig = lane & 3;

    const int which = blockIdx.z;
    const int n0 = blockIdx.x * 128;
    const int m0 = blockIdx.y * 128;
    const float* bias = (which == 0) ? bq : (which == 1) ? bk : bv;
    __half* out = g_qkvh[which];

    const __half* A = g_xh + (size_t)m0 * HH;
    const __half* B = g_wh[which] + (size_t)n0 * HH;

    const int m_w = (wid & 1) * 64;
    const int n_w = (wid >> 1) * 32;

    const uint32_t aoff = ((m_w + (lane & 15)) * KSTRIDE + (lane >> 4) * 8) * 2;
    const uint32_t boff = ((n_w + ((lane >> 4) & 1) * 8 + (lane & 7)) * KSTRIDE
                           + ((lane >> 3) & 1) * 8) * 2;

    float acc[4][4][4];
    #pragma unroll
    for (int i = 0; i < 4; i++)
        #pragma unroll
        for (int j = 0; j < 4; j++)
            #pragma unroll
            for (int r = 0; r < 4; r++) acc[i][j][r] = 0.0f;

    load_stage_async(smem, 0, A, B, 0, tid);
    CP_COMMIT();
    load_stage_async(smem, 1, A, B, BK, tid);
    CP_COMMIT();

    for (int kt = 0; kt < NKT; kt++) {
        const int s = kt % 3;
        if (kt + 2 < NKT) {
            load_stage_async(smem, (kt + 2) % 3, A, B, (kt + 2) * BK, tid);
            CP_COMMIT();
        }
        if (kt < NKT - 2)      { CP_WAIT(2); }
        else if (kt == NKT - 2){ CP_WAIT(1); }
        else                   { CP_WAIT(0); }
        __syncthreads();

        const uint32_t sA = smem_base + s * STAGE_BYTES;
        const uint32_t sB = sA + TILE_BYTES_G;

        #pragma unroll
        for (int kc = 0; kc < 2; kc++) {
            uint32_t a[4][4];
            #pragma unroll
            for (int mi = 0; mi < 4; mi++)
                LDSM_X4(a[mi][0], a[mi][1], a[mi][2], a[mi][3],
                        sA + aoff + mi * 16 * KSTRIDE * 2 + kc * 32);
            uint32_t b[2][4];
            #pragma unroll
            for (int n2 = 0; n2 < 2; n2++)
                LDSM_X4(b[n2][0], b[n2][1], b[n2][2], b[n2][3],
                        sB + boff + n2 * 16 * KSTRIDE * 2 + kc * 32);
            #pragma unroll
            for (int mi = 0; mi < 4; mi++)
                #pragma unroll
                for (int ni = 0; ni < 4; ni++)
                    mma_fp16(acc[mi][ni], a[mi][0], a[mi][1], a[mi][2], a[mi][3],
                             b[ni >> 1][(ni & 1) * 2], b[ni >> 1][(ni & 1) * 2 + 1]);
        }
        __syncthreads();
    }

    #pragma unroll
    for (int mi = 0; mi < 4; mi++) {
        int row = m0 + m_w + mi * 16 + g;
        #pragma unroll
        for (int ni = 0; ni < 4; ni++) {
            int n = n0 + n_w + ni * 8 + tig * 2;
            float b0f = bias[n], b1f = bias[n + 1];
            __half2 v0 = __floats2half2_rn(acc[mi][ni][0] + b0f, acc[mi][ni][1] + b1f);
            __half2 v1 = __floats2half2_rn(acc[mi][ni][2] + b0f, acc[mi][ni][3] + b1f);
            *reinterpret_cast<__half2*>(out + (size_t)row * HH + n) = v0;
            *reinterpret_cast<__half2*>(out + (size_t)(row + 8) * HH + n) = v1;
        }
    }
}

// ---------------------------------------------------------------------------
// Kernel 2: register-resident flash-style attention.
// 512 threads = 16 warps: mw = wid&3 (16-row m-strip), nw = wid>>2 (16-col group).
// Each warp keeps its S slice (16 rows x 128 cols, spread over 8 K-tiles)
// entirely in registers; softmax via fragment reductions + 4-warp smem combine;
// P converted in-register to MMA A-fragments; ctx partials tree-summed in smem.
// ---------------------------------------------------------------------------
static constexpr int TST = 72;     // fp16 tile row stride

static constexpr int SM_Q    = 0;                          // 64*72*2  = 9216
static constexpr int SM_KV   = SM_Q + 64 * TST * 2;        // 2 stages = 18432
static constexpr int SM_MSK  = SM_KV + 2 * 64 * TST * 2;   // 512*4    = 2048
static constexpr int SM_WMAX = SM_MSK + SS * 4;            // 4*64*4   = 1024
static constexpr int SM_WSUM = SM_WMAX + 4 * 64 * 4;       // 1024
static constexpr int SM_CTX  = SM_WSUM + 4 * 64 * 4;       // 4*64*68*4 = 69632
static constexpr int CTXST = 68;
static constexpr int ATTN_SMEM_TOTAL = SM_CTX + 4 * 64 * CTXST * 4;  // 101376

__global__ __launch_bounds__(512, 1) void attn_kernel(
    const float* __restrict__ mask,
    float* __restrict__ ctx,
    float* __restrict__ probs)
{
    extern __shared__ char smem[];
    const uint32_t smem_base = smem_to_u32(smem);
    float* msk   = (float*)(smem + SM_MSK);
    float* wmax  = (float*)(smem + SM_WMAX);
    float* wsum  = (float*)(smem + SM_WSUM);
    float* ctxb  = (float*)(smem + SM_CTX);

    const int qt = blockIdx.x;   // 0..7
    const int h  = blockIdx.y;   // 0..11
    const int b  = blockIdx.z;   // 0..15
    const int tid  = threadIdx.x;
    const int wid  = tid >> 5;   // 0..15
    const int lane = tid & 31;
    const int g    = lane >> 2;
    const int tig  = lane & 3;
    const int mw   = (wid & 3);        // m-strip index (16 rows each)
    const int nw   = (wid >> 2);       // col-group index (16 cols per K-tile)
    const int q0 = qt * 64;
    const float scale = 0.125f;

    const __half* Q = g_qkvh[0];
    const __half* K = g_qkvh[1];
    const __half* V = g_qkvh[2];

    // mask additive term
    msk[tid] = (1.0f - mask[(size_t)b * SS + tid]) * -10000.0f;

    // load Q tile [64 x 64]
    {
        int r = tid >> 3, q = tid & 7;
        uint4 v = *reinterpret_cast<const uint4*>(
            Q + ((size_t)(b * SS + q0 + r)) * HH + h * HDD + q * 8);
        *reinterpret_cast<uint4*>((__half*)(smem + SM_Q) + r * TST + q * 8) = v;
    }
    // prologue: K tile 0 -> kv buf 0
    {
        int r = tid >> 3, q = tid & 7;
        CP_ASYNC16(smem_base + SM_KV + r * TST * 2 + q * 16,
                   K + ((size_t)(b * SS + r)) * HH + h * HDD + q * 8);
        CP_COMMIT();
    }
    __syncthreads();

    // Q fragments resident in registers
    uint32_t qf[4][4];
    {
        const uint32_t qbase = smem_base + SM_Q
            + ((mw * 16 + (lane & 15)) * TST) * 2 + (lane >> 4) * 16;
        #pragma unroll
        for (int kc = 0; kc < 4; kc++)
            LDSM_X4(qf[kc][0], qf[kc][1], qf[kc][2], qf[kc][3], qbase + kc * 32);
    }

    // per-lane ldmatrix offsets
    const uint32_t koff = (nw * 16 + ((lane >> 4) & 1) * 8 + (lane & 7)) * TST * 2
                          + ((lane >> 3) & 1) * 16;   // K (n16k16), n-rows at nw*16
    const uint32_t voff = (nw * 16 + (lane & 7) + ((lane >> 3) & 1) * 8) * TST * 2
                          + ((lane >> 4) & 1) * 16;   // V (trans), k-rows at nw*16

    // ---- phase 1: S = Q K^T * scale + mask, held in registers ----
    float sreg[8][2][4];
    for (int kt = 0; kt < 8; kt++) {
        const int s = kt & 1;
        if (kt + 1 < 8) {
            int r = tid >> 3, q = tid & 7;
            CP_ASYNC16(smem_base + SM_KV + ((kt + 1) & 1) * 64 * TST * 2 + r * TST * 2 + q * 16,
                       K + ((size_t)(b * SS + (kt + 1) * 64 + r)) * HH + h * HDD + q * 8);
            CP_COMMIT();
            CP_WAIT(1);
        } else {
            CP_WAIT(0);
        }
        __syncthreads();

        const uint32_t kvb = smem_base + SM_KV + s * 64 * TST * 2;
        float acc[2][4];
        #pragma unroll
        for (int ni = 0; ni < 2; ni++)
            #pragma unroll
            for (int r = 0; r < 4; r++) acc[ni][r] = 0.0f;

        #pragma unroll
        for (int kc = 0; kc < 4; kc++) {
            uint32_t bf[4];
            LDSM_X4(bf[0], bf[1], bf[2], bf[3], kvb + koff + kc * 32);
            mma_fp16(acc[0], qf[kc][0], qf[kc][1], qf[kc][2], qf[kc][3], bf[0], bf[1]);
            mma_fp16(acc[1], qf[kc][0], qf[kc][1], qf[kc][2], qf[kc][3], bf[2], bf[3]);
        }
        #pragma unroll
        for (int ni = 0; ni < 2; ni++) {
            int col = kt * 64 + nw * 16 + ni * 8 + tig * 2;
            sreg[kt][ni][0] = acc[ni][0] * scale + msk[col];
            sreg[kt][ni][1] = acc[ni][1] * scale + msk[col + 1];
            sreg[kt][ni][2] = acc[ni][2] * scale + msk[col];
            sreg[kt][ni][3] = acc[ni][3] * scale + msk[col + 1];
        }
        __syncthreads();
    }

    // prologue: V tile 0 -> kv buf 0 (overlaps with softmax)
    {
        int r = tid >> 3, q = tid & 7;
        CP_ASYNC16(smem_base + SM_KV + r * TST * 2 + q * 16,
                   V + ((size_t)(b * SS + r)) * HH + h * HDD + q * 8);
        CP_COMMIT();
    }

    // ---- phase 2: softmax over register fragments ----
    const int r0 = mw * 16 + g;        // row within 64
    const int r1 = r0 + 8;

    float m0 = -1e30f, m1 = -1e30f;
    #pragma unroll
    for (int kt = 0; kt < 8; kt++)
        #pragma unroll
        for (int ni = 0; ni < 2; ni++) {
            m0 = fmaxf(m0, fmaxf(sreg[kt][ni][0], sreg[kt][ni][1]));
            m1 = fmaxf(m1, fmaxf(sreg[kt][ni][2], sreg[kt][ni][3]));
        }
    #pragma unroll
    for (int o = 1; o <= 2; o <<= 1) {
        m0 = fmaxf(m0, __shfl_xor_sync(0xffffffffu, m0, o));
        m1 = fmaxf(m1, __shfl_xor_sync(0xffffffffu, m1, o));
    }
    if (tig == 0) {
        wmax[nw * 64 + r0] = m0;
        wmax[nw * 64 + r1] = m1;
    }
    __syncthreads();
    float rm0 = fmaxf(fmaxf(wmax[r0], wmax[64 + r0]), fmaxf(wmax[128 + r0], wmax[192 + r0]));
    float rm1 = fmaxf(fmaxf(wmax[r1], wmax[64 + r1]), fmaxf(wmax[128 + r1], wmax[192 + r1]));

    float s0 = 0.0f, s1 = 0.0f;
    #pragma unroll
    for (int kt = 0; kt < 8; kt++)
        #pragma unroll
        for (int ni = 0; ni < 2; ni++) {
            float e0 = fexp(sreg[kt][ni][0] - rm0);
            float e1 = fexp(sreg[kt][ni][1] - rm0);
            float e2 = fexp(sreg[kt][ni][2] - rm1);
            float e3 = fexp(sreg[kt][ni][3] - rm1);
            sreg[kt][ni][0] = e0; sreg[kt][ni][1] = e1;
            sreg[kt][ni][2] = e2; sreg[kt][ni][3] = e3;
            s0 += e0 + e1;
            s1 += e2 + e3;
        }
    #pragma unroll
    for (int o = 1; o <= 2; o <<= 1) {
        s0 += __shfl_xor_sync(0xffffffffu, s0, o);
        s1 += __shfl_xor_sync(0xffffffffu, s1, o);
    }
    if (tig == 0) {
        wsum[nw * 64 + r0] = s0;
        wsum[nw * 64 + r1] = s1;
    }
    __syncthreads();
    float inv0 = 1.0f / (wsum[r0] + wsum[64 + r0] + wsum[128 + r0] + wsum[192 + r0]);
    float inv1 = 1.0f / (wsum[r1] + wsum[64 + r1] + wsum[128 + r1] + wsum[192 + r1]);

    // probs (streaming stores) + in-register P A-fragments
    uint32_t paf[8][4];
    {
        const size_t pb0 = (((size_t)b * NHH + h) * SS + q0 + r0) * SS;
        const size_t pb1 = (((size_t)b * NHH + h) * SS + q0 + r1) * SS;
        #pragma unroll
        for (int kt = 0; kt < 8; kt++)
            #pragma unroll
            for (int ni = 0; ni < 2; ni++) {
                int col = kt * 64 + nw * 16 + ni * 8 + tig * 2;
                float p0 = sreg[kt][ni][0] * inv0;
                float p1 = sreg[kt][ni][1] * inv0;
                float p2 = sreg[kt][ni][2] * inv1;
                float p3 = sreg[kt][ni][3] * inv1;
                __stcs(reinterpret_cast<float2*>(probs + pb0 + col), make_float2(p0, p1));
                __stcs(reinterpret_cast<float2*>(probs + pb1 + col), make_float2(p2, p3));
                __half2 h01 = __floats2half2_rn(p0, p1);
                __half2 h23 = __floats2half2_rn(p2, p3);
                paf[kt][ni * 2]     = reinterpret_cast<uint32_t&>(h01);
                paf[kt][ni * 2 + 1] = reinterpret_cast<uint32_t&>(h23);
            }
    }

    // ---- phase 3: ctx partial = P(16x128) @ V(128x64) per warp ----
    float cacc[8][4];
    #pragma unroll
    for (int nd = 0; nd < 8; nd++)
        #pragma unroll
        for (int r = 0; r < 4; r++) cacc[nd][r] = 0.0f;

    for (int kt = 0; kt < 8; kt++) {
        const int s = kt & 1;
        if (kt + 1 < 8) {
            int r = tid >> 3, q = tid & 7;
            CP_ASYNC16(smem_base + SM_KV + ((kt + 1) & 1) * 64 * TST * 2 + r * TST * 2 + q * 16,
                       V + ((size_t)(b * SS + (kt + 1) * 64 + r)) * HH + h * HDD + q * 8);
            CP_COMMIT();
            CP_WAIT(1);
        } else {
            CP_WAIT(0);
        }
        __syncthreads();

        const uint32_t kvb = smem_base + SM_KV + s * 64 * TST * 2;
        #pragma unroll
        for (int dd = 0; dd < 4; dd++) {
            uint32_t bf[4];
            LDSM_X4T(bf[0], bf[1], bf[2], bf[3], kvb + voff + dd * 32);
            mma_fp16(cacc[dd * 2],     paf[kt][0], paf[kt][1], paf[kt][2], paf[kt][3], bf[0], bf[1]);
            mma_fp16(cacc[dd * 2 + 1], paf[kt][0], paf[kt][1], paf[kt][2], paf[kt][3], bf[2], bf[3]);
        }
        __syncthreads();
    }

    // write ctx partials to smem
    #pragma unroll
    for (int nd = 0; nd < 8; nd++) {
        int d = nd * 8 + tig * 2;
        *reinterpret_cast<float2*>(ctxb + (nw * 64 + r0) * CTXST + d) =
            make_float2(cacc[nd][0], cacc[nd][1]);
        *reinterpret_cast<float2*>(ctxb + (nw * 64 + r1) * CTXST + d) =
            make_float2(cacc[nd][2], cacc[nd][3]);
    }
    __syncthreads();

    // 4-way tree sum + global write (each thread: one row, 8 consecutive d)
    {
        int row = tid >> 3;
        int d0  = (tid & 7) * 8;
        #pragma unroll
        for (int half = 0; half < 2; half++) {
            int d = d0 + half * 4;
            float4 v0 = *reinterpret_cast<float4*>(ctxb + (0 * 64 + row) * CTXST + d);
            float4 v1 = *reinterpret_cast<float4*>(ctxb + (1 * 64 + row) * CTXST + d);
            float4 v2 = *reinterpret_cast<float4*>(ctxb + (2 * 64 + row) * CTXST + d);
            float4 v3 = *reinterpret_cast<float4*>(ctxb + (3 * 64 + row) * CTXST + d);
            float4 o;
            o.x = v0.x + v1.x + v2.x + v3.x;
            o.y = v0.y + v1.y + v2.y + v3.y;
            o.z = v0.z + v1.z + v2.z + v3.z;
            o.w = v0.w + v1.w + v2.w + v3.w;
            *reinterpret_cast<float4*>(
                ctx + ((size_t)(b * SS + q0 + row)) * HH + h * HDD + d) = o;
        }
    }
}

// ---------------------------------------------------------------------------
// kernel_launch
// ---------------------------------------------------------------------------
extern "C" void kernel_launch(void* const* d_in, const int* in_sizes, int n_in,
                              void* d_out, int out_size)
{
    const float* hidden = (const float*)d_in[0];
    const float* mask   = (const float*)d_in[1];
    const float* Wq = (const float*)d_in[2];
    const float* bq = (const float*)d_in[3];
    const float* Wk = (const float*)d_in[4];
    const float* bk = (const float*)d_in[5];
    const float* Wv = (const float*)d_in[6];
    const float* bv = (const float*)d_in[7];

    float* out   = (float*)d_out;
    float* ctx   = out;
    float* probs = out + (size_t)BB * SS * HH;

    // 0) fp32 -> fp16
    dim3 gs(256, 1, 4);
    split_kernel<<<gs, 256>>>(hidden, Wq, Wk, Wv);

    // 1) QKV projections (fp16 mma.sync + ldmatrix)
    cudaFuncSetAttribute(qkv_gemm_mma, cudaFuncAttributeMaxDynamicSharedMemorySize, GEMM_SMEM_TOTAL);
    dim3 g1(HH / 128, MROWS / 128, 3);
    qkv_gemm_mma<<<g1, 256, GEMM_SMEM_TOTAL>>>(bq, bk, bv);

    // 2) fused attention (register-resident flash style)
    cudaFuncSetAttribute(attn_kernel, cudaFuncAttributeMaxDynamicSharedMemorySize, ATTN_SMEM_TOTAL);
    dim3 g2(SS / 64, NHH, BB);
    attn_kernel<<<g2, 512, ATTN_SMEM_TOTAL>>>(mask, ctx, probs);
}

// round 8
// speedup vs baseline: 5.5284x; 1.0743x over previous
#include <cuda_runtime.h>
#include <cuda_fp16.h>
#include <cstdint>
#include <math.h>

// Problem constants
static constexpr int BB = 16;     // batch
static constexpr int SS = 512;    // seq len
static constexpr int HH = 768;    // hidden
static constexpr int NHH = 12;    // heads
static constexpr int HDD = 64;    // head dim
static constexpr int MROWS = BB * SS;  // 8192

// Scratch (static device allocations allowed)
__device__ __half g_qkvh[3][(size_t)MROWS * HH];   // fp16 Q,K,V
__device__ __half g_xh[(size_t)MROWS * HH];        // fp16 hidden
__device__ __half g_wh[3][(size_t)HH * HH];        // fp16 weights

// ---------------------------------------------------------------------------
// helpers
// ---------------------------------------------------------------------------
__device__ __forceinline__ uint32_t smem_to_u32(const void* p) {
    uint32_t a;
    asm("{ .reg .u64 t; cvta.to.shared.u64 t, %1; cvt.u32.u64 %0, t; }" : "=r"(a) : "l"(p));
    return a;
}
#define CP_ASYNC16(dst_u32, src_ptr) \
    asm volatile("cp.async.cg.shared.global [%0], [%1], 16;" :: "r"(dst_u32), "l"(src_ptr) : "memory")
#define CP_COMMIT() asm volatile("cp.async.commit_group;" ::: "memory")
#define CP_WAIT(n)  asm volatile("cp.async.wait_group %0;" :: "n"(n) : "memory")

#define LDSM_X4(r0, r1, r2, r3, a) \
    asm volatile("ldmatrix.sync.aligned.m8n8.x4.shared.b16 {%0,%1,%2,%3}, [%4];" \
                 : "=r"(r0), "=r"(r1), "=r"(r2), "=r"(r3) : "r"(a))
#define LDSM_X4T(r0, r1, r2, r3, a) \
    asm volatile("ldmatrix.sync.aligned.m8n8.x4.trans.shared.b16 {%0,%1,%2,%3}, [%4];" \
                 : "=r"(r0), "=r"(r1), "=r"(r2), "=r"(r3) : "r"(a))

__device__ __forceinline__ void mma_fp16(float d[4],
                                         uint32_t a0, uint32_t a1, uint32_t a2, uint32_t a3,
                                         uint32_t b0, uint32_t b1) {
    asm volatile(
        "mma.sync.aligned.m16n8k16.row.col.f32.f16.f16.f32 "
        "{%0,%1,%2,%3}, {%4,%5,%6,%7}, {%8,%9}, {%0,%1,%2,%3};"
        : "+f"(d[0]), "+f"(d[1]), "+f"(d[2]), "+f"(d[3])
        : "r"(a0), "r"(a1), "r"(a2), "r"(a3), "r"(b0), "r"(b1));
}

// FMA-only exp (no MUFU): e^x = 2^(x*log2e)
__device__ __forceinline__ float fexp(float x) {
    float y = x * 1.4426950408889634f;
    y = fmaxf(y, -120.0f);
    float r = rintf(y);
    float f = y - r;
    float p = 1.5403530393381609e-4f;
    p = fmaf(p, f, 1.3333558146428443e-3f);
    p = fmaf(p, f, 9.6181291076284770e-3f);
    p = fmaf(p, f, 5.5504108664821580e-2f);
    p = fmaf(p, f, 2.4022650695910070e-1f);
    p = fmaf(p, f, 6.9314718055994531e-1f);
    p = fmaf(p, f, 1.0f);
    int i = (int)r;
    float s = __int_as_float((i + 127) << 23);
    return p * s;
}

// ---------------------------------------------------------------------------
// Kernel 0: fp32 -> fp16 conversion, flattened (one float4 per thread).
// Regions: X (MROWS*HH), then Wq, Wk, Wv (HH*HH each).
// ---------------------------------------------------------------------------
static constexpr size_t NX4 = (size_t)MROWS * HH / 4;   // 1,572,864
static constexpr size_t NW4 = (size_t)HH * HH / 4;      //   147,456
static constexpr size_t NTOT4 = NX4 + 3 * NW4;          // 2,015,232

__global__ __launch_bounds__(256) void split_kernel(
    const float* __restrict__ X,
    const float* __restrict__ Wq, const float* __restrict__ Wk, const float* __restrict__ Wv)
{
    size_t i = (size_t)blockIdx.x * blockDim.x + threadIdx.x;
    if (i >= NTOT4) return;

    const float* src;
    __half* dst;
    size_t off;
    if (i < NX4) {
        src = X; dst = g_xh; off = i;
    } else {
        size_t j = i - NX4;
        int w = (int)(j / NW4);
        off = j - (size_t)w * NW4;
        src = (w == 0) ? Wq : (w == 1) ? Wk : Wv;
        dst = g_wh[w];
    }
    float4 v = reinterpret_cast<const float4*>(src)[off];
    __half2 h0 = __floats2half2_rn(v.x, v.y);
    __half2 h1 = __floats2half2_rn(v.z, v.w);
    uint2 st;
    st.x = reinterpret_cast<uint32_t&>(h0);
    st.y = reinterpret_cast<uint32_t&>(h1);
    *reinterpret_cast<uint2*>(dst + 4 * off) = st;
}

// ---------------------------------------------------------------------------
// Kernel 1: QKV projection, fp16 mma.sync + ldmatrix, 3-stage cp.async.
// (unchanged)
// ---------------------------------------------------------------------------
static constexpr int BK = 32;
static constexpr int KSTRIDE = 40;
static constexpr int TILE_BYTES_G = 128 * KSTRIDE * 2;
static constexpr int STAGE_BYTES = 2 * TILE_BYTES_G;
static constexpr int GEMM_SMEM_TOTAL = 3 * STAGE_BYTES;
static constexpr int NKT = HH / BK;

__device__ __forceinline__ void load_stage_async(
    char* smem, int s,
    const __half* __restrict__ A, const __half* __restrict__ B,
    int k0, int tid)
{
    char* base = smem + s * STAGE_BYTES;
    #pragma unroll
    for (int e = 0; e < 4; e++) {
        const int tile = e >> 1;
        int idx = ((e & 1) << 8) + tid;
        int r = idx >> 2;
        int q = idx & 3;
        const __half* src = (tile == 0 ? A : B) + (size_t)r * HH + k0 + q * 8;
        uint32_t dst = smem_to_u32(base + tile * TILE_BYTES_G + (r * KSTRIDE + q * 8) * 2);
        CP_ASYNC16(dst, src);
    }
}

__global__ __launch_bounds__(256, 2) void qkv_gemm_mma(
    const float* __restrict__ bq, const float* __restrict__ bk, const float* __restrict__ bv)
{
    extern __shared__ char smem[];
    const uint32_t smem_base = smem_to_u32(smem);
    const int tid = threadIdx.x;
    const int wid = tid >> 5;
    const int lane = tid & 31;
    const int g = lane >> 2;
    const int tig = lane & 3;

    const int which = blockIdx.z;
    const int n0 = blockIdx.x * 128;
    const int m0 = blockIdx.y * 128;
    const float* bias = (which == 0) ? bq : (which == 1) ? bk : bv;
    __half* out = g_qkvh[which];

    const __half* A = g_xh + (size_t)m0 * HH;
    const __half* B = g_wh[which] + (size_t)n0 * HH;

    const int m_w = (wid & 1) * 64;
    const int n_w = (wid >> 1) * 32;

    const uint32_t aoff = ((m_w + (lane & 15)) * KSTRIDE + (lane >> 4) * 8) * 2;
    const uint32_t boff = ((n_w + ((lane >> 4) & 1) * 8 + (lane & 7)) * KSTRIDE
                           + ((lane >> 3) & 1) * 8) * 2;

    float acc[4][4][4];
    #pragma unroll
    for (int i = 0; i < 4; i++)
        #pragma unroll
        for (int j = 0; j < 4; j++)
            #pragma unroll
            for (int r = 0; r < 4; r++) acc[i][j][r] = 0.0f;

    load_stage_async(smem, 0, A, B, 0, tid);
    CP_COMMIT();
    load_stage_async(smem, 1, A, B, BK, tid);
    CP_COMMIT();

    for (int kt = 0; kt < NKT; kt++) {
        const int s = kt % 3;
        if (kt + 2 < NKT) {
            load_stage_async(smem, (kt + 2) % 3, A, B, (kt + 2) * BK, tid);
            CP_COMMIT();
        }
        if (kt < NKT - 2)      { CP_WAIT(2); }
        else if (kt == NKT - 2){ CP_WAIT(1); }
        else                   { CP_WAIT(0); }
        __syncthreads();

        const uint32_t sA = smem_base + s * STAGE_BYTES;
        const uint32_t sB = sA + TILE_BYTES_G;

        #pragma unroll
        for (int kc = 0; kc < 2; kc++) {
            uint32_t a[4][4];
            #pragma unroll
            for (int mi = 0; mi < 4; mi++)
                LDSM_X4(a[mi][0], a[mi][1], a[mi][2], a[mi][3],
                        sA + aoff + mi * 16 * KSTRIDE * 2 + kc * 32);
            uint32_t b[2][4];
            #pragma unroll
            for (int n2 = 0; n2 < 2; n2++)
                LDSM_X4(b[n2][0], b[n2][1], b[n2][2], b[n2][3],
                        sB + boff + n2 * 16 * KSTRIDE * 2 + kc * 32);
            #pragma unroll
            for (int mi = 0; mi < 4; mi++)
                #pragma unroll
                for (int ni = 0; ni < 4; ni++)
                    mma_fp16(acc[mi][ni], a[mi][0], a[mi][1], a[mi][2], a[mi][3],
                             b[ni >> 1][(ni & 1) * 2], b[ni >> 1][(ni & 1) * 2 + 1]);
        }
        __syncthreads();
    }

    #pragma unroll
    for (int mi = 0; mi < 4; mi++) {
        int row = m0 + m_w + mi * 16 + g;
        #pragma unroll
        for (int ni = 0; ni < 4; ni++) {
            int n = n0 + n_w + ni * 8 + tig * 2;
            float b0f = bias[n], b1f = bias[n + 1];
            __half2 v0 = __floats2half2_rn(acc[mi][ni][0] + b0f, acc[mi][ni][1] + b1f);
            __half2 v1 = __floats2half2_rn(acc[mi][ni][2] + b0f, acc[mi][ni][3] + b1f);
            *reinterpret_cast<__half2*>(out + (size_t)row * HH + n) = v0;
            *reinterpret_cast<__half2*>(out + (size_t)(row + 8) * HH + n) = v1;
        }
    }
}

// ---------------------------------------------------------------------------
// Kernel 2: register-resident flash-style attention, FULL K/V PRELOAD.
// 512 threads = 16 warps: mw = wid&3 (16-row m-strip), nw = wid>>2 (16-col grp).
// All 8 K tiles + all 8 V tiles cp.async'd up front (K in 4 groups, V in 1).
// ctx-partial buffer aliases the K region (K dead after phase 1).
// Phase 3 runs 64 MMAs with no barriers or waits.
// ---------------------------------------------------------------------------
static constexpr int TST = 72;                    // fp16 tile row stride
static constexpr int TILE_B = 64 * TST * 2;       // 9216 per 64x64 tile

static constexpr int SM_Q    = 0;                         // 9216
static constexpr int SM_K    = SM_Q + TILE_B;             // 8 tiles = 73728
static constexpr int SM_V    = SM_K + 8 * TILE_B;         // 8 tiles = 73728
static constexpr int SM_MSK  = SM_V + 8 * TILE_B;         // 2048
static constexpr int SM_WMAX = SM_MSK + SS * 4;           // 1024
static constexpr int SM_WSUM = SM_WMAX + 4 * 64 * 4;      // 1024
static constexpr int ATTN_SMEM_TOTAL = SM_WSUM + 4 * 64 * 4;  // 160768
static constexpr int CTXST = 68;
// ctx partial buffer aliases SM_K: 4*64*CTXST*4 = 69632 <= 73728

__global__ __launch_bounds__(512, 1) void attn_kernel(
    const float* __restrict__ mask,
    float* __restrict__ ctx,
    float* __restrict__ probs)
{
    extern __shared__ char smem[];
    const uint32_t smem_base = smem_to_u32(smem);
    float* msk   = (float*)(smem + SM_MSK);
    float* wmax  = (float*)(smem + SM_WMAX);
    float* wsum  = (float*)(smem + SM_WSUM);
    float* ctxb  = (float*)(smem + SM_K);     // aliases K region

    const int qt = blockIdx.x;   // 0..7
    const int h  = blockIdx.y;   // 0..11
    const int b  = blockIdx.z;   // 0..15
    const int tid  = threadIdx.x;
    const int lane = tid & 31;
    const int g    = lane >> 2;
    const int tig  = lane & 3;
    const int mw   = ((tid >> 5) & 3);   // m-strip (16 rows)
    const int nw   = (tid >> 7);         // col group (16 cols per K-tile)
    const int q0 = qt * 64;
    const float scale = 0.125f;

    const __half* Q = g_qkvh[0];
    const __half* K = g_qkvh[1];
    const __half* V = g_qkvh[2];

    // mask additive term
    msk[tid] = (1.0f - mask[(size_t)b * SS + tid]) * -10000.0f;

    const int r = tid >> 3, q = tid & 7;   // load coords: row 0..63, 16B quad 0..7

    // load Q tile [64 x 64]
    {
        uint4 v = *reinterpret_cast<const uint4*>(
            Q + ((size_t)(b * SS + q0 + r)) * HH + h * HDD + q * 8);
        *reinterpret_cast<uint4*>((__half*)(smem + SM_Q) + r * TST + q * 8) = v;
    }
    // issue ALL K tiles (commit every 2 tiles -> groups 0..3)
    #pragma unroll
    for (int kt = 0; kt < 8; kt++) {
        CP_ASYNC16(smem_base + SM_K + kt * TILE_B + r * TST * 2 + q * 16,
                   K + ((size_t)(b * SS + kt * 64 + r)) * HH + h * HDD + q * 8);
        if (kt & 1) CP_COMMIT();
    }
    // issue ALL V tiles (single group 4)
    #pragma unroll
    for (int kt = 0; kt < 8; kt++) {
        CP_ASYNC16(smem_base + SM_V + kt * TILE_B + r * TST * 2 + q * 16,
                   V + ((size_t)(b * SS + kt * 64 + r)) * HH + h * HDD + q * 8);
    }
    CP_COMMIT();

    // per-lane ldmatrix offsets within a 64x64 tile
    const uint32_t koff = (nw * 16 + ((lane >> 4) & 1) * 8 + (lane & 7)) * TST * 2
                          + ((lane >> 3) & 1) * 16;   // K (n16k16)
    const uint32_t voff = (nw * 16 + (lane & 7) + ((lane >> 3) & 1) * 8) * TST * 2
                          + ((lane >> 4) & 1) * 16;   // V (trans)

    // wait for K tiles 0-1 (and Q/msk visibility)
    CP_WAIT(4);
    __syncthreads();

    // Q fragments resident in registers
    uint32_t qf[4][4];
    {
        const uint32_t qbase = smem_base + SM_Q
            + ((mw * 16 + (lane & 15)) * TST) * 2 + (lane >> 4) * 16;
        #pragma unroll
        for (int kc = 0; kc < 4; kc++)
            LDSM_X4(qf[kc][0], qf[kc][1], qf[kc][2], qf[kc][3], qbase + kc * 32);
    }

    // ---- phase 1: S = Q K^T * scale + mask, held in registers ----
    float sreg[8][2][4];
    #pragma unroll
    for (int kt = 0; kt < 8; kt++) {
        if (kt == 2) { CP_WAIT(3); __syncthreads(); }
        else if (kt == 4) { CP_WAIT(2); __syncthreads(); }
        else if (kt == 6) { CP_WAIT(1); __syncthreads(); }

        const uint32_t kvb = smem_base + SM_K + kt * TILE_B;
        float acc[2][4];
        #pragma unroll
        for (int ni = 0; ni < 2; ni++)
            #pragma unroll
            for (int rr = 0; rr < 4; rr++) acc[ni][rr] = 0.0f;

        #pragma unroll
        for (int kc = 0; kc < 4; kc++) {
            uint32_t bf[4];
            LDSM_X4(bf[0], bf[1], bf[2], bf[3], kvb + koff + kc * 32);
            mma_fp16(acc[0], qf[kc][0], qf[kc][1], qf[kc][2], qf[kc][3], bf[0], bf[1]);
            mma_fp16(acc[1], qf[kc][0], qf[kc][1], qf[kc][2], qf[kc][3], bf[2], bf[3]);
        }
        #pragma unroll
        for (int ni = 0; ni < 2; ni++) {
            int col = kt * 64 + nw * 16 + ni * 8 + tig * 2;
            sreg[kt][ni][0] = acc[ni][0] * scale + msk[col];
            sreg[kt][ni][1] = acc[ni][1] * scale + msk[col + 1];
            sreg[kt][ni][2] = acc[ni][2] * scale + msk[col];
            sreg[kt][ni][3] = acc[ni][3] * scale + msk[col + 1];
        }
    }

    // ---- phase 2: softmax over register fragments ----
    const int r0 = mw * 16 + g;
    const int r1 = r0 + 8;

    float m0 = -1e30f, m1 = -1e30f;
    #pragma unroll
    for (int kt = 0; kt < 8; kt++)
        #pragma unroll
        for (int ni = 0; ni < 2; ni++) {
            m0 = fmaxf(m0, fmaxf(sreg[kt][ni][0], sreg[kt][ni][1]));
            m1 = fmaxf(m1, fmaxf(sreg[kt][ni][2], sreg[kt][ni][3]));
        }
    #pragma unroll
    for (int o = 1; o <= 2; o <<= 1) {
        m0 = fmaxf(m0, __shfl_xor_sync(0xffffffffu, m0, o));
        m1 = fmaxf(m1, __shfl_xor_sync(0xffffffffu, m1, o));
    }
    if (tig == 0) {
        wmax[nw * 64 + r0] = m0;
        wmax[nw * 64 + r1] = m1;
    }
    __syncthreads();
    float rm0 = fmaxf(fmaxf(wmax[r0], wmax[64 + r0]), fmaxf(wmax[128 + r0], wmax[192 + r0]));
    float rm1 = fmaxf(fmaxf(wmax[r1], wmax[64 + r1]), fmaxf(wmax[128 + r1], wmax[192 + r1]));

    float s0 = 0.0f, s1 = 0.0f;
    #pragma unroll
    for (int kt = 0; kt < 8; kt++)
        #pragma unroll
        for (int ni = 0; ni < 2; ni++) {
            float e0 = fexp(sreg[kt][ni][0] - rm0);
            float e1 = fexp(sreg[kt][ni][1] - rm0);
            float e2 = fexp(sreg[kt][ni][2] - rm1);
            float e3 = fexp(sreg[kt][ni][3] - rm1);
            sreg[kt][ni][0] = e0; sreg[kt][ni][1] = e1;
            sreg[kt][ni][2] = e2; sreg[kt][ni][3] = e3;
            s0 += e0 + e1;
            s1 += e2 + e3;
        }
    #pragma unroll
    for (int o = 1; o <= 2; o <<= 1) {
        s0 += __shfl_xor_sync(0xffffffffu, s0, o);
        s1 += __shfl_xor_sync(0xffffffffu, s1, o);
    }
    if (tig == 0) {
        wsum[nw * 64 + r0] = s0;
        wsum[nw * 64 + r1] = s1;
    }
    CP_WAIT(0);        // all V tiles complete (per-thread) ...
    __syncthreads();   // ... and visible block-wide; also publishes wsum
    float inv0 = 1.0f / (wsum[r0] + wsum[64 + r0] + wsum[128 + r0] + wsum[192 + r0]);
    float inv1 = 1.0f / (wsum[r1] + wsum[64 + r1] + wsum[128 + r1] + wsum[192 + r1]);

    // probs (streaming stores) + in-register P A-fragments
    uint32_t paf[8][4];
    {
        const size_t pb0 = (((size_t)b * NHH + h) * SS + q0 + r0) * SS;
        const size_t pb1 = (((size_t)b * NHH + h) * SS + q0 + r1) * SS;
        #pragma unroll
        for (int kt = 0; kt < 8; kt++)
            #pragma unroll
            for (int ni = 0; ni < 2; ni++) {
                int col = kt * 64 + nw * 16 + ni * 8 + tig * 2;
                float p0 = sreg[kt][ni][0] * inv0;
                float p1 = sreg[kt][ni][1] * inv0;
                float p2 = sreg[kt][ni][2] * inv1;
                float p3 = sreg[kt][ni][3] * inv1;
                __stcs(reinterpret_cast<float2*>(probs + pb0 + col), make_float2(p0, p1));
                __stcs(reinterpret_cast<float2*>(probs + pb1 + col), make_float2(p2, p3));
                __half2 h01 = __floats2half2_rn(p0, p1);
                __half2 h23 = __floats2half2_rn(p2, p3);
                paf[kt][ni * 2]     = reinterpret_cast<uint32_t&>(h01);
                paf[kt][ni * 2 + 1] = reinterpret_cast<uint32_t&>(h23);
            }
    }

    // ---- phase 3: ctx partial = P(16x128) @ V(128x64); no barriers ----
    float cacc[8][4];
    #pragma unroll
    for (int nd = 0; nd < 8; nd++)
        #pragma unroll
        for (int rr = 0; rr < 4; rr++) cacc[nd][rr] = 0.0f;

    #pragma unroll
    for (int kt = 0; kt < 8; kt++) {
        const uint32_t kvb = smem_base + SM_V + kt * TILE_B;
        #pragma unroll
        for (int dd = 0; dd < 4; dd++) {
            uint32_t bf[4];
            LDSM_X4T(bf[0], bf[1], bf[2], bf[3], kvb + voff + dd * 32);
            mma_fp16(cacc[dd * 2],     paf[kt][0], paf[kt][1], paf[kt][2], paf[kt][3], bf[0], bf[1]);
            mma_fp16(cacc[dd * 2 + 1], paf[kt][0], paf[kt][1], paf[kt][2], paf[kt][3], bf[2], bf[3]);
        }
    }

    // write ctx partials to smem (aliases K region; K dead since phase 1)
    #pragma unroll
    for (int nd = 0; nd < 8; nd++) {
        int d = nd * 8 + tig * 2;
        *reinterpret_cast<float2*>(ctxb + (nw * 64 + r0) * CTXST + d) =
            make_float2(cacc[nd][0], cacc[nd][1]);
        *reinterpret_cast<float2*>(ctxb + (nw * 64 + r1) * CTXST + d) =
            make_float2(cacc[nd][2], cacc[nd][3]);
    }
    __syncthreads();

    // 4-way tree sum + global write
    {
        int row = tid >> 3;
        int d0  = (tid & 7) * 8;
        #pragma unroll
        for (int half = 0; half < 2; half++) {
            int d = d0 + half * 4;
            float4 v0 = *reinterpret_cast<float4*>(ctxb + (0 * 64 + row) * CTXST + d);
            float4 v1 = *reinterpret_cast<float4*>(ctxb + (1 * 64 + row) * CTXST + d);
            float4 v2 = *reinterpret_cast<float4*>(ctxb + (2 * 64 + row) * CTXST + d);
            float4 v3 = *reinterpret_cast<float4*>(ctxb + (3 * 64 + row) * CTXST + d);
            float4 o;
            o.x = v0.x + v1.x + v2.x + v3.x;
            o.y = v0.y + v1.y + v2.y + v3.y;
            o.z = v0.z + v1.z + v2.z + v3.z;
            o.w = v0.w + v1.w + v2.w + v3.w;
            *reinterpret_cast<float4*>(
                ctx + ((size_t)(b * SS + q0 + row)) * HH + h * HDD + d) = o;
        }
    }
}

// ---------------------------------------------------------------------------
// kernel_launch
// ---------------------------------------------------------------------------
extern "C" void kernel_launch(void* const* d_in, const int* in_sizes, int n_in,
                              void* d_out, int out_size)
{
    const float* hidden = (const float*)d_in[0];
    const float* mask   = (const float*)d_in[1];
    const float* Wq = (const float*)d_in[2];
    const float* bq = (const float*)d_in[3];
    const float* Wk = (const float*)d_in[4];
    const float* bk = (const float*)d_in[5];
    const float* Wv = (const float*)d_in[6];
    const float* bv = (const float*)d_in[7];

    float* out   = (float*)d_out;
    float* ctx   = out;
    float* probs = out + (size_t)BB * SS * HH;

    // 0) fp32 -> fp16 (flattened, balanced)
    int nblk = (int)((NTOT4 + 255) / 256);
    split_kernel<<<nblk, 256>>>(hidden, Wq, Wk, Wv);

    // 1) QKV projections (fp16 mma.sync + ldmatrix)
    cudaFuncSetAttribute(qkv_gemm_mma, cudaFuncAttributeMaxDynamicSharedMemorySize, GEMM_SMEM_TOTAL);
    dim3 g1(HH / 128, MROWS / 128, 3);
    qkv_gemm_mma<<<g1, 256, GEMM_SMEM_TOTAL>>>(bq, bk, bv);

    // 2) fused attention (register-resident, full K/V preload)
    cudaFuncSetAttribute(attn_kernel, cudaFuncAttributeMaxDynamicSharedMemorySize, ATTN_SMEM_TOTAL);
    dim3 g2(SS / 64, NHH, BB);
    attn_kernel<<<g2, 512, ATTN_SMEM_TOTAL>>>(mask, ctx, probs);
}

// round 9
// speedup vs baseline: 5.8148x; 1.0518x over previous
#include <cuda_runtime.h>
#include <cuda_fp16.h>
#include <cstdint>
#include <math.h>

// Problem constants
static constexpr int BB = 16;     // batch
static constexpr int SS = 512;    // seq len
static constexpr int HH = 768;    // hidden
static constexpr int NHH = 12;    // heads
static constexpr int HDD = 64;    // head dim
static constexpr int MROWS = BB * SS;  // 8192

// Scratch (static device allocations allowed)
__device__ __half g_qkvh[3][(size_t)MROWS * HH];   // fp16 Q,K,V
__device__ __half g_xh[(size_t)MROWS * HH];        // fp16 hidden
__device__ __half g_wh[3][(size_t)HH * HH];        // fp16 weights

// ---------------------------------------------------------------------------
// helpers
// ---------------------------------------------------------------------------
__device__ __forceinline__ uint32_t smem_to_u32(const void* p) {
    uint32_t a;
    asm("{ .reg .u64 t; cvta.to.shared.u64 t, %1; cvt.u32.u64 %0, t; }" : "=r"(a) : "l"(p));
    return a;
}
#define CP_ASYNC16(dst_u32, src_ptr) \
    asm volatile("cp.async.cg.shared.global [%0], [%1], 16;" :: "r"(dst_u32), "l"(src_ptr) : "memory")
#define CP_COMMIT() asm volatile("cp.async.commit_group;" ::: "memory")
#define CP_WAIT(n)  asm volatile("cp.async.wait_group %0;" :: "n"(n) : "memory")

#define LDSM_X4(r0, r1, r2, r3, a) \
    asm volatile("ldmatrix.sync.aligned.m8n8.x4.shared.b16 {%0,%1,%2,%3}, [%4];" \
                 : "=r"(r0), "=r"(r1), "=r"(r2), "=r"(r3) : "r"(a))
#define LDSM_X4T(r0, r1, r2, r3, a) \
    asm volatile("ldmatrix.sync.aligned.m8n8.x4.trans.shared.b16 {%0,%1,%2,%3}, [%4];" \
                 : "=r"(r0), "=r"(r1), "=r"(r2), "=r"(r3) : "r"(a))

__device__ __forceinline__ void mma_fp16(float d[4],
                                         uint32_t a0, uint32_t a1, uint32_t a2, uint32_t a3,
                                         uint32_t b0, uint32_t b1) {
    asm volatile(
        "mma.sync.aligned.m16n8k16.row.col.f32.f16.f16.f32 "
        "{%0,%1,%2,%3}, {%4,%5,%6,%7}, {%8,%9}, {%0,%1,%2,%3};"
        : "+f"(d[0]), "+f"(d[1]), "+f"(d[2]), "+f"(d[3])
        : "r"(a0), "r"(a1), "r"(a2), "r"(a3), "r"(b0), "r"(b1));
}

// FMA-only exp (no MUFU): e^x = 2^(x*log2e)
__device__ __forceinline__ float fexp(float x) {
    float y = x * 1.4426950408889634f;
    y = fmaxf(y, -120.0f);
    float r = rintf(y);
    float f = y - r;
    float p = 1.5403530393381609e-4f;
    p = fmaf(p, f, 1.3333558146428443e-3f);
    p = fmaf(p, f, 9.6181291076284770e-3f);
    p = fmaf(p, f, 5.5504108664821580e-2f);
    p = fmaf(p, f, 2.4022650695910070e-1f);
    p = fmaf(p, f, 6.9314718055994531e-1f);
    p = fmaf(p, f, 1.0f);
    int i = (int)r;
    float s = __int_as_float((i + 127) << 23);
    return p * s;
}

// ---------------------------------------------------------------------------
// Kernel 0: fp32 -> fp16 conversion, flattened (one float4 per thread).
// ---------------------------------------------------------------------------
static constexpr size_t NX4 = (size_t)MROWS * HH / 4;
static constexpr size_t NW4 = (size_t)HH * HH / 4;
static constexpr size_t NTOT4 = NX4 + 3 * NW4;

__global__ __launch_bounds__(256) void split_kernel(
    const float* __restrict__ X,
    const float* __restrict__ Wq, const float* __restrict__ Wk, const float* __restrict__ Wv)
{
    size_t i = (size_t)blockIdx.x * blockDim.x + threadIdx.x;
    if (i >= NTOT4) return;

    const float* src;
    __half* dst;
    size_t off;
    if (i < NX4) {
        src = X; dst = g_xh; off = i;
    } else {
        size_t j = i - NX4;
        int w = (int)(j / NW4);
        off = j - (size_t)w * NW4;
        src = (w == 0) ? Wq : (w == 1) ? Wk : Wv;
        dst = g_wh[w];
    }
    float4 v = reinterpret_cast<const float4*>(src)[off];
    __half2 h0 = __floats2half2_rn(v.x, v.y);
    __half2 h1 = __floats2half2_rn(v.z, v.w);
    uint2 st;
    st.x = reinterpret_cast<uint32_t&>(h0);
    st.y = reinterpret_cast<uint32_t&>(h1);
    *reinterpret_cast<uint2*>(dst + 4 * off) = st;
}

// ---------------------------------------------------------------------------
// Kernel 1: QKV projection, fp16 mma.sync + ldmatrix.
// NOW: 4-stage cp.async ring, prefetch distance 2, SINGLE barrier per k-iter.
// Block tile 128x128, K tile 32, 8 warps 2(m)x4(n); warp tile 64x32.
// ---------------------------------------------------------------------------
static constexpr int BK = 32;
static constexpr int KSTRIDE = 40;
static constexpr int TILE_BYTES_G = 128 * KSTRIDE * 2;   // 10240
static constexpr int STAGE_BYTES = 2 * TILE_BYTES_G;     // 20480
static constexpr int GEMM_SMEM_TOTAL = 4 * STAGE_BYTES;  // 81920 (2 CTAs/SM)
static constexpr int NKT = HH / BK;                      // 24

__device__ __forceinline__ void load_stage_async(
    char* smem, int s,
    const __half* __restrict__ A, const __half* __restrict__ B,
    int k0, int tid)
{
    char* base = smem + s * STAGE_BYTES;
    #pragma unroll
    for (int e = 0; e < 4; e++) {
        const int tile = e >> 1;
        int idx = ((e & 1) << 8) + tid;
        int r = idx >> 2;
        int q = idx & 3;
        const __half* src = (tile == 0 ? A : B) + (size_t)r * HH + k0 + q * 8;
        uint32_t dst = smem_to_u32(base + tile * TILE_BYTES_G + (r * KSTRIDE + q * 8) * 2);
        CP_ASYNC16(dst, src);
    }
}

__global__ __launch_bounds__(256, 2) void qkv_gemm_mma(
    const float* __restrict__ bq, const float* __restrict__ bk, const float* __restrict__ bv)
{
    extern __shared__ char smem[];
    const uint32_t smem_base = smem_to_u32(smem);
    const int tid = threadIdx.x;
    const int wid = tid >> 5;
    const int lane = tid & 31;
    const int g = lane >> 2;
    const int tig = lane & 3;

    const int which = blockIdx.z;
    const int n0 = blockIdx.x * 128;
    const int m0 = blockIdx.y * 128;
    const float* bias = (which == 0) ? bq : (which == 1) ? bk : bv;
    __half* out = g_qkvh[which];

    const __half* A = g_xh + (size_t)m0 * HH;
    const __half* B = g_wh[which] + (size_t)n0 * HH;

    const int m_w = (wid & 1) * 64;
    const int n_w = (wid >> 1) * 32;

    const uint32_t aoff = ((m_w + (lane & 15)) * KSTRIDE + (lane >> 4) * 8) * 2;
    const uint32_t boff = ((n_w + ((lane >> 4) & 1) * 8 + (lane & 7)) * KSTRIDE
                           + ((lane >> 3) & 1) * 8) * 2;

    float acc[4][4][4];
    #pragma unroll
    for (int i = 0; i < 4; i++)
        #pragma unroll
        for (int j = 0; j < 4; j++)
            #pragma unroll
            for (int r = 0; r < 4; r++) acc[i][j][r] = 0.0f;

    load_stage_async(smem, 0, A, B, 0, tid);
    CP_COMMIT();
    load_stage_async(smem, 1, A, B, BK, tid);
    CP_COMMIT();

    for (int kt = 0; kt < NKT; kt++) {
        const int s = kt & 3;
        if (kt + 2 < NKT) {
            load_stage_async(smem, (kt + 2) & 3, A, B, (kt + 2) * BK, tid);
            CP_COMMIT();
        }
        if (kt < NKT - 2)      { CP_WAIT(2); }
        else if (kt == NKT - 2){ CP_WAIT(1); }
        else                   { CP_WAIT(0); }
        __syncthreads();
        // NOTE: no trailing barrier. With 4 stages and prefetch distance 2,
        // a warp in iteration kt+1 writes stage (kt+3)&3 while the slowest
        // warp (guaranteed past barrier kt) reads at most stage kt — distances
        // 2 and 3 mod 4 are nonzero, so no stage aliasing is possible.

        const uint32_t sA = smem_base + s * STAGE_BYTES;
        const uint32_t sB = sA + TILE_BYTES_G;

        #pragma unroll
        for (int kc = 0; kc < 2; kc++) {
            uint32_t a[4][4];
            #pragma unroll
            for (int mi = 0; mi < 4; mi++)
                LDSM_X4(a[mi][0], a[mi][1], a[mi][2], a[mi][3],
                        sA + aoff + mi * 16 * KSTRIDE * 2 + kc * 32);
            uint32_t b[2][4];
            #pragma unroll
            for (int n2 = 0; n2 < 2; n2++)
                LDSM_X4(b[n2][0], b[n2][1], b[n2][2], b[n2][3],
                        sB + boff + n2 * 16 * KSTRIDE * 2 + kc * 32);
            #pragma unroll
            for (int mi = 0; mi < 4; mi++)
                #pragma unroll
                for (int ni = 0; ni < 4; ni++)
                    mma_fp16(acc[mi][ni], a[mi][0], a[mi][1], a[mi][2], a[mi][3],
                             b[ni >> 1][(ni & 1) * 2], b[ni >> 1][(ni & 1) * 2 + 1]);
        }
    }

    #pragma unroll
    for (int mi = 0; mi < 4; mi++) {
        int row = m0 + m_w + mi * 16 + g;
        #pragma unroll
        for (int ni = 0; ni < 4; ni++) {
            int n = n0 + n_w + ni * 8 + tig * 2;
            float b0f = bias[n], b1f = bias[n + 1];
            __half2 v0 = __floats2half2_rn(acc[mi][ni][0] + b0f, acc[mi][ni][1] + b1f);
            __half2 v1 = __floats2half2_rn(acc[mi][ni][2] + b0f, acc[mi][ni][3] + b1f);
            *reinterpret_cast<__half2*>(out + (size_t)row * HH + n) = v0;
            *reinterpret_cast<__half2*>(out + (size_t)(row + 8) * HH + n) = v1;
        }
    }
}

// ---------------------------------------------------------------------------
// Kernel 2: register-resident flash-style attention, FULL K/V PRELOAD.
// (unchanged from round 8)
// ---------------------------------------------------------------------------
static constexpr int TST = 72;
static constexpr int TILE_B = 64 * TST * 2;

static constexpr int SM_Q    = 0;
static constexpr int SM_K    = SM_Q + TILE_B;
static constexpr int SM_V    = SM_K + 8 * TILE_B;
static constexpr int SM_MSK  = SM_V + 8 * TILE_B;
static constexpr int SM_WMAX = SM_MSK + SS * 4;
static constexpr int SM_WSUM = SM_WMAX + 4 * 64 * 4;
static constexpr int ATTN_SMEM_TOTAL = SM_WSUM + 4 * 64 * 4;
static constexpr int CTXST = 68;

__global__ __launch_bounds__(512, 1) void attn_kernel(
    const float* __restrict__ mask,
    float* __restrict__ ctx,
    float* __restrict__ probs)
{
    extern __shared__ char smem[];
    const uint32_t smem_base = smem_to_u32(smem);
    float* msk   = (float*)(smem + SM_MSK);
    float* wmax  = (float*)(smem + SM_WMAX);
    float* wsum  = (float*)(smem + SM_WSUM);
    float* ctxb  = (float*)(smem + SM_K);     // aliases K region

    const int qt = blockIdx.x;
    const int h  = blockIdx.y;
    const int b  = blockIdx.z;
    const int tid  = threadIdx.x;
    const int lane = tid & 31;
    const int g    = lane >> 2;
    const int tig  = lane & 3;
    const int mw   = ((tid >> 5) & 3);
    const int nw   = (tid >> 7);
    const int q0 = qt * 64;
    const float scale = 0.125f;

    const __half* Q = g_qkvh[0];
    const __half* K = g_qkvh[1];
    const __half* V = g_qkvh[2];

    msk[tid] = (1.0f - mask[(size_t)b * SS + tid]) * -10000.0f;

    const int r = tid >> 3, q = tid & 7;

    {
        uint4 v = *reinterpret_cast<const uint4*>(
            Q + ((size_t)(b * SS + q0 + r)) * HH + h * HDD + q * 8);
        *reinterpret_cast<uint4*>((__half*)(smem + SM_Q) + r * TST + q * 8) = v;
    }
    #pragma unroll
    for (int kt = 0; kt < 8; kt++) {
        CP_ASYNC16(smem_base + SM_K + kt * TILE_B + r * TST * 2 + q * 16,
                   K + ((size_t)(b * SS + kt * 64 + r)) * HH + h * HDD + q * 8);
        if (kt & 1) CP_COMMIT();
    }
    #pragma unroll
    for (int kt = 0; kt < 8; kt++) {
        CP_ASYNC16(smem_base + SM_V + kt * TILE_B + r * TST * 2 + q * 16,
                   V + ((size_t)(b * SS + kt * 64 + r)) * HH + h * HDD + q * 8);
    }
    CP_COMMIT();

    const uint32_t koff = (nw * 16 + ((lane >> 4) & 1) * 8 + (lane & 7)) * TST * 2
                          + ((lane >> 3) & 1) * 16;
    const uint32_t voff = (nw * 16 + (lane & 7) + ((lane >> 3) & 1) * 8) * TST * 2
                          + ((lane >> 4) & 1) * 16;

    CP_WAIT(4);
    __syncthreads();

    uint32_t qf[4][4];
    {
        const uint32_t qbase = smem_base + SM_Q
            + ((mw * 16 + (lane & 15)) * TST) * 2 + (lane >> 4) * 16;
        #pragma unroll
        for (int kc = 0; kc < 4; kc++)
            LDSM_X4(qf[kc][0], qf[kc][1], qf[kc][2], qf[kc][3], qbase + kc * 32);
    }

    float sreg[8][2][4];
    #pragma unroll
    for (int kt = 0; kt < 8; kt++) {
        if (kt == 2) { CP_WAIT(3); __syncthreads(); }
        else if (kt == 4) { CP_WAIT(2); __syncthreads(); }
        else if (kt == 6) { CP_WAIT(1); __syncthreads(); }

        const uint32_t kvb = smem_base + SM_K + kt * TILE_B;
        float acc[2][4];
        #pragma unroll
        for (int ni = 0; ni < 2; ni++)
            #pragma unroll
            for (int rr = 0; rr < 4; rr++) acc[ni][rr] = 0.0f;

        #pragma unroll
        for (int kc = 0; kc < 4; kc++) {
            uint32_t bf[4];
            LDSM_X4(bf[0], bf[1], bf[2], bf[3], kvb + koff + kc * 32);
            mma_fp16(acc[0], qf[kc][0], qf[kc][1], qf[kc][2], qf[kc][3], bf[0], bf[1]);
            mma_fp16(acc[1], qf[kc][0], qf[kc][1], qf[kc][2], qf[kc][3], bf[2], bf[3]);
        }
        #pragma unroll
        for (int ni = 0; ni < 2; ni++) {
            int col = kt * 64 + nw * 16 + ni * 8 + tig * 2;
            sreg[kt][ni][0] = acc[ni][0] * scale + msk[col];
            sreg[kt][ni][1] = acc[ni][1] * scale + msk[col + 1];
            sreg[kt][ni][2] = acc[ni][2] * scale + msk[col];
            sreg[kt][ni][3] = acc[ni][3] * scale + msk[col + 1];
        }
    }

    const int r0 = mw * 16 + g;
    const int r1 = r0 + 8;

    float m0 = -1e30f, m1 = -1e30f;
    #pragma unroll
    for (int kt = 0; kt < 8; kt++)
        #pragma unroll
        for (int ni = 0; ni < 2; ni++) {
            m0 = fmaxf(m0, fmaxf(sreg[kt][ni][0], sreg[kt][ni][1]));
            m1 = fmaxf(m1, fmaxf(sreg[kt][ni][2], sreg[kt][ni][3]));
        }
    #pragma unroll
    for (int o = 1; o <= 2; o <<= 1) {
        m0 = fmaxf(m0, __shfl_xor_sync(0xffffffffu, m0, o));
        m1 = fmaxf(m1, __shfl_xor_sync(0xffffffffu, m1, o));
    }
    if (tig == 0) {
        wmax[nw * 64 + r0] = m0;
        wmax[nw * 64 + r1] = m1;
    }
    __syncthreads();
    float rm0 = fmaxf(fmaxf(wmax[r0], wmax[64 + r0]), fmaxf(wmax[128 + r0], wmax[192 + r0]));
    float rm1 = fmaxf(fmaxf(wmax[r1], wmax[64 + r1]), fmaxf(wmax[128 + r1], wmax[192 + r1]));

    float s0 = 0.0f, s1 = 0.0f;
    #pragma unroll
    for (int kt = 0; kt < 8; kt++)
        #pragma unroll
        for (int ni = 0; ni < 2; ni++) {
            float e0 = fexp(sreg[kt][ni][0] - rm0);
            float e1 = fexp(sreg[kt][ni][1] - rm0);
            float e2 = fexp(sreg[kt][ni][2] - rm1);
            float e3 = fexp(sreg[kt][ni][3] - rm1);
            sreg[kt][ni][0] = e0; sreg[kt][ni][1] = e1;
            sreg[kt][ni][2] = e2; sreg[kt][ni][3] = e3;
            s0 += e0 + e1;
            s1 += e2 + e3;
        }
    #pragma unroll
    for (int o = 1; o <= 2; o <<= 1) {
        s0 += __shfl_xor_sync(0xffffffffu, s0, o);
        s1 += __shfl_xor_sync(0xffffffffu, s1, o);
    }
    if (tig == 0) {
        wsum[nw * 64 + r0] = s0;
        wsum[nw * 64 + r1] = s1;
    }
    CP_WAIT(0);
    __syncthreads();
    float inv0 = 1.0f / (wsum[r0] + wsum[64 + r0] + wsum[128 + r0] + wsum[192 + r0]);
    float inv1 = 1.0f / (wsum[r1] + wsum[64 + r1] + wsum[128 + r1] + wsum[192 + r1]);

    uint32_t paf[8][4];
    {
        const size_t pb0 = (((size_t)b * NHH + h) * SS + q0 + r0) * SS;
        const size_t pb1 = (((size_t)b * NHH + h) * SS + q0 + r1) * SS;
        #pragma unroll
        for (int kt = 0; kt < 8; kt++)
            #pragma unroll
            for (int ni = 0; ni < 2; ni++) {
                int col = kt * 64 + nw * 16 + ni * 8 + tig * 2;
                float p0 = sreg[kt][ni][0] * inv0;
                float p1 = sreg[kt][ni][1] * inv0;
                float p2 = sreg[kt][ni][2] * inv1;
                float p3 = sreg[kt][ni][3] * inv1;
                __stcs(reinterpret_cast<float2*>(probs + pb0 + col), make_float2(p0, p1));
                __stcs(reinterpret_cast<float2*>(probs + pb1 + col), make_float2(p2, p3));
                __half2 h01 = __floats2half2_rn(p0, p1);
                __half2 h23 = __floats2half2_rn(p2, p3);
                paf[kt][ni * 2]     = reinterpret_cast<uint32_t&>(h01);
                paf[kt][ni * 2 + 1] = reinterpret_cast<uint32_t&>(h23);
            }
    }

    float cacc[8][4];
    #pragma unroll
    for (int nd = 0; nd < 8; nd++)
        #pragma unroll
        for (int rr = 0; rr < 4; rr++) cacc[nd][rr] = 0.0f;

    #pragma unroll
    for (int kt = 0; kt < 8; kt++) {
        const uint32_t kvb = smem_base + SM_V + kt * TILE_B;
        #pragma unroll
        for (int dd = 0; dd < 4; dd++) {
            uint32_t bf[4];
            LDSM_X4T(bf[0], bf[1], bf[2], bf[3], kvb + voff + dd * 32);
            mma_fp16(cacc[dd * 2],     paf[kt][0], paf[kt][1], paf[kt][2], paf[kt][3], bf[0], bf[1]);
            mma_fp16(cacc[dd * 2 + 1], paf[kt][0], paf[kt][1], paf[kt][2], paf[kt][3], bf[2], bf[3]);
        }
    }

    #pragma unroll
    for (int nd = 0; nd < 8; nd++) {
        int d = nd * 8 + tig * 2;
        *reinterpret_cast<float2*>(ctxb + (nw * 64 + r0) * CTXST + d) =
            make_float2(cacc[nd][0], cacc[nd][1]);
        *reinterpret_cast<float2*>(ctxb + (nw * 64 + r1) * CTXST + d) =
            make_float2(cacc[nd][2], cacc[nd][3]);
    }
    __syncthreads();

    {
        int row = tid >> 3;
        int d0  = (tid & 7) * 8;
        #pragma unroll
        for (int half = 0; half < 2; half++) {
            int d = d0 + half * 4;
            float4 v0 = *reinterpret_cast<float4*>(ctxb + (0 * 64 + row) * CTXST + d);
            float4 v1 = *reinterpret_cast<float4*>(ctxb + (1 * 64 + row) * CTXST + d);
            float4 v2 = *reinterpret_cast<float4*>(ctxb + (2 * 64 + row) * CTXST + d);
            float4 v3 = *reinterpret_cast<float4*>(ctxb + (3 * 64 + row) * CTXST + d);
            float4 o;
            o.x = v0.x + v1.x + v2.x + v3.x;
            o.y = v0.y + v1.y + v2.y + v3.y;
            o.z = v0.z + v1.z + v2.z + v3.z;
            o.w = v0.w + v1.w + v2.w + v3.w;
            *reinterpret_cast<float4*>(
                ctx + ((size_t)(b * SS + q0 + row)) * HH + h * HDD + d) = o;
        }
    }
}

// ---------------------------------------------------------------------------
// kernel_launch
// ---------------------------------------------------------------------------
extern "C" void kernel_launch(void* const* d_in, const int* in_sizes, int n_in,
                              void* d_out, int out_size)
{
    const float* hidden = (const float*)d_in[0];
    const float* mask   = (const float*)d_in[1];
    const float* Wq = (const float*)d_in[2];
    const float* bq = (const float*)d_in[3];
    const float* Wk = (const float*)d_in[4];
    const float* bk = (const float*)d_in[5];
    const float* Wv = (const float*)d_in[6];
    const float* bv = (const float*)d_in[7];

    float* out   = (float*)d_out;
    float* ctx   = out;
    float* probs = out + (size_t)BB * SS * HH;

    // 0) fp32 -> fp16 (flattened, balanced)
    int nblk = (int)((NTOT4 + 255) / 256);
    split_kernel<<<nblk, 256>>>(hidden, Wq, Wk, Wv);

    // 1) QKV projections (fp16 mma.sync, 4-stage single-barrier pipeline)
    cudaFuncSetAttribute(qkv_gemm_mma, cudaFuncAttributeMaxDynamicSharedMemorySize, GEMM_SMEM_TOTAL);
    dim3 g1(HH / 128, MROWS / 128, 3);
    qkv_gemm_mma<<<g1, 256, GEMM_SMEM_TOTAL>>>(bq, bk, bv);

    // 2) fused attention (register-resident, full K/V preload)
    cudaFuncSetAttribute(attn_kernel, cudaFuncAttributeMaxDynamicSharedMemorySize, ATTN_SMEM_TOTAL);
    dim3 g2(SS / 64, NHH, BB);
    attn_kernel<<<g2, 512, ATTN_SMEM_TOTAL>>>(mask, ctx, probs);
}

// round 10
// speedup vs baseline: 6.1646x; 1.0602x over previous
#include <cuda_runtime.h>
#include <cuda_fp16.h>
#include <cstdint>
#include <math.h>

// Problem constants
static constexpr int BB = 16;     // batch
static constexpr int SS = 512;    // seq len
static constexpr int HH = 768;    // hidden
static constexpr int NHH = 12;    // heads
static constexpr int HDD = 64;    // head dim
static constexpr int MROWS = BB * SS;  // 8192

// Scratch (static device allocations allowed)
__device__ __half g_qkvh[3][(size_t)MROWS * HH];   // fp16 Q,K,V
__device__ __half g_xh[(size_t)MROWS * HH];        // fp16 hidden
__device__ __half g_wh[3][(size_t)HH * HH];        // fp16 weights

// ---------------------------------------------------------------------------
// helpers
// ---------------------------------------------------------------------------
__device__ __forceinline__ uint32_t smem_to_u32(const void* p) {
    uint32_t a;
    asm("{ .reg .u64 t; cvta.to.shared.u64 t, %1; cvt.u32.u64 %0, t; }" : "=r"(a) : "l"(p));
    return a;
}
#define CP_ASYNC16(dst_u32, src_ptr) \
    asm volatile("cp.async.cg.shared.global [%0], [%1], 16;" :: "r"(dst_u32), "l"(src_ptr) : "memory")
#define CP_COMMIT() asm volatile("cp.async.commit_group;" ::: "memory")
#define CP_WAIT(n)  asm volatile("cp.async.wait_group %0;" :: "n"(n) : "memory")

#define LDSM_X4(r0, r1, r2, r3, a) \
    asm volatile("ldmatrix.sync.aligned.m8n8.x4.shared.b16 {%0,%1,%2,%3}, [%4];" \
                 : "=r"(r0), "=r"(r1), "=r"(r2), "=r"(r3) : "r"(a))
#define LDSM_X4T(r0, r1, r2, r3, a) \
    asm volatile("ldmatrix.sync.aligned.m8n8.x4.trans.shared.b16 {%0,%1,%2,%3}, [%4];" \
                 : "=r"(r0), "=r"(r1), "=r"(r2), "=r"(r3) : "r"(a))

__device__ __forceinline__ void mma_fp16(float d[4],
                                         uint32_t a0, uint32_t a1, uint32_t a2, uint32_t a3,
                                         uint32_t b0, uint32_t b1) {
    asm volatile(
        "mma.sync.aligned.m16n8k16.row.col.f32.f16.f16.f32 "
        "{%0,%1,%2,%3}, {%4,%5,%6,%7}, {%8,%9}, {%0,%1,%2,%3};"
        : "+f"(d[0]), "+f"(d[1]), "+f"(d[2]), "+f"(d[3])
        : "r"(a0), "r"(a1), "r"(a2), "r"(a3), "r"(b0), "r"(b1));
}

// FMA-only exp (no MUFU): e^x = 2^(x*log2e)
__device__ __forceinline__ float fexp(float x) {
    float y = x * 1.4426950408889634f;
    y = fmaxf(y, -120.0f);
    float r = rintf(y);
    float f = y - r;
    float p = 1.5403530393381609e-4f;
    p = fmaf(p, f, 1.3333558146428443e-3f);
    p = fmaf(p, f, 9.6181291076284770e-3f);
    p = fmaf(p, f, 5.5504108664821580e-2f);
    p = fmaf(p, f, 2.4022650695910070e-1f);
    p = fmaf(p, f, 6.9314718055994531e-1f);
    p = fmaf(p, f, 1.0f);
    int i = (int)r;
    float s = __int_as_float((i + 127) << 23);
    return p * s;
}

// ---------------------------------------------------------------------------
// Kernel 0: fp32 -> fp16 conversion, flattened (one float4 per thread).
// ---------------------------------------------------------------------------
static constexpr size_t NX4 = (size_t)MROWS * HH / 4;
static constexpr size_t NW4 = (size_t)HH * HH / 4;
static constexpr size_t NTOT4 = NX4 + 3 * NW4;

__global__ __launch_bounds__(256) void split_kernel(
    const float* __restrict__ X,
    const float* __restrict__ Wq, const float* __restrict__ Wk, const float* __restrict__ Wv)
{
    size_t i = (size_t)blockIdx.x * blockDim.x + threadIdx.x;
    if (i >= NTOT4) return;

    const float* src;
    __half* dst;
    size_t off;
    if (i < NX4) {
        src = X; dst = g_xh; off = i;
    } else {
        size_t j = i - NX4;
        int w = (int)(j / NW4);
        off = j - (size_t)w * NW4;
        src = (w == 0) ? Wq : (w == 1) ? Wk : Wv;
        dst = g_wh[w];
    }
    float4 v = reinterpret_cast<const float4*>(src)[off];
    __half2 h0 = __floats2half2_rn(v.x, v.y);
    __half2 h1 = __floats2half2_rn(v.z, v.w);
    uint2 st;
    st.x = reinterpret_cast<uint32_t&>(h0);
    st.y = reinterpret_cast<uint32_t&>(h1);
    *reinterpret_cast<uint2*>(dst + 4 * off) = st;
}

// ---------------------------------------------------------------------------
// Kernel 1: QKV projection, fp16 mma.sync + ldmatrix.
// NOW: BK=64, 3-stage ring, prefetch distance 1, 1 barrier per k-iter (12 total).
// Block tile 128x128, 8 warps 2(m)x4(n); warp tile 64x32.
// ---------------------------------------------------------------------------
static constexpr int BK = 64;
static constexpr int KSTRIDE = 72;                       // fp16 per smem row (144B, 36 u32 ≡ 4 mod 32)
static constexpr int TILE_BYTES_G = 128 * KSTRIDE * 2;   // 18432
static constexpr int STAGE_BYTES = 2 * TILE_BYTES_G;     // 36864 (A+B)
static constexpr int GEMM_SMEM_TOTAL = 3 * STAGE_BYTES;  // 110592 (2 CTAs/SM: 221184 <= 227KB)
static constexpr int NKT = HH / BK;                      // 12

__device__ __forceinline__ void load_stage_async(
    char* smem, int s,
    const __half* __restrict__ A, const __half* __restrict__ B,
    int k0, int tid)
{
    char* base = smem + s * STAGE_BYTES;
    #pragma unroll
    for (int e = 0; e < 8; e++) {
        const int tile = e >> 2;                 // 0:A 1:B
        int idx = ((e & 3) << 8) + tid;          // 0..1023
        int r = idx >> 3;                        // 0..127
        int q = idx & 7;                         // 16B quad within 128B row
        const __half* src = (tile == 0 ? A : B) + (size_t)r * HH + k0 + q * 8;
        uint32_t dst = smem_to_u32(base + tile * TILE_BYTES_G + (r * KSTRIDE + q * 8) * 2);
        CP_ASYNC16(dst, src);
    }
}

__global__ __launch_bounds__(256, 2) void qkv_gemm_mma(
    const float* __restrict__ bq, const float* __restrict__ bk, const float* __restrict__ bv)
{
    extern __shared__ char smem[];
    const uint32_t smem_base = smem_to_u32(smem);
    const int tid = threadIdx.x;
    const int wid = tid >> 5;
    const int lane = tid & 31;
    const int g = lane >> 2;
    const int tig = lane & 3;

    const int which = blockIdx.z;
    const int n0 = blockIdx.x * 128;
    const int m0 = blockIdx.y * 128;
    const float* bias = (which == 0) ? bq : (which == 1) ? bk : bv;
    __half* out = g_qkvh[which];

    const __half* A = g_xh + (size_t)m0 * HH;
    const __half* B = g_wh[which] + (size_t)n0 * HH;

    const int m_w = (wid & 1) * 64;
    const int n_w = (wid >> 1) * 32;

    const uint32_t aoff = ((m_w + (lane & 15)) * KSTRIDE + (lane >> 4) * 8) * 2;
    const uint32_t boff = ((n_w + ((lane >> 4) & 1) * 8 + (lane & 7)) * KSTRIDE
                           + ((lane >> 3) & 1) * 8) * 2;

    float acc[4][4][4];
    #pragma unroll
    for (int i = 0; i < 4; i++)
        #pragma unroll
        for (int j = 0; j < 4; j++)
            #pragma unroll
            for (int r = 0; r < 4; r++) acc[i][j][r] = 0.0f;

    // prologue: stage 0
    load_stage_async(smem, 0, A, B, 0, tid);
    CP_COMMIT();

    for (int kt = 0; kt < NKT; kt++) {
        const int s = kt % 3;
        // prefetch distance 1 into stage (kt+1)%3
        if (kt + 1 < NKT) {
            load_stage_async(smem, (kt + 1) % 3, A, B, (kt + 1) * BK, tid);
            CP_COMMIT();
            CP_WAIT(1);       // kt's group complete; (kt+1)'s may be in flight
        } else {
            CP_WAIT(0);
        }
        __syncthreads();
        // No trailing barrier: a warp at iter kt+1 writes stage (kt+2)%3 while
        // the slowest warp (past barrier kt) reads stage kt%3 — distance 2 mod 3
        // and its own reads at (kt+1)%3 — distance 1 mod 3; no aliasing.

        const uint32_t sA = smem_base + s * STAGE_BYTES;
        const uint32_t sB = sA + TILE_BYTES_G;

        #pragma unroll
        for (int kc = 0; kc < 4; kc++) {
            uint32_t a[4][4];
            #pragma unroll
            for (int mi = 0; mi < 4; mi++)
                LDSM_X4(a[mi][0], a[mi][1], a[mi][2], a[mi][3],
                        sA + aoff + mi * 16 * KSTRIDE * 2 + kc * 32);
            uint32_t b[2][4];
            #pragma unroll
            for (int n2 = 0; n2 < 2; n2++)
                LDSM_X4(b[n2][0], b[n2][1], b[n2][2], b[n2][3],
                        sB + boff + n2 * 16 * KSTRIDE * 2 + kc * 32);
            #pragma unroll
            for (int mi = 0; mi < 4; mi++)
                #pragma unroll
                for (int ni = 0; ni < 4; ni++)
                    mma_fp16(acc[mi][ni], a[mi][0], a[mi][1], a[mi][2], a[mi][3],
                             b[ni >> 1][(ni & 1) * 2], b[ni >> 1][(ni & 1) * 2 + 1]);
        }
    }

    #pragma unroll
    for (int mi = 0; mi < 4; mi++) {
        int row = m0 + m_w + mi * 16 + g;
        #pragma unroll
        for (int ni = 0; ni < 4; ni++) {
            int n = n0 + n_w + ni * 8 + tig * 2;
            float b0f = bias[n], b1f = bias[n + 1];
            __half2 v0 = __floats2half2_rn(acc[mi][ni][0] + b0f, acc[mi][ni][1] + b1f);
            __half2 v1 = __floats2half2_rn(acc[mi][ni][2] + b0f, acc[mi][ni][3] + b1f);
            *reinterpret_cast<__half2*>(out + (size_t)row * HH + n) = v0;
            *reinterpret_cast<__half2*>(out + (size_t)(row + 8) * HH + n) = v1;
        }
    }
}

// ---------------------------------------------------------------------------
// Kernel 2: register-resident flash-style attention, FULL K/V PRELOAD.
// (unchanged from round 9)
// ---------------------------------------------------------------------------
static constexpr int TST = 72;
static constexpr int TILE_B = 64 * TST * 2;

static constexpr int SM_Q    = 0;
static constexpr int SM_K    = SM_Q + TILE_B;
static constexpr int SM_V    = SM_K + 8 * TILE_B;
static constexpr int SM_MSK  = SM_V + 8 * TILE_B;
static constexpr int SM_WMAX = SM_MSK + SS * 4;
static constexpr int SM_WSUM = SM_WMAX + 4 * 64 * 4;
static constexpr int ATTN_SMEM_TOTAL = SM_WSUM + 4 * 64 * 4;
static constexpr int CTXST = 68;

__global__ __launch_bounds__(512, 1) void attn_kernel(
    const float* __restrict__ mask,
    float* __restrict__ ctx,
    float* __restrict__ probs)
{
    extern __shared__ char smem[];
    const uint32_t smem_base = smem_to_u32(smem);
    float* msk   = (float*)(smem + SM_MSK);
    float* wmax  = (float*)(smem + SM_WMAX);
    float* wsum  = (float*)(smem + SM_WSUM);
    float* ctxb  = (float*)(smem + SM_K);     // aliases K region

    const int qt = blockIdx.x;
    const int h  = blockIdx.y;
    const int b  = blockIdx.z;
    const int tid  = threadIdx.x;
    const int lane = tid & 31;
    const int g    = lane >> 2;
    const int tig  = lane & 3;
    const int mw   = ((tid >> 5) & 3);
    const int nw   = (tid >> 7);
    const int q0 = qt * 64;
    const float scale = 0.125f;

    const __half* Q = g_qkvh[0];
    const __half* K = g_qkvh[1];
    const __half* V = g_qkvh[2];

    msk[tid] = (1.0f - mask[(size_t)b * SS + tid]) * -10000.0f;

    const int r = tid >> 3, q = tid & 7;

    {
        uint4 v = *reinterpret_cast<const uint4*>(
            Q + ((size_t)(b * SS + q0 + r)) * HH + h * HDD + q * 8);
        *reinterpret_cast<uint4*>((__half*)(smem + SM_Q) + r * TST + q * 8) = v;
    }
    #pragma unroll
    for (int kt = 0; kt < 8; kt++) {
        CP_ASYNC16(smem_base + SM_K + kt * TILE_B + r * TST * 2 + q * 16,
                   K + ((size_t)(b * SS + kt * 64 + r)) * HH + h * HDD + q * 8);
        if (kt & 1) CP_COMMIT();
    }
    #pragma unroll
    for (int kt = 0; kt < 8; kt++) {
        CP_ASYNC16(smem_base + SM_V + kt * TILE_B + r * TST * 2 + q * 16,
                   V + ((size_t)(b * SS + kt * 64 + r)) * HH + h * HDD + q * 8);
    }
    CP_COMMIT();

    const uint32_t koff = (nw * 16 + ((lane >> 4) & 1) * 8 + (lane & 7)) * TST * 2
                          + ((lane >> 3) & 1) * 16;
    const uint32_t voff = (nw * 16 + (lane & 7) + ((lane >> 3) & 1) * 8) * TST * 2
                          + ((lane >> 4) & 1) * 16;

    CP_WAIT(4);
    __syncthreads();

    uint32_t qf[4][4];
    {
        const uint32_t qbase = smem_base + SM_Q
            + ((mw * 16 + (lane & 15)) * TST) * 2 + (lane >> 4) * 16;
        #pragma unroll
        for (int kc = 0; kc < 4; kc++)
            LDSM_X4(qf[kc][0], qf[kc][1], qf[kc][2], qf[kc][3], qbase + kc * 32);
    }

    float sreg[8][2][4];
    #pragma unroll
    for (int kt = 0; kt < 8; kt++) {
        if (kt == 2) { CP_WAIT(3); __syncthreads(); }
        else if (kt == 4) { CP_WAIT(2); __syncthreads(); }
        else if (kt == 6) { CP_WAIT(1); __syncthreads(); }

        const uint32_t kvb = smem_base + SM_K + kt * TILE_B;
        float acc[2][4];
        #pragma unroll
        for (int ni = 0; ni < 2; ni++)
            #pragma unroll
            for (int rr = 0; rr < 4; rr++) acc[ni][rr] = 0.0f;

        #pragma unroll
        for (int kc = 0; kc < 4; kc++) {
            uint32_t bf[4];
            LDSM_X4(bf[0], bf[1], bf[2], bf[3], kvb + koff + kc * 32);
            mma_fp16(acc[0], qf[kc][0], qf[kc][1], qf[kc][2], qf[kc][3], bf[0], bf[1]);
            mma_fp16(acc[1], qf[kc][0], qf[kc][1], qf[kc][2], qf[kc][3], bf[2], bf[3]);
        }
        #pragma unroll
        for (int ni = 0; ni < 2; ni++) {
            int col = kt * 64 + nw * 16 + ni * 8 + tig * 2;
            sreg[kt][ni][0] = acc[ni][0] * scale + msk[col];
            sreg[kt][ni][1] = acc[ni][1] * scale + msk[col + 1];
            sreg[kt][ni][2] = acc[ni][2] * scale + msk[col];
            sreg[kt][ni][3] = acc[ni][3] * scale + msk[col + 1];
        }
    }

    const int r0 = mw * 16 + g;
    const int r1 = r0 + 8;

    float m0 = -1e30f, m1 = -1e30f;
    #pragma unroll
    for (int kt = 0; kt < 8; kt++)
        #pragma unroll
        for (int ni = 0; ni < 2; ni++) {
            m0 = fmaxf(m0, fmaxf(sreg[kt][ni][0], sreg[kt][ni][1]));
            m1 = fmaxf(m1, fmaxf(sreg[kt][ni][2], sreg[kt][ni][3]));
        }
    #pragma unroll
    for (int o = 1; o <= 2; o <<= 1) {
        m0 = fmaxf(m0, __shfl_xor_sync(0xffffffffu, m0, o));
        m1 = fmaxf(m1, __shfl_xor_sync(0xffffffffu, m1, o));
    }
    if (tig == 0) {
        wmax[nw * 64 + r0] = m0;
        wmax[nw * 64 + r1] = m1;
    }
    __syncthreads();
    float rm0 = fmaxf(fmaxf(wmax[r0], wmax[64 + r0]), fmaxf(wmax[128 + r0], wmax[192 + r0]));
    float rm1 = fmaxf(fmaxf(wmax[r1], wmax[64 + r1]), fmaxf(wmax[128 + r1], wmax[192 + r1]));

    float s0 = 0.0f, s1 = 0.0f;
    #pragma unroll
    for (int kt = 0; kt < 8; kt++)
        #pragma unroll
        for (int ni = 0; ni < 2; ni++) {
            float e0 = fexp(sreg[kt][ni][0] - rm0);
            float e1 = fexp(sreg[kt][ni][1] - rm0);
            float e2 = fexp(sreg[kt][ni][2] - rm1);
            float e3 = fexp(sreg[kt][ni][3] - rm1);
            sreg[kt][ni][0] = e0; sreg[kt][ni][1] = e1;
            sreg[kt][ni][2] = e2; sreg[kt][ni][3] = e3;
            s0 += e0 + e1;
            s1 += e2 + e3;
        }
    #pragma unroll
    for (int o = 1; o <= 2; o <<= 1) {
        s0 += __shfl_xor_sync(0xffffffffu, s0, o);
        s1 += __shfl_xor_sync(0xffffffffu, s1, o);
    }
    if (tig == 0) {
        wsum[nw * 64 + r0] = s0;
        wsum[nw * 64 + r1] = s1;
    }
    CP_WAIT(0);
    __syncthreads();
    float inv0 = 1.0f / (wsum[r0] + wsum[64 + r0] + wsum[128 + r0] + wsum[192 + r0]);
    float inv1 = 1.0f / (wsum[r1] + wsum[64 + r1] + wsum[128 + r1] + wsum[192 + r1]);

    uint32_t paf[8][4];
    {
        const size_t pb0 = (((size_t)b * NHH + h) * SS + q0 + r0) * SS;
        const size_t pb1 = (((size_t)b * NHH + h) * SS + q0 + r1) * SS;
        #pragma unroll
        for (int kt = 0; kt < 8; kt++)
            #pragma unroll
            for (int ni = 0; ni < 2; ni++) {
                int col = kt * 64 + nw * 16 + ni * 8 + tig * 2;
                float p0 = sreg[kt][ni][0] * inv0;
                float p1 = sreg[kt][ni][1] * inv0;
                float p2 = sreg[kt][ni][2] * inv1;
                float p3 = sreg[kt][ni][3] * inv1;
                __stcs(reinterpret_cast<float2*>(probs + pb0 + col), make_float2(p0, p1));
                __stcs(reinterpret_cast<float2*>(probs + pb1 + col), make_float2(p2, p3));
                __half2 h01 = __floats2half2_rn(p0, p1);
                __half2 h23 = __floats2half2_rn(p2, p3);
                paf[kt][ni * 2]     = reinterpret_cast<uint32_t&>(h01);
                paf[kt][ni * 2 + 1] = reinterpret_cast<uint32_t&>(h23);
            }
    }

    float cacc[8][4];
    #pragma unroll
    for (int nd = 0; nd < 8; nd++)
        #pragma unroll
        for (int rr = 0; rr < 4; rr++) cacc[nd][rr] = 0.0f;

    #pragma unroll
    for (int kt = 0; kt < 8; kt++) {
        const uint32_t kvb = smem_base + SM_V + kt * TILE_B;
        #pragma unroll
        for (int dd = 0; dd < 4; dd++) {
            uint32_t bf[4];
            LDSM_X4T(bf[0], bf[1], bf[2], bf[3], kvb + voff + dd * 32);
            mma_fp16(cacc[dd * 2],     paf[kt][0], paf[kt][1], paf[kt][2], paf[kt][3], bf[0], bf[1]);
            mma_fp16(cacc[dd * 2 + 1], paf[kt][0], paf[kt][1], paf[kt][2], paf[kt][3], bf[2], bf[3]);
        }
    }

    #pragma unroll
    for (int nd = 0; nd < 8; nd++) {
        int d = nd * 8 + tig * 2;
        *reinterpret_cast<float2*>(ctxb + (nw * 64 + r0) * CTXST + d) =
            make_float2(cacc[nd][0], cacc[nd][1]);
        *reinterpret_cast<float2*>(ctxb + (nw * 64 + r1) * CTXST + d) =
            make_float2(cacc[nd][2], cacc[nd][3]);
    }
    __syncthreads();

    {
        int row = tid >> 3;
        int d0  = (tid & 7) * 8;
        #pragma unroll
        for (int half = 0; half < 2; half++) {
            int d = d0 + half * 4;
            float4 v0 = *reinterpret_cast<float4*>(ctxb + (0 * 64 + row) * CTXST + d);
            float4 v1 = *reinterpret_cast<float4*>(ctxb + (1 * 64 + row) * CTXST + d);
            float4 v2 = *reinterpret_cast<float4*>(ctxb + (2 * 64 + row) * CTXST + d);
            float4 v3 = *reinterpret_cast<float4*>(ctxb + (3 * 64 + row) * CTXST + d);
            float4 o;
            o.x = v0.x + v1.x + v2.x + v3.x;
            o.y = v0.y + v1.y + v2.y + v3.y;
            o.z = v0.z + v1.z + v2.z + v3.z;
            o.w = v0.w + v1.w + v2.w + v3.w;
            *reinterpret_cast<float4*>(
                ctx + ((size_t)(b * SS + q0 + row)) * HH + h * HDD + d) = o;
        }
    }
}

// ---------------------------------------------------------------------------
// kernel_launch
// ---------------------------------------------------------------------------
extern "C" void kernel_launch(void* const* d_in, const int* in_sizes, int n_in,
                              void* d_out, int out_size)
{
    const float* hidden = (const float*)d_in[0];
    const float* mask   = (const float*)d_in[1];
    const float* Wq = (const float*)d_in[2];
    const float* bq = (const float*)d_in[3];
    const float* Wk = (const float*)d_in[4];
    const float* bk = (const float*)d_in[5];
    const float* Wv = (const float*)d_in[6];
    const float* bv = (const float*)d_in[7];

    float* out   = (float*)d_out;
    float* ctx   = out;
    float* probs = out + (size_t)BB * SS * HH;

    // 0) fp32 -> fp16 (flattened, balanced)
    int nblk = (int)((NTOT4 + 255) / 256);
    split_kernel<<<nblk, 256>>>(hidden, Wq, Wk, Wv);

    // 1) QKV projections (fp16 mma.sync, BK=64, 3-stage single-barrier pipeline)
    cudaFuncSetAttribute(qkv_gemm_mma, cudaFuncAttributeMaxDynamicSharedMemorySize, GEMM_SMEM_TOTAL);
    dim3 g1(HH / 128, MROWS / 128, 3);
    qkv_gemm_mma<<<g1, 256, GEMM_SMEM_TOTAL>>>(bq, bk, bv);

    // 2) fused attention (register-resident, full K/V preload)
    cudaFuncSetAttribute(attn_kernel, cudaFuncAttributeMaxDynamicSharedMemorySize, ATTN_SMEM_TOTAL);
    dim3 g2(SS / 64, NHH, BB);
    attn_kernel<<<g2, 512, ATTN_SMEM_TOTAL>>>(mask, ctx, probs);
}

// round 11
// speedup vs baseline: 6.2219x; 1.0093x over previous
#include <cuda_runtime.h>
#include <cuda_fp16.h>
#include <cstdint>
#include <math.h>

// Problem constants
static constexpr int BB = 16;     // batch
static constexpr int SS = 512;    // seq len
static constexpr int HH = 768;    // hidden
static constexpr int NHH = 12;    // heads
static constexpr int HDD = 64;    // head dim
static constexpr int MROWS = BB * SS;  // 8192

// Scratch (static device allocations allowed)
__device__ __half g_qkvh[3][(size_t)MROWS * HH];   // fp16 Q,K,V
__device__ __half g_xh[(size_t)MROWS * HH];        // fp16 hidden
__device__ __half g_wh[3][(size_t)HH * HH];        // fp16 weights

// ---------------------------------------------------------------------------
// helpers
// ---------------------------------------------------------------------------
__device__ __forceinline__ uint32_t smem_to_u32(const void* p) {
    uint32_t a;
    asm("{ .reg .u64 t; cvta.to.shared.u64 t, %1; cvt.u32.u64 %0, t; }" : "=r"(a) : "l"(p));
    return a;
}
#define CP_ASYNC16(dst_u32, src_ptr) \
    asm volatile("cp.async.cg.shared.global [%0], [%1], 16;" :: "r"(dst_u32), "l"(src_ptr) : "memory")
#define CP_COMMIT() asm volatile("cp.async.commit_group;" ::: "memory")
#define CP_WAIT(n)  asm volatile("cp.async.wait_group %0;" :: "n"(n) : "memory")

#define LDSM_X4(r0, r1, r2, r3, a) \
    asm volatile("ldmatrix.sync.aligned.m8n8.x4.shared.b16 {%0,%1,%2,%3}, [%4];" \
                 : "=r"(r0), "=r"(r1), "=r"(r2), "=r"(r3) : "r"(a))
#define LDSM_X4T(r0, r1, r2, r3, a) \
    asm volatile("ldmatrix.sync.aligned.m8n8.x4.trans.shared.b16 {%0,%1,%2,%3}, [%4];" \
                 : "=r"(r0), "=r"(r1), "=r"(r2), "=r"(r3) : "r"(a))

__device__ __forceinline__ void mma_fp16(float d[4],
                                         uint32_t a0, uint32_t a1, uint32_t a2, uint32_t a3,
                                         uint32_t b0, uint32_t b1) {
    asm volatile(
        "mma.sync.aligned.m16n8k16.row.col.f32.f16.f16.f32 "
        "{%0,%1,%2,%3}, {%4,%5,%6,%7}, {%8,%9}, {%0,%1,%2,%3};"
        : "+f"(d[0]), "+f"(d[1]), "+f"(d[2]), "+f"(d[3])
        : "r"(a0), "r"(a1), "r"(a2), "r"(a3), "r"(b0), "r"(b1));
}

// FMA-only exp (no MUFU): e^x = 2^(x*log2e)
__device__ __forceinline__ float fexp(float x) {
    float y = x * 1.4426950408889634f;
    y = fmaxf(y, -120.0f);
    float r = rintf(y);
    float f = y - r;
    float p = 1.5403530393381609e-4f;
    p = fmaf(p, f, 1.3333558146428443e-3f);
    p = fmaf(p, f, 9.6181291076284770e-3f);
    p = fmaf(p, f, 5.5504108664821580e-2f);
    p = fmaf(p, f, 2.4022650695910070e-1f);
    p = fmaf(p, f, 6.9314718055994531e-1f);
    p = fmaf(p, f, 1.0f);
    int i = (int)r;
    float s = __int_as_float((i + 127) << 23);
    return p * s;
}

// ---------------------------------------------------------------------------
// Kernel 0: fp32 -> fp16 conversion, 2 float4 per thread (MLP).
// ---------------------------------------------------------------------------
static constexpr size_t NX4 = (size_t)MROWS * HH / 4;
static constexpr size_t NW4 = (size_t)HH * HH / 4;
static constexpr size_t NTOT4 = NX4 + 3 * NW4;

__device__ __forceinline__ void split_one(
    const float* __restrict__ X,
    const float* __restrict__ Wq, const float* __restrict__ Wk, const float* __restrict__ Wv,
    size_t i)
{
    const float* src;
    __half* dst;
    size_t off;
    if (i < NX4) {
        src = X; dst = g_xh; off = i;
    } else {
        size_t j = i - NX4;
        int w = (int)(j / NW4);
        off = j - (size_t)w * NW4;
        src = (w == 0) ? Wq : (w == 1) ? Wk : Wv;
        dst = g_wh[w];
    }
    float4 v = reinterpret_cast<const float4*>(src)[off];
    __half2 h0 = __floats2half2_rn(v.x, v.y);
    __half2 h1 = __floats2half2_rn(v.z, v.w);
    uint2 st;
    st.x = reinterpret_cast<uint32_t&>(h0);
    st.y = reinterpret_cast<uint32_t&>(h1);
    *reinterpret_cast<uint2*>(dst + 4 * off) = st;
}

__global__ __launch_bounds__(256) void split_kernel(
    const float* __restrict__ X,
    const float* __restrict__ Wq, const float* __restrict__ Wk, const float* __restrict__ Wv)
{
    size_t stride = (size_t)gridDim.x * blockDim.x;
    size_t i0 = (size_t)blockIdx.x * blockDim.x + threadIdx.x;
    size_t i1 = i0 + stride;
    if (i0 < NTOT4) split_one(X, Wq, Wk, Wv, i0);
    if (i1 < NTOT4) split_one(X, Wq, Wk, Wv, i1);
}

// ---------------------------------------------------------------------------
// Kernel 1: QKV projection (unchanged from round 10).
// BK=64, 3-stage ring, prefetch distance 1, 1 barrier per k-iter.
// ---------------------------------------------------------------------------
static constexpr int BK = 64;
static constexpr int KSTRIDE = 72;
static constexpr int TILE_BYTES_G = 128 * KSTRIDE * 2;   // 18432
static constexpr int STAGE_BYTES = 2 * TILE_BYTES_G;     // 36864
static constexpr int GEMM_SMEM_TOTAL = 3 * STAGE_BYTES;  // 110592
static constexpr int NKT = HH / BK;                      // 12

__device__ __forceinline__ void load_stage_async(
    char* smem, int s,
    const __half* __restrict__ A, const __half* __restrict__ B,
    int k0, int tid)
{
    char* base = smem + s * STAGE_BYTES;
    #pragma unroll
    for (int e = 0; e < 8; e++) {
        const int tile = e >> 2;
        int idx = ((e & 3) << 8) + tid;
        int r = idx >> 3;
        int q = idx & 7;
        const __half* src = (tile == 0 ? A : B) + (size_t)r * HH + k0 + q * 8;
        uint32_t dst = smem_to_u32(base + tile * TILE_BYTES_G + (r * KSTRIDE + q * 8) * 2);
        CP_ASYNC16(dst, src);
    }
}

__global__ __launch_bounds__(256, 2) void qkv_gemm_mma(
    const float* __restrict__ bq, const float* __restrict__ bk, const float* __restrict__ bv)
{
    extern __shared__ char smem[];
    const uint32_t smem_base = smem_to_u32(smem);
    const int tid = threadIdx.x;
    const int wid = tid >> 5;
    const int lane = tid & 31;
    const int g = lane >> 2;
    const int tig = lane & 3;

    const int which = blockIdx.z;
    const int n0 = blockIdx.x * 128;
    const int m0 = blockIdx.y * 128;
    const float* bias = (which == 0) ? bq : (which == 1) ? bk : bv;
    __half* out = g_qkvh[which];

    const __half* A = g_xh + (size_t)m0 * HH;
    const __half* B = g_wh[which] + (size_t)n0 * HH;

    const int m_w = (wid & 1) * 64;
    const int n_w = (wid >> 1) * 32;

    const uint32_t aoff = ((m_w + (lane & 15)) * KSTRIDE + (lane >> 4) * 8) * 2;
    const uint32_t boff = ((n_w + ((lane >> 4) & 1) * 8 + (lane & 7)) * KSTRIDE
                           + ((lane >> 3) & 1) * 8) * 2;

    float acc[4][4][4];
    #pragma unroll
    for (int i = 0; i < 4; i++)
        #pragma unroll
        for (int j = 0; j < 4; j++)
            #pragma unroll
            for (int r = 0; r < 4; r++) acc[i][j][r] = 0.0f;

    load_stage_async(smem, 0, A, B, 0, tid);
    CP_COMMIT();

    for (int kt = 0; kt < NKT; kt++) {
        const int s = kt % 3;
        if (kt + 1 < NKT) {
            load_stage_async(smem, (kt + 1) % 3, A, B, (kt + 1) * BK, tid);
            CP_COMMIT();
            CP_WAIT(1);
        } else {
            CP_WAIT(0);
        }
        __syncthreads();

        const uint32_t sA = smem_base + s * STAGE_BYTES;
        const uint32_t sB = sA + TILE_BYTES_G;

        #pragma unroll
        for (int kc = 0; kc < 4; kc++) {
            uint32_t a[4][4];
            #pragma unroll
            for (int mi = 0; mi < 4; mi++)
                LDSM_X4(a[mi][0], a[mi][1], a[mi][2], a[mi][3],
                        sA + aoff + mi * 16 * KSTRIDE * 2 + kc * 32);
            uint32_t b[2][4];
            #pragma unroll
            for (int n2 = 0; n2 < 2; n2++)
                LDSM_X4(b[n2][0], b[n2][1], b[n2][2], b[n2][3],
                        sB + boff + n2 * 16 * KSTRIDE * 2 + kc * 32);
            #pragma unroll
            for (int mi = 0; mi < 4; mi++)
                #pragma unroll
                for (int ni = 0; ni < 4; ni++)
                    mma_fp16(acc[mi][ni], a[mi][0], a[mi][1], a[mi][2], a[mi][3],
                             b[ni >> 1][(ni & 1) * 2], b[ni >> 1][(ni & 1) * 2 + 1]);
        }
    }

    #pragma unroll
    for (int mi = 0; mi < 4; mi++) {
        int row = m0 + m_w + mi * 16 + g;
        #pragma unroll
        for (int ni = 0; ni < 4; ni++) {
            int n = n0 + n_w + ni * 8 + tig * 2;
            float b0f = bias[n], b1f = bias[n + 1];
            __half2 v0 = __floats2half2_rn(acc[mi][ni][0] + b0f, acc[mi][ni][1] + b1f);
            __half2 v1 = __floats2half2_rn(acc[mi][ni][2] + b0f, acc[mi][ni][3] + b1f);
            *reinterpret_cast<__half2*>(out + (size_t)row * HH + n) = v0;
            *reinterpret_cast<__half2*>(out + (size_t)(row + 8) * HH + n) = v1;
        }
    }
}

// ---------------------------------------------------------------------------
// Kernel 2: register-resident flash-style attention, full K/V preload.
// NOW: probs stores + paf construction interleaved into PV loop; finer K
// commit groups (t0, t1, pairs) so phase 1 starts one tile earlier.
// ---------------------------------------------------------------------------
static constexpr int TST = 72;
static constexpr int TILE_B = 64 * TST * 2;

static constexpr int SM_Q    = 0;
static constexpr int SM_K    = SM_Q + TILE_B;
static constexpr int SM_V    = SM_K + 8 * TILE_B;
static constexpr int SM_MSK  = SM_V + 8 * TILE_B;
static constexpr int SM_WMAX = SM_MSK + SS * 4;
static constexpr int SM_WSUM = SM_WMAX + 4 * 64 * 4;
static constexpr int ATTN_SMEM_TOTAL = SM_WSUM + 4 * 64 * 4;
static constexpr int CTXST = 68;

__global__ __launch_bounds__(512, 1) void attn_kernel(
    const float* __restrict__ mask,
    float* __restrict__ ctx,
    float* __restrict__ probs)
{
    extern __shared__ char smem[];
    const uint32_t smem_base = smem_to_u32(smem);
    float* msk   = (float*)(smem + SM_MSK);
    float* wmax  = (float*)(smem + SM_WMAX);
    float* wsum  = (float*)(smem + SM_WSUM);
    float* ctxb  = (float*)(smem + SM_K);     // aliases K region

    const int qt = blockIdx.x;
    const int h  = blockIdx.y;
    const int b  = blockIdx.z;
    const int tid  = threadIdx.x;
    const int lane = tid & 31;
    const int g    = lane >> 2;
    const int tig  = lane & 3;
    const int mw   = ((tid >> 5) & 3);
    const int nw   = (tid >> 7);
    const int q0 = qt * 64;
    const float scale = 0.125f;

    const __half* Q = g_qkvh[0];
    const __half* K = g_qkvh[1];
    const __half* V = g_qkvh[2];

    msk[tid] = (1.0f - mask[(size_t)b * SS + tid]) * -10000.0f;

    const int r = tid >> 3, q = tid & 7;

    {
        uint4 v = *reinterpret_cast<const uint4*>(
            Q + ((size_t)(b * SS + q0 + r)) * HH + h * HDD + q * 8);
        *reinterpret_cast<uint4*>((__half*)(smem + SM_Q) + r * TST + q * 8) = v;
    }
    // K commits: tile0, tile1, {2,3}, {4,5}, {6,7}  -> 5 groups; V -> 1 group
    #pragma unroll
    for (int kt = 0; kt < 8; kt++) {
        CP_ASYNC16(smem_base + SM_K + kt * TILE_B + r * TST * 2 + q * 16,
                   K + ((size_t)(b * SS + kt * 64 + r)) * HH + h * HDD + q * 8);
        if (kt == 0 || kt == 1 || kt == 3 || kt == 5 || kt == 7) CP_COMMIT();
    }
    #pragma unroll
    for (int kt = 0; kt < 8; kt++) {
        CP_ASYNC16(smem_base + SM_V + kt * TILE_B + r * TST * 2 + q * 16,
                   V + ((size_t)(b * SS + kt * 64 + r)) * HH + h * HDD + q * 8);
    }
    CP_COMMIT();

    const uint32_t koff = (nw * 16 + ((lane >> 4) & 1) * 8 + (lane & 7)) * TST * 2
                          + ((lane >> 3) & 1) * 16;
    const uint32_t voff = (nw * 16 + (lane & 7) + ((lane >> 3) & 1) * 8) * TST * 2
                          + ((lane >> 4) & 1) * 16;

    // wait for K tile 0 only (5 groups still outstanding: K t1, 3 pairs, V)
    CP_WAIT(5);
    __syncthreads();

    uint32_t qf[4][4];
    {
        const uint32_t qbase = smem_base + SM_Q
            + ((mw * 16 + (lane & 15)) * TST) * 2 + (lane >> 4) * 16;
        #pragma unroll
        for (int kc = 0; kc < 4; kc++)
            LDSM_X4(qf[kc][0], qf[kc][1], qf[kc][2], qf[kc][3], qbase + kc * 32);
    }

    float sreg[8][2][4];
    #pragma unroll
    for (int kt = 0; kt < 8; kt++) {
        if (kt == 1)      { CP_WAIT(4); __syncthreads(); }
        else if (kt == 2) { CP_WAIT(3); __syncthreads(); }
        else if (kt == 4) { CP_WAIT(2); __syncthreads(); }
        else if (kt == 6) { CP_WAIT(1); __syncthreads(); }

        const uint32_t kvb = smem_base + SM_K + kt * TILE_B;
        float acc[2][4];
        #pragma unroll
        for (int ni = 0; ni < 2; ni++)
            #pragma unroll
            for (int rr = 0; rr < 4; rr++) acc[ni][rr] = 0.0f;

        #pragma unroll
        for (int kc = 0; kc < 4; kc++) {
            uint32_t bf[4];
            LDSM_X4(bf[0], bf[1], bf[2], bf[3], kvb + koff + kc * 32);
            mma_fp16(acc[0], qf[kc][0], qf[kc][1], qf[kc][2], qf[kc][3], bf[0], bf[1]);
            mma_fp16(acc[1], qf[kc][0], qf[kc][1], qf[kc][2], qf[kc][3], bf[2], bf[3]);
        }
        #pragma unroll
        for (int ni = 0; ni < 2; ni++) {
            int col = kt * 64 + nw * 16 + ni * 8 + tig * 2;
            sreg[kt][ni][0] = acc[ni][0] * scale + msk[col];
            sreg[kt][ni][1] = acc[ni][1] * scale + msk[col + 1];
            sreg[kt][ni][2] = acc[ni][2] * scale + msk[col];
            sreg[kt][ni][3] = acc[ni][3] * scale + msk[col + 1];
        }
    }

    const int r0 = mw * 16 + g;
    const int r1 = r0 + 8;

    float m0 = -1e30f, m1 = -1e30f;
    #pragma unroll
    for (int kt = 0; kt < 8; kt++)
        #pragma unroll
        for (int ni = 0; ni < 2; ni++) {
            m0 = fmaxf(m0, fmaxf(sreg[kt][ni][0], sreg[kt][ni][1]));
            m1 = fmaxf(m1, fmaxf(sreg[kt][ni][2], sreg[kt][ni][3]));
        }
    #pragma unroll
    for (int o = 1; o <= 2; o <<= 1) {
        m0 = fmaxf(m0, __shfl_xor_sync(0xffffffffu, m0, o));
        m1 = fmaxf(m1, __shfl_xor_sync(0xffffffffu, m1, o));
    }
    if (tig == 0) {
        wmax[nw * 64 + r0] = m0;
        wmax[nw * 64 + r1] = m1;
    }
    __syncthreads();
    float rm0 = fmaxf(fmaxf(wmax[r0], wmax[64 + r0]), fmaxf(wmax[128 + r0], wmax[192 + r0]));
    float rm1 = fmaxf(fmaxf(wmax[r1], wmax[64 + r1]), fmaxf(wmax[128 + r1], wmax[192 + r1]));

    float s0 = 0.0f, s1 = 0.0f;
    #pragma unroll
    for (int kt = 0; kt < 8; kt++)
        #pragma unroll
        for (int ni = 0; ni < 2; ni++) {
            float e0 = fexp(sreg[kt][ni][0] - rm0);
            float e1 = fexp(sreg[kt][ni][1] - rm0);
            float e2 = fexp(sreg[kt][ni][2] - rm1);
            float e3 = fexp(sreg[kt][ni][3] - rm1);
            sreg[kt][ni][0] = e0; sreg[kt][ni][1] = e1;
            sreg[kt][ni][2] = e2; sreg[kt][ni][3] = e3;
            s0 += e0 + e1;
            s1 += e2 + e3;
        }
    #pragma unroll
    for (int o = 1; o <= 2; o <<= 1) {
        s0 += __shfl_xor_sync(0xffffffffu, s0, o);
        s1 += __shfl_xor_sync(0xffffffffu, s1, o);
    }
    if (tig == 0) {
        wsum[nw * 64 + r0] = s0;
        wsum[nw * 64 + r1] = s1;
    }
    CP_WAIT(0);        // all V tiles complete (per-thread) ...
    __syncthreads();   // ... and visible block-wide; also publishes wsum
    float inv0 = 1.0f / (wsum[r0] + wsum[64 + r0] + wsum[128 + r0] + wsum[192 + r0]);
    float inv1 = 1.0f / (wsum[r1] + wsum[64 + r1] + wsum[128 + r1] + wsum[192 + r1]);

    // ---- phase 3: ctx = P @ V with probs stores interleaved per tile ----
    const size_t pb0 = (((size_t)b * NHH + h) * SS + q0 + r0) * SS;
    const size_t pb1 = (((size_t)b * NHH + h) * SS + q0 + r1) * SS;

    float cacc[8][4];
    #pragma unroll
    for (int nd = 0; nd < 8; nd++)
        #pragma unroll
        for (int rr = 0; rr < 4; rr++) cacc[nd][rr] = 0.0f;

    #pragma unroll
    for (int kt = 0; kt < 8; kt++) {
        // probs for tile kt (streaming stores) + P fragments for this tile
        uint32_t paf[4];
        #pragma unroll
        for (int ni = 0; ni < 2; ni++) {
            int col = kt * 64 + nw * 16 + ni * 8 + tig * 2;
            float p0 = sreg[kt][ni][0] * inv0;
            float p1 = sreg[kt][ni][1] * inv0;
            float p2 = sreg[kt][ni][2] * inv1;
            float p3 = sreg[kt][ni][3] * inv1;
            __stcs(reinterpret_cast<float2*>(probs + pb0 + col), make_float2(p0, p1));
            __stcs(reinterpret_cast<float2*>(probs + pb1 + col), make_float2(p2, p3));
            __half2 h01 = __floats2half2_rn(p0, p1);
            __half2 h23 = __floats2half2_rn(p2, p3);
            paf[ni * 2]     = reinterpret_cast<uint32_t&>(h01);
            paf[ni * 2 + 1] = reinterpret_cast<uint32_t&>(h23);
        }
        const uint32_t kvb = smem_base + SM_V + kt * TILE_B;
        #pragma unroll
        for (int dd = 0; dd < 4; dd++) {
            uint32_t bf[4];
            LDSM_X4T(bf[0], bf[1], bf[2], bf[3], kvb + voff + dd * 32);
            mma_fp16(cacc[dd * 2],     paf[0], paf[1], paf[2], paf[3], bf[0], bf[1]);
            mma_fp16(cacc[dd * 2 + 1], paf[0], paf[1], paf[2], paf[3], bf[2], bf[3]);
        }
    }

    #pragma unroll
    for (int nd = 0; nd < 8; nd++) {
        int d = nd * 8 + tig * 2;
        *reinterpret_cast<float2*>(ctxb + (nw * 64 + r0) * CTXST + d) =
            make_float2(cacc[nd][0], cacc[nd][1]);
        *reinterpret_cast<float2*>(ctxb + (nw * 64 + r1) * CTXST + d) =
            make_float2(cacc[nd][2], cacc[nd][3]);
    }
    __syncthreads();

    {
        int row = tid >> 3;
        int d0  = (tid & 7) * 8;
        #pragma unroll
        for (int half = 0; half < 2; half++) {
            int d = d0 + half * 4;
            float4 v0 = *reinterpret_cast<float4*>(ctxb + (0 * 64 + row) * CTXST + d);
            float4 v1 = *reinterpret_cast<float4*>(ctxb + (1 * 64 + row) * CTXST + d);
            float4 v2 = *reinterpret_cast<float4*>(ctxb + (2 * 64 + row) * CTXST + d);
            float4 v3 = *reinterpret_cast<float4*>(ctxb + (3 * 64 + row) * CTXST + d);
            float4 o;
            o.x = v0.x + v1.x + v2.x + v3.x;
            o.y = v0.y + v1.y + v2.y + v3.y;
            o.z = v0.z + v1.z + v2.z + v3.z;
            o.w = v0.w + v1.w + v2.w + v3.w;
            *reinterpret_cast<float4*>(
                ctx + ((size_t)(b * SS + q0 + row)) * HH + h * HDD + d) = o;
        }
    }
}

// ---------------------------------------------------------------------------
// kernel_launch
// ---------------------------------------------------------------------------
extern "C" void kernel_launch(void* const* d_in, const int* in_sizes, int n_in,
                              void* d_out, int out_size)
{
    const float* hidden = (const float*)d_in[0];
    const float* mask   = (const float*)d_in[1];
    const float* Wq = (const float*)d_in[2];
    const float* bq = (const float*)d_in[3];
    const float* Wk = (const float*)d_in[4];
    const float* bk = (const float*)d_in[5];
    const float* Wv = (const float*)d_in[6];
    const float* bv = (const float*)d_in[7];

    float* out   = (float*)d_out;
    float* ctx   = out;
    float* probs = out + (size_t)BB * SS * HH;

    // 0) fp32 -> fp16 (2 float4 per thread)
    int nblk = (int)((NTOT4 / 2 + 255) / 256);
    split_kernel<<<nblk, 256>>>(hidden, Wq, Wk, Wv);

    // 1) QKV projections (fp16 mma.sync, BK=64, 3-stage single-barrier pipeline)
    cudaFuncSetAttribute(qkv_gemm_mma, cudaFuncAttributeMaxDynamicSharedMemorySize, GEMM_SMEM_TOTAL);
    dim3 g1(HH / 128, MROWS / 128, 3);
    qkv_gemm_mma<<<g1, 256, GEMM_SMEM_TOTAL>>>(bq, bk, bv);

    // 2) fused attention (register-resident, full K/V preload, interleaved stores)
    cudaFuncSetAttribute(attn_kernel, cudaFuncAttributeMaxDynamicSharedMemorySize, ATTN_SMEM_TOTAL);
    dim3 g2(SS / 64, NHH, BB);
    attn_kernel<<<g2, 512, ATTN_SMEM_TOTAL>>>(mask, ctx, probs);
}